// round 6
// baseline (speedup 1.0000x reference)
#include <cuda_runtime.h>
#include <cuda_bf16.h>
#include <math.h>
#include <stdint.h>

#define Bc 2
#define Sc 2048
#define Dc 1024
#define Hc 16
#define DPc 64

static const size_t SZ_QKV  = (size_t)Bc * Sc * Dc;        // 4194304
static const size_t SZ_ATTN = (size_t)Bc * Hc * Sc * Sc;   // 134217728
#define MD  ((size_t)4194304)       // M*Dc
#define DD  ((size_t)1048576)       // Dc*Dc

// bf16 hi/lo plane scratch (allocation-free device globals)
__device__ __nv_bfloat16 g_iah[3 * MD], g_ial[3 * MD];   // Q,K,V inputs
__device__ __nv_bfloat16 g_wh[4 * DD],  g_wl[4 * DD];    // Wq,Wk,Wv,Wo
__device__ __nv_bfloat16 g_qh[MD], g_ql[MD];
__device__ __nv_bfloat16 g_kh[MD], g_kl[MD];
__device__ __nv_bfloat16 g_vh[MD], g_vl[MD];
__device__ __nv_bfloat16 g_ch2[MD], g_cl2[MD];           // ctx planes
__device__ float g_lbuf[(size_t)Bc * Hc * Sc];

// ---------------------------------------------------------------------------
// helpers
// ---------------------------------------------------------------------------
__device__ __forceinline__ uint32_t smem_u32(const void* p) {
    uint32_t a;
    asm("{ .reg .u64 t; cvta.to.shared.u64 t, %1; cvt.u32.u64 %0, t; }"
        : "=r"(a) : "l"(p));
    return a;
}
__device__ __forceinline__ void mma16816(float* d, const uint32_t* a, const uint32_t* b) {
    asm volatile(
        "mma.sync.aligned.m16n8k16.row.col.f32.bf16.bf16.f32 "
        "{%0,%1,%2,%3}, {%4,%5,%6,%7}, {%8,%9}, {%0,%1,%2,%3};"
        : "+f"(d[0]), "+f"(d[1]), "+f"(d[2]), "+f"(d[3])
        : "r"(a[0]), "r"(a[1]), "r"(a[2]), "r"(a[3]), "r"(b[0]), "r"(b[1]));
}
__device__ __forceinline__ void ldsm4(uint32_t* r, uint32_t addr) {
    asm volatile("ldmatrix.sync.aligned.m8n8.x4.shared.b16 {%0,%1,%2,%3}, [%4];"
                 : "=r"(r[0]), "=r"(r[1]), "=r"(r[2]), "=r"(r[3]) : "r"(addr));
}
__device__ __forceinline__ float fexp2(float x) {
    float r;
    asm("ex2.approx.f32 %0, %1;" : "=f"(r) : "f"(x));
    return r;
}
__device__ __forceinline__ uint32_t pack_hi(float x, float y) {
    __nv_bfloat162 h = __float22bfloat162_rn(make_float2(x, y));
    return *(uint32_t*)&h;
}
__device__ __forceinline__ uint32_t pack_lo(float x, float y) {
    __nv_bfloat16 hx = __float2bfloat16(x), hy = __float2bfloat16(y);
    __nv_bfloat162 l = __float22bfloat162_rn(
        make_float2(x - __bfloat162float(hx), y - __bfloat162float(hy)));
    return *(uint32_t*)&l;
}
__device__ __forceinline__ void cpa16(uint32_t s, const void* g) {
    asm volatile("cp.async.cg.shared.global [%0], [%1], 16;" :: "r"(s), "l"(g));
}
#define CP_COMMIT() asm volatile("cp.async.commit_group;" ::: "memory")
#define CP_WAIT1()  asm volatile("cp.async.wait_group 1;" ::: "memory")

// ---------------------------------------------------------------------------
// f32 -> hi/lo bf16 planes (7 jobs: 3 inputs + 4 weights)
// ---------------------------------------------------------------------------
struct ConvJob { const float* src; __nv_bfloat16 *h, *l; int n4; };
struct ConvBatch { ConvJob j[7]; };

__global__ __launch_bounds__(256, 4)
void convert_all(ConvBatch cb)
{
    ConvJob jb = cb.j[blockIdx.z];
    int i = blockIdx.x * 256 + threadIdx.x;
    if (i >= jb.n4) return;
    float4 v = ((const float4*)jb.src)[i];
    uint2 H, L;
    H.x = pack_hi(v.x, v.y); H.y = pack_hi(v.z, v.w);
    L.x = pack_lo(v.x, v.y); L.y = pack_lo(v.z, v.w);
    ((uint2*)jb.h)[i] = H;
    ((uint2*)jb.l)[i] = L;
}

// ---------------------------------------------------------------------------
// Tensor-core GEMM from pre-converted bf16 hi/lo planes.
// C[M,N] = A @ B^T + bias. 128x128x32 tile, 8 warps, cp.async 3-stage ring.
// smem plane: 128 rows x 80B (32 bf16 + pad), 4 planes/stage, 3 stages.
// ---------------------------------------------------------------------------
#define GROWB 80
#define GPLANE (128 * GROWB)     // 10240
#define GSTAGE (4 * GPLANE)      // 40960
#define GSM3 (3 * GSTAGE)        // 122880

struct GemmJob {
    const __nv_bfloat16 *Ah, *Al, *Bh, *Bl;
    const float* bias;
    float* C;
    __nv_bfloat16 *Ch, *Cl;      // optional bf16 hi/lo output planes (may be null)
};
struct GemmBatch { GemmJob j[3]; };

__global__ __launch_bounds__(256, 1)
void gemm_bf16(GemmBatch gb, int M, int N, int K)
{
    extern __shared__ __align__(128) char sm[];
    const uint32_t smb = smem_u32(sm);
    const GemmJob jb = gb.j[blockIdx.z];
    const int tid = threadIdx.x;
    const int wid = tid >> 5, lane = tid & 31;
    const int m0 = blockIdx.y * 128, n0 = blockIdx.x * 128;
    const int warp_m = (wid & 1) * 64;
    const int warp_n = (wid >> 1) * 32;
    const int nch = K / 32;

    const __nv_bfloat16* bases[4] = { jb.Ah, jb.Al, jb.Bh, jb.Bl };

    auto issue = [&](int ch) {
        const uint32_t sb = smb + (uint32_t)((ch % 3) * GSTAGE);
        const size_t gk = (size_t)ch * 32;
#pragma unroll
        for (int p = 0; p < 4; p++) {
            const int rbase = (p < 2) ? m0 : n0;
#pragma unroll
            for (int hh = 0; hh < 2; hh++) {
                int idx = hh * 256 + tid;      // 0..511
                int r = idx >> 2, c = idx & 3;
                cpa16(sb + (uint32_t)(p * GPLANE + r * 80 + c * 16),
                      bases[p] + (size_t)(rbase + r) * K + gk + c * 8);
            }
        }
    };

    float acc[4][4][4];
#pragma unroll
    for (int i = 0; i < 4; i++)
#pragma unroll
        for (int j = 0; j < 4; j++)
#pragma unroll
            for (int c = 0; c < 4; c++) acc[i][j][c] = 0.0f;

    issue(0); CP_COMMIT();
    issue(1); CP_COMMIT();

    const int arow = lane & 15;
    const int acol = (lane >> 4) * 8;
    const int bg = lane >> 3, bw = lane & 7;

    for (int ch = 0; ch < nch; ch++) {
        CP_WAIT1();
        __syncthreads();
        if (ch + 2 < nch) issue(ch + 2);
        CP_COMMIT();

        const uint32_t sb = smb + (uint32_t)((ch % 3) * GSTAGE);
#pragma unroll
        for (int ks = 0; ks < 2; ks++) {
            const int k16 = ks * 16;
            uint32_t ah[4][4], al[4][4];
#pragma unroll
            for (int mt = 0; mt < 4; mt++) {
                uint32_t off = (uint32_t)((warp_m + mt * 16 + arow) * 80 + (k16 + acol) * 2);
                ldsm4(ah[mt], sb + 0 * GPLANE + off);
                ldsm4(al[mt], sb + 1 * GPLANE + off);
            }
            uint32_t bh[4][2], bl[4][2];
#pragma unroll
            for (int nb = 0; nb < 2; nb++) {
                uint32_t off = (uint32_t)((warp_n + nb * 16 + (bg & 1) * 8 + bw) * 80
                                          + (k16 + (bg >> 1) * 8) * 2);
                uint32_t t[4];
                ldsm4(t, sb + 2 * GPLANE + off);
                bh[nb * 2 + 0][0] = t[0]; bh[nb * 2 + 0][1] = t[2];
                bh[nb * 2 + 1][0] = t[1]; bh[nb * 2 + 1][1] = t[3];
                ldsm4(t, sb + 3 * GPLANE + off);
                bl[nb * 2 + 0][0] = t[0]; bl[nb * 2 + 0][1] = t[2];
                bl[nb * 2 + 1][0] = t[1]; bl[nb * 2 + 1][1] = t[3];
            }
#pragma unroll
            for (int mt = 0; mt < 4; mt++)
#pragma unroll
                for (int nt = 0; nt < 4; nt++) {
                    mma16816(acc[mt][nt], ah[mt], bh[nt]);
                    mma16816(acc[mt][nt], ah[mt], bl[nt]);
                    mma16816(acc[mt][nt], al[mt], bh[nt]);
                }
        }
        __syncthreads();
    }

    const int lr = lane >> 2, lc = (lane & 3) * 2;
    const bool wplanes = (jb.Ch != nullptr);
#pragma unroll
    for (int nt = 0; nt < 4; nt++) {
        int col = n0 + warp_n + nt * 8 + lc;
        float2 bv = *(const float2*)&jb.bias[col];
#pragma unroll
        for (int mt = 0; mt < 4; mt++) {
            int r0 = m0 + warp_m + mt * 16 + lr;
            float2 o0 = make_float2(acc[mt][nt][0] + bv.x, acc[mt][nt][1] + bv.y);
            float2 o1 = make_float2(acc[mt][nt][2] + bv.x, acc[mt][nt][3] + bv.y);
            *(float2*)(jb.C + (size_t)r0 * N + col) = o0;
            *(float2*)(jb.C + (size_t)(r0 + 8) * N + col) = o1;
            if (wplanes) {
                size_t i0 = (size_t)r0 * N + col;
                size_t i1 = (size_t)(r0 + 8) * N + col;
                *(uint32_t*)&jb.Ch[i0] = pack_hi(o0.x, o0.y);
                *(uint32_t*)&jb.Cl[i0] = pack_lo(o0.x, o0.y);
                *(uint32_t*)&jb.Ch[i1] = pack_hi(o1.x, o1.y);
                *(uint32_t*)&jb.Cl[i1] = pack_lo(o1.x, o1.y);
            }
        }
    }
}

// ---------------------------------------------------------------------------
// Fused single-pass attention from bf16 planes. 128x128 S tile per CTA.
// ---------------------------------------------------------------------------
#define QROWB 144
#define VROWB 272
#define AQH 0
#define AQL 18432
#define AKH 36864
#define AKL 55296
#define AVH 73728
#define AVL 91136
#define APH 108544
#define APL 143360
#define SM2_TOT 178176

// raw copy of a 128x64 bf16 tile (gmem row stride Dc) into smem stride QROWB
__device__ __forceinline__ void copy_tile(const __nv_bfloat16* gp, char* sm,
                                          uint32_t off, int tid)
{
#pragma unroll
    for (int e = 0; e < 4; e++) {
        int idx = tid + e * 256;     // 0..1023
        int r = idx >> 3, c = idx & 7;
        *(uint4*)(sm + off + (uint32_t)(r * QROWB + c * 16)) =
            *(const uint4*)(gp + (size_t)r * Dc + c * 8);
    }
}

__device__ __forceinline__ void s_tile_mma(float acc[4][4][4], uint32_t smb,
                                           int warp_m, int warp_n, int lane)
{
    const int arow = lane & 15;
    const int acol = (lane >> 4) * 8;
    const int bg = lane >> 3, bw = lane & 7;
#pragma unroll
    for (int ks = 0; ks < 4; ks++) {
        const int k16 = ks * 16;
        uint32_t ah[4][4], al[4][4];
#pragma unroll
        for (int mt = 0; mt < 4; mt++) {
            uint32_t off = (uint32_t)((warp_m + mt * 16 + arow) * QROWB + (k16 + acol) * 2);
            ldsm4(ah[mt], smb + AQH + off);
            ldsm4(al[mt], smb + AQL + off);
        }
        uint32_t bh[4][2], bl[4][2];
#pragma unroll
        for (int nb = 0; nb < 2; nb++) {
            uint32_t off = (uint32_t)((warp_n + nb * 16 + (bg & 1) * 8 + bw) * QROWB
                                      + (k16 + (bg >> 1) * 8) * 2);
            uint32_t t[4];
            ldsm4(t, smb + AKH + off);
            bh[nb * 2 + 0][0] = t[0]; bh[nb * 2 + 0][1] = t[2];
            bh[nb * 2 + 1][0] = t[1]; bh[nb * 2 + 1][1] = t[3];
            ldsm4(t, smb + AKL + off);
            bl[nb * 2 + 0][0] = t[0]; bl[nb * 2 + 0][1] = t[2];
            bl[nb * 2 + 1][0] = t[1]; bl[nb * 2 + 1][1] = t[3];
        }
#pragma unroll
        for (int mt = 0; mt < 4; mt++)
#pragma unroll
            for (int nt = 0; nt < 4; nt++) {
                mma16816(acc[mt][nt], ah[mt], bh[nt]);
                mma16816(acc[mt][nt], ah[mt], bl[nt]);
                mma16816(acc[mt][nt], al[mt], bh[nt]);
            }
    }
}

__global__ __launch_bounds__(256, 1)
void attn_fused_mma(float* __restrict__ attn)
{
    extern __shared__ __align__(128) char sm[];
    const uint32_t smb = smem_u32(sm);
    const int tid = threadIdx.x;
    const int wid = tid >> 5, lane = tid & 31;
    const int b = blockIdx.z, h = blockIdx.y;
    const int it = (int)gridDim.x - 1 - (int)blockIdx.x;   // big tiles first
    const int r0 = it * 128;
    const int warp_m = (wid & 1) * 64;
    const int warp_n = (wid >> 1) * 32;
    const int wnp = (wid >> 1) * 16;
    const int lr = lane >> 2, lc2 = (lane & 3) * 2;
    const float CE = 0.125f * 1.4426950408889634f;

    const size_t qoff = ((size_t)b * Sc + r0) * Dc + h * DPc;
    const size_t koff = (size_t)b * Sc * Dc + h * DPc;
    const size_t bh_ = (size_t)(b * Hc + h);
    float* attnp = attn + bh_ * Sc * Sc;

    copy_tile(g_qh + qoff, sm, AQH, tid);
    copy_tile(g_ql + qoff, sm, AQL, tid);

    float ctx[4][2][4];
#pragma unroll
    for (int i = 0; i < 4; i++)
#pragma unroll
        for (int j = 0; j < 2; j++)
#pragma unroll
            for (int c = 0; c < 4; c++) ctx[i][j][c] = 0.0f;

    float lsum[4][2];
#pragma unroll
    for (int i = 0; i < 4; i++) { lsum[i][0] = 0.0f; lsum[i][1] = 0.0f; }

    const int arow = lane & 15;
    const int acol = (lane >> 4) * 8;
    const int bg = lane >> 3, bw = lane & 7;

    for (int jt = 0; jt <= it; jt++) {
        const int j0 = jt * 128;
        __syncthreads();
        copy_tile(g_kh + koff + (size_t)j0 * Dc, sm, AKH, tid);
        copy_tile(g_kl + koff + (size_t)j0 * Dc, sm, AKL, tid);
        // V^T from bf16 planes
        {
            const int j = tid >> 1;
            const int dbase = (tid & 1) * 32;
            const uint32_t* sh = (const uint32_t*)(g_vh + koff + (size_t)(j0 + j) * Dc + dbase);
            const uint32_t* sl = (const uint32_t*)(g_vl + koff + (size_t)(j0 + j) * Dc + dbase);
#pragma unroll
            for (int e = 0; e < 16; e++) {
                uint32_t wh = sh[e], wl = sl[e];
                int d = dbase + e * 2;
                *(uint16_t*)(sm + AVH + (d + 0) * VROWB + j * 2) = (uint16_t)wh;
                *(uint16_t*)(sm + AVH + (d + 1) * VROWB + j * 2) = (uint16_t)(wh >> 16);
                *(uint16_t*)(sm + AVL + (d + 0) * VROWB + j * 2) = (uint16_t)wl;
                *(uint16_t*)(sm + AVL + (d + 1) * VROWB + j * 2) = (uint16_t)(wl >> 16);
            }
        }
        __syncthreads();

        float acc[4][4][4];
#pragma unroll
        for (int i = 0; i < 4; i++)
#pragma unroll
            for (int j = 0; j < 4; j++)
#pragma unroll
                for (int c = 0; c < 4; c++) acc[i][j][c] = 0.0f;

        s_tile_mma(acc, smb, warp_m, warp_n, lane);

        const bool diag = (jt == it);
#pragma unroll
        for (int mt = 0; mt < 4; mt++)
#pragma unroll
            for (int hf = 0; hf < 2; hf++) {
                const int rowg = warp_m + mt * 16 + lr + hf * 8;
                const int growg = r0 + rowg;
                float rl = 0.0f;
#pragma unroll
                for (int nt = 0; nt < 4; nt++) {
                    int col = warp_n + nt * 8 + lc2;
                    float p0 = fexp2(acc[mt][nt][hf * 2 + 0] * CE);
                    float p1 = fexp2(acc[mt][nt][hf * 2 + 1] * CE);
                    if (diag && (j0 + col + 0) > growg) p0 = 0.0f;
                    if (diag && (j0 + col + 1) > growg) p1 = 0.0f;
                    *(float2*)&attnp[(size_t)growg * Sc + j0 + col] = make_float2(p0, p1);
                    *(uint32_t*)(sm + APH + rowg * VROWB + col * 2) = pack_hi(p0, p1);
                    *(uint32_t*)(sm + APL + rowg * VROWB + col * 2) = pack_lo(p0, p1);
                    rl += p0 + p1;
                }
                lsum[mt][hf] += rl;
            }
        __syncthreads();

#pragma unroll
        for (int ks = 0; ks < 8; ks++) {
            const int k16 = ks * 16;
            uint32_t ph[4][4], pl[4][4];
#pragma unroll
            for (int mt = 0; mt < 4; mt++) {
                uint32_t off = (uint32_t)((warp_m + mt * 16 + arow) * VROWB + (k16 + acol) * 2);
                ldsm4(ph[mt], smb + APH + off);
                ldsm4(pl[mt], smb + APL + off);
            }
            uint32_t vh[2][2], vl[2][2];
            {
                uint32_t off = (uint32_t)((wnp + (bg & 1) * 8 + bw) * VROWB
                                          + (k16 + (bg >> 1) * 8) * 2);
                uint32_t t[4];
                ldsm4(t, smb + AVH + off);
                vh[0][0] = t[0]; vh[0][1] = t[2];
                vh[1][0] = t[1]; vh[1][1] = t[3];
                ldsm4(t, smb + AVL + off);
                vl[0][0] = t[0]; vl[0][1] = t[2];
                vl[1][0] = t[1]; vl[1][1] = t[3];
            }
#pragma unroll
            for (int mt = 0; mt < 4; mt++)
#pragma unroll
                for (int ntp = 0; ntp < 2; ntp++) {
                    mma16816(ctx[mt][ntp], ph[mt], vh[ntp]);
                    mma16816(ctx[mt][ntp], ph[mt], vl[ntp]);
                    mma16816(ctx[mt][ntp], pl[mt], vh[ntp]);
                }
        }
    }

    // reduce row sums
#pragma unroll
    for (int off = 1; off <= 2; off <<= 1)
#pragma unroll
        for (int mt = 0; mt < 4; mt++)
#pragma unroll
            for (int hf = 0; hf < 2; hf++)
                lsum[mt][hf] += __shfl_xor_sync(0xffffffffu, lsum[mt][hf], off);

    __syncthreads();
    float* smR = (float*)(sm + AVH);
    float* smF = smR + 512;
    if ((lane & 3) == 0) {
        const int g = wid >> 1;
#pragma unroll
        for (int mt = 0; mt < 4; mt++)
#pragma unroll
            for (int hf = 0; hf < 2; hf++)
                smR[g * 128 + warp_m + mt * 16 + lr + hf * 8] = lsum[mt][hf];
    }
    __syncthreads();
    if (tid < 128) {
        float l = smR[tid] + smR[128 + tid] + smR[256 + tid] + smR[384 + tid];
        smF[tid] = 1.0f / l;
        g_lbuf[bh_ * Sc + r0 + tid] = l;
    }
    __syncthreads();

    // write normalized ctx hi/lo planes
#pragma unroll
    for (int mt = 0; mt < 4; mt++)
#pragma unroll
        for (int ntp = 0; ntp < 2; ntp++) {
            int dcol = h * DPc + wnp + ntp * 8 + lc2;
#pragma unroll
            for (int hf = 0; hf < 2; hf++) {
                int rowl = warp_m + mt * 16 + lr + hf * 8;
                float inv = smF[rowl];
                int row = r0 + rowl;
                float x0 = ctx[mt][ntp][hf * 2 + 0] * inv;
                float x1 = ctx[mt][ntp][hf * 2 + 1] * inv;
                size_t idx = ((size_t)b * Sc + row) * Dc + dcol;
                *(uint32_t*)&g_ch2[idx] = pack_hi(x0, x1);
                *(uint32_t*)&g_cl2[idx] = pack_lo(x0, x1);
            }
        }
}

// ---------------------------------------------------------------------------
// Normalize lower-tri attn rows by 1/l and zero-fill the causal upper part.
// ---------------------------------------------------------------------------
__global__ __launch_bounds__(256, 1)
void attn_norm_fill(float* __restrict__ attn)
{
    const int b = blockIdx.z, h = blockIdx.y, it = blockIdx.x;
    const int r0 = it * 128;
    const int tid = threadIdx.x;
    const size_t bh_ = (size_t)(b * Hc + h);
    float* ap = attn + bh_ * Sc * Sc;

    __shared__ float inv[128];
    if (tid < 128) inv[tid] = 1.0f / g_lbuf[bh_ * Sc + r0 + tid];
    __syncthreads();

    const int lim4 = (it + 1) * 32;
    for (int idx = tid; idx < 128 * 512; idx += 256) {
        int row = idx >> 9;
        int c4 = idx & 511;
        float4* p = (float4*)&ap[(size_t)(r0 + row) * Sc + c4 * 4];
        if (c4 < lim4) {
            float s = inv[row];
            float4 vv = *p;
            vv.x *= s; vv.y *= s; vv.z *= s; vv.w *= s;
            *p = vv;
        } else {
            *p = make_float4(0.f, 0.f, 0.f, 0.f);
        }
    }
}

// ---------------------------------------------------------------------------
extern "C" void kernel_launch(void* const* d_in, const int* in_sizes, int n_in,
                              void* d_out, int out_size)
{
    (void)in_sizes; (void)n_in; (void)out_size;
    const float* Q   = (const float*)d_in[0];
    const float* Kin = (const float*)d_in[1];
    const float* Vin = (const float*)d_in[2];
    const float* Wq = (const float*)d_in[4];
    const float* bq = (const float*)d_in[5];
    const float* Wk = (const float*)d_in[6];
    const float* bk = (const float*)d_in[7];
    const float* Wv = (const float*)d_in[8];
    const float* bv = (const float*)d_in[9];
    const float* Wo = (const float*)d_in[10];
    const float* bo = (const float*)d_in[11];

    float* out  = (float*)d_out;
    float* attn = out + SZ_QKV;
    float* qo   = attn + SZ_ATTN;
    float* ko   = qo + SZ_QKV;
    float* vo   = ko + SZ_QKV;

    // symbol addresses
    void *iah, *ial, *wh, *wl, *qh, *ql, *kh, *kl, *vh, *vl, *ch2, *cl2;
    cudaGetSymbolAddress(&iah, g_iah);  cudaGetSymbolAddress(&ial, g_ial);
    cudaGetSymbolAddress(&wh, g_wh);    cudaGetSymbolAddress(&wl, g_wl);
    cudaGetSymbolAddress(&qh, g_qh);    cudaGetSymbolAddress(&ql, g_ql);
    cudaGetSymbolAddress(&kh, g_kh);    cudaGetSymbolAddress(&kl, g_kl);
    cudaGetSymbolAddress(&vh, g_vh);    cudaGetSymbolAddress(&vl, g_vl);
    cudaGetSymbolAddress(&ch2, g_ch2);  cudaGetSymbolAddress(&cl2, g_cl2);
    __nv_bfloat16 *IAH = (__nv_bfloat16*)iah, *IAL = (__nv_bfloat16*)ial;
    __nv_bfloat16 *WH  = (__nv_bfloat16*)wh,  *WL  = (__nv_bfloat16*)wl;

    cudaFuncSetAttribute(gemm_bf16,
                         cudaFuncAttributeMaxDynamicSharedMemorySize, GSM3);
    cudaFuncSetAttribute(attn_fused_mma,
                         cudaFuncAttributeMaxDynamicSharedMemorySize, SM2_TOT);

    const int M = Bc * Sc;

    // 1) convert inputs + weights
    ConvBatch cb;
    const float* srcs[7] = { Q, Kin, Vin, Wq, Wk, Wv, Wo };
    for (int z = 0; z < 7; z++) {
        cb.j[z].src = srcs[z];
        if (z < 3) {
            cb.j[z].h = IAH + (size_t)z * MD;
            cb.j[z].l = IAL + (size_t)z * MD;
            cb.j[z].n4 = (int)(MD / 4);
        } else {
            cb.j[z].h = WH + (size_t)(z - 3) * DD;
            cb.j[z].l = WL + (size_t)(z - 3) * DD;
            cb.j[z].n4 = (int)(DD / 4);
        }
    }
    dim3 cgrid((unsigned)((MD / 4 + 255) / 256), 1, 7);
    convert_all<<<cgrid, 256>>>(cb);

    // 2) QKV projections (fused, epilogue emits bf16 planes)
    GemmBatch qb;
    const float* biases[3] = { bq, bk, bv };
    float* outs[3] = { qo, ko, vo };
    __nv_bfloat16* chp[3] = { (__nv_bfloat16*)qh, (__nv_bfloat16*)kh, (__nv_bfloat16*)vh };
    __nv_bfloat16* clp[3] = { (__nv_bfloat16*)ql, (__nv_bfloat16*)kl, (__nv_bfloat16*)vl };
    for (int z = 0; z < 3; z++) {
        qb.j[z].Ah = IAH + (size_t)z * MD; qb.j[z].Al = IAL + (size_t)z * MD;
        qb.j[z].Bh = WH + (size_t)z * DD;  qb.j[z].Bl = WL + (size_t)z * DD;
        qb.j[z].bias = biases[z]; qb.j[z].C = outs[z];
        qb.j[z].Ch = chp[z]; qb.j[z].Cl = clp[z];
    }
    dim3 qgrid(Dc / 128, M / 128, 3);
    gemm_bf16<<<qgrid, 256, GSM3>>>(qb, M, Dc, Dc);

    // 3) fused attention + norm/zero fill
    dim3 agrid(Sc / 128, Hc, Bc);
    attn_fused_mma<<<agrid, 256, SM2_TOT>>>(attn);
    attn_norm_fill<<<agrid, 256>>>(attn);

    // 4) output projection (A = ctx planes)
    GemmBatch ob;
    ob.j[0].Ah = (__nv_bfloat16*)ch2; ob.j[0].Al = (__nv_bfloat16*)cl2;
    ob.j[0].Bh = WH + 3 * DD;         ob.j[0].Bl = WL + 3 * DD;
    ob.j[0].bias = bo; ob.j[0].C = out;
    ob.j[0].Ch = nullptr; ob.j[0].Cl = nullptr;
    ob.j[1] = ob.j[0]; ob.j[2] = ob.j[0];
    dim3 ogrid(Dc / 128, M / 128, 1);
    gemm_bf16<<<ogrid, 256, GSM3>>>(ob, M, Dc, Dc);
}

// round 7
// speedup vs baseline: 1.0724x; 1.0724x over previous
#include <cuda_runtime.h>
#include <cuda_bf16.h>
#include <math.h>
#include <stdint.h>

#define Bc 2
#define Sc 2048
#define Dc 1024
#define Hc 16
#define DPc 64

static const size_t SZ_QKV  = (size_t)Bc * Sc * Dc;        // 4194304
static const size_t SZ_ATTN = (size_t)Bc * Hc * Sc * Sc;   // 134217728
#define MD  ((size_t)4194304)       // M*Dc
#define DD  ((size_t)1048576)       // Dc*Dc

// bf16 hi/lo plane scratch (allocation-free device globals)
__device__ __nv_bfloat16 g_iah[3 * MD], g_ial[3 * MD];   // Q,K,V inputs
__device__ __nv_bfloat16 g_wh[4 * DD],  g_wl[4 * DD];    // Wq,Wk,Wv,Wo
__device__ __nv_bfloat16 g_qh[MD], g_ql[MD];
__device__ __nv_bfloat16 g_kh[MD], g_kl[MD];
__device__ __nv_bfloat16 g_vh[MD], g_vl[MD];
__device__ __nv_bfloat16 g_ch2[MD], g_cl2[MD];           // ctx planes
__device__ float g_lbuf[(size_t)Bc * Hc * Sc];

// ---------------------------------------------------------------------------
// helpers
// ---------------------------------------------------------------------------
__device__ __forceinline__ uint32_t smem_u32(const void* p) {
    uint32_t a;
    asm("{ .reg .u64 t; cvta.to.shared.u64 t, %1; cvt.u32.u64 %0, t; }"
        : "=r"(a) : "l"(p));
    return a;
}
__device__ __forceinline__ void mma16816(float* d, const uint32_t* a, const uint32_t* b) {
    asm volatile(
        "mma.sync.aligned.m16n8k16.row.col.f32.bf16.bf16.f32 "
        "{%0,%1,%2,%3}, {%4,%5,%6,%7}, {%8,%9}, {%0,%1,%2,%3};"
        : "+f"(d[0]), "+f"(d[1]), "+f"(d[2]), "+f"(d[3])
        : "r"(a[0]), "r"(a[1]), "r"(a[2]), "r"(a[3]), "r"(b[0]), "r"(b[1]));
}
__device__ __forceinline__ void ldsm4(uint32_t* r, uint32_t addr) {
    asm volatile("ldmatrix.sync.aligned.m8n8.x4.shared.b16 {%0,%1,%2,%3}, [%4];"
                 : "=r"(r[0]), "=r"(r[1]), "=r"(r[2]), "=r"(r[3]) : "r"(addr));
}
__device__ __forceinline__ float fexp2(float x) {
    float r;
    asm("ex2.approx.f32 %0, %1;" : "=f"(r) : "f"(x));
    return r;
}
__device__ __forceinline__ uint32_t pack_hi(float x, float y) {
    __nv_bfloat162 h = __float22bfloat162_rn(make_float2(x, y));
    return *(uint32_t*)&h;
}
__device__ __forceinline__ uint32_t pack_lo(float x, float y) {
    __nv_bfloat16 hx = __float2bfloat16(x), hy = __float2bfloat16(y);
    __nv_bfloat162 l = __float22bfloat162_rn(
        make_float2(x - __bfloat162float(hx), y - __bfloat162float(hy)));
    return *(uint32_t*)&l;
}
__device__ __forceinline__ void cpa16(uint32_t s, const void* g) {
    asm volatile("cp.async.cg.shared.global [%0], [%1], 16;" :: "r"(s), "l"(g));
}
#define CP_COMMIT() asm volatile("cp.async.commit_group;" ::: "memory")
#define CP_WAIT1()  asm volatile("cp.async.wait_group 1;" ::: "memory")

// ---------------------------------------------------------------------------
// f32 -> hi/lo bf16 planes (7 jobs: 3 inputs + 4 weights)
// ---------------------------------------------------------------------------
struct ConvJob { const float* src; __nv_bfloat16 *h, *l; int n4; };
struct ConvBatch { ConvJob j[7]; };

__global__ __launch_bounds__(256, 4)
void convert_all(ConvBatch cb)
{
    ConvJob jb = cb.j[blockIdx.z];
    int i = blockIdx.x * 256 + threadIdx.x;
    if (i >= jb.n4) return;
    float4 v = ((const float4*)jb.src)[i];
    uint2 H, L;
    H.x = pack_hi(v.x, v.y); H.y = pack_hi(v.z, v.w);
    L.x = pack_lo(v.x, v.y); L.y = pack_lo(v.z, v.w);
    ((uint2*)jb.h)[i] = H;
    ((uint2*)jb.l)[i] = L;
}

// ---------------------------------------------------------------------------
// Tensor-core GEMM from pre-converted bf16 hi/lo planes. (unchanged from R6)
// ---------------------------------------------------------------------------
#define GROWB 80
#define GPLANE (128 * GROWB)     // 10240
#define GSTAGE (4 * GPLANE)      // 40960
#define GSM3 (3 * GSTAGE)        // 122880

struct GemmJob {
    const __nv_bfloat16 *Ah, *Al, *Bh, *Bl;
    const float* bias;
    float* C;
    __nv_bfloat16 *Ch, *Cl;
};
struct GemmBatch { GemmJob j[3]; };

__global__ __launch_bounds__(256, 1)
void gemm_bf16(GemmBatch gb, int M, int N, int K)
{
    extern __shared__ __align__(128) char sm[];
    const uint32_t smb = smem_u32(sm);
    const GemmJob jb = gb.j[blockIdx.z];
    const int tid = threadIdx.x;
    const int wid = tid >> 5, lane = tid & 31;
    const int m0 = blockIdx.y * 128, n0 = blockIdx.x * 128;
    const int warp_m = (wid & 1) * 64;
    const int warp_n = (wid >> 1) * 32;
    const int nch = K / 32;

    const __nv_bfloat16* bases[4] = { jb.Ah, jb.Al, jb.Bh, jb.Bl };

    auto issue = [&](int ch) {
        const uint32_t sb = smb + (uint32_t)((ch % 3) * GSTAGE);
        const size_t gk = (size_t)ch * 32;
#pragma unroll
        for (int p = 0; p < 4; p++) {
            const int rbase = (p < 2) ? m0 : n0;
#pragma unroll
            for (int hh = 0; hh < 2; hh++) {
                int idx = hh * 256 + tid;
                int r = idx >> 2, c = idx & 3;
                cpa16(sb + (uint32_t)(p * GPLANE + r * 80 + c * 16),
                      bases[p] + (size_t)(rbase + r) * K + gk + c * 8);
            }
        }
    };

    float acc[4][4][4];
#pragma unroll
    for (int i = 0; i < 4; i++)
#pragma unroll
        for (int j = 0; j < 4; j++)
#pragma unroll
            for (int c = 0; c < 4; c++) acc[i][j][c] = 0.0f;

    issue(0); CP_COMMIT();
    issue(1); CP_COMMIT();

    const int arow = lane & 15;
    const int acol = (lane >> 4) * 8;
    const int bg = lane >> 3, bw = lane & 7;

    for (int ch = 0; ch < nch; ch++) {
        CP_WAIT1();
        __syncthreads();
        if (ch + 2 < nch) issue(ch + 2);
        CP_COMMIT();

        const uint32_t sb = smb + (uint32_t)((ch % 3) * GSTAGE);
#pragma unroll
        for (int ks = 0; ks < 2; ks++) {
            const int k16 = ks * 16;
            uint32_t ah[4][4], al[4][4];
#pragma unroll
            for (int mt = 0; mt < 4; mt++) {
                uint32_t off = (uint32_t)((warp_m + mt * 16 + arow) * 80 + (k16 + acol) * 2);
                ldsm4(ah[mt], sb + 0 * GPLANE + off);
                ldsm4(al[mt], sb + 1 * GPLANE + off);
            }
            uint32_t bh[4][2], bl[4][2];
#pragma unroll
            for (int nb = 0; nb < 2; nb++) {
                uint32_t off = (uint32_t)((warp_n + nb * 16 + (bg & 1) * 8 + bw) * 80
                                          + (k16 + (bg >> 1) * 8) * 2);
                uint32_t t[4];
                ldsm4(t, sb + 2 * GPLANE + off);
                bh[nb * 2 + 0][0] = t[0]; bh[nb * 2 + 0][1] = t[2];
                bh[nb * 2 + 1][0] = t[1]; bh[nb * 2 + 1][1] = t[3];
                ldsm4(t, sb + 3 * GPLANE + off);
                bl[nb * 2 + 0][0] = t[0]; bl[nb * 2 + 0][1] = t[2];
                bl[nb * 2 + 1][0] = t[1]; bl[nb * 2 + 1][1] = t[3];
            }
#pragma unroll
            for (int mt = 0; mt < 4; mt++)
#pragma unroll
                for (int nt = 0; nt < 4; nt++) {
                    mma16816(acc[mt][nt], ah[mt], bh[nt]);
                    mma16816(acc[mt][nt], ah[mt], bl[nt]);
                    mma16816(acc[mt][nt], al[mt], bh[nt]);
                }
        }
        __syncthreads();
    }

    const int lr = lane >> 2, lc = (lane & 3) * 2;
    const bool wplanes = (jb.Ch != nullptr);
#pragma unroll
    for (int nt = 0; nt < 4; nt++) {
        int col = n0 + warp_n + nt * 8 + lc;
        float2 bv = *(const float2*)&jb.bias[col];
#pragma unroll
        for (int mt = 0; mt < 4; mt++) {
            int r0 = m0 + warp_m + mt * 16 + lr;
            float2 o0 = make_float2(acc[mt][nt][0] + bv.x, acc[mt][nt][1] + bv.y);
            float2 o1 = make_float2(acc[mt][nt][2] + bv.x, acc[mt][nt][3] + bv.y);
            *(float2*)(jb.C + (size_t)r0 * N + col) = o0;
            *(float2*)(jb.C + (size_t)(r0 + 8) * N + col) = o1;
            if (wplanes) {
                size_t i0 = (size_t)r0 * N + col;
                size_t i1 = (size_t)(r0 + 8) * N + col;
                *(uint32_t*)&jb.Ch[i0] = pack_hi(o0.x, o0.y);
                *(uint32_t*)&jb.Cl[i0] = pack_lo(o0.x, o0.y);
                *(uint32_t*)&jb.Ch[i1] = pack_hi(o1.x, o1.y);
                *(uint32_t*)&jb.Cl[i1] = pack_lo(o1.x, o1.y);
            }
        }
    }
}

// ---------------------------------------------------------------------------
// Fused single-pass attention from bf16 planes (unchanged from R6).
// ---------------------------------------------------------------------------
#define QROWB 144
#define VROWB 272
#define AQH 0
#define AQL 18432
#define AKH 36864
#define AKL 55296
#define AVH 73728
#define AVL 91136
#define APH 108544
#define APL 143360
#define SM2_TOT 178176

__device__ __forceinline__ void copy_tile(const __nv_bfloat16* gp, char* sm,
                                          uint32_t off, int tid)
{
#pragma unroll
    for (int e = 0; e < 4; e++) {
        int idx = tid + e * 256;
        int r = idx >> 3, c = idx & 7;
        *(uint4*)(sm + off + (uint32_t)(r * QROWB + c * 16)) =
            *(const uint4*)(gp + (size_t)r * Dc + c * 8);
    }
}

__device__ __forceinline__ void s_tile_mma(float acc[4][4][4], uint32_t smb,
                                           int warp_m, int warp_n, int lane)
{
    const int arow = lane & 15;
    const int acol = (lane >> 4) * 8;
    const int bg = lane >> 3, bw = lane & 7;
#pragma unroll
    for (int ks = 0; ks < 4; ks++) {
        const int k16 = ks * 16;
        uint32_t ah[4][4], al[4][4];
#pragma unroll
        for (int mt = 0; mt < 4; mt++) {
            uint32_t off = (uint32_t)((warp_m + mt * 16 + arow) * QROWB + (k16 + acol) * 2);
            ldsm4(ah[mt], smb + AQH + off);
            ldsm4(al[mt], smb + AQL + off);
        }
        uint32_t bh[4][2], bl[4][2];
#pragma unroll
        for (int nb = 0; nb < 2; nb++) {
            uint32_t off = (uint32_t)((warp_n + nb * 16 + (bg & 1) * 8 + bw) * QROWB
                                      + (k16 + (bg >> 1) * 8) * 2);
            uint32_t t[4];
            ldsm4(t, smb + AKH + off);
            bh[nb * 2 + 0][0] = t[0]; bh[nb * 2 + 0][1] = t[2];
            bh[nb * 2 + 1][0] = t[1]; bh[nb * 2 + 1][1] = t[3];
            ldsm4(t, smb + AKL + off);
            bl[nb * 2 + 0][0] = t[0]; bl[nb * 2 + 0][1] = t[2];
            bl[nb * 2 + 1][0] = t[1]; bl[nb * 2 + 1][1] = t[3];
        }
#pragma unroll
        for (int mt = 0; mt < 4; mt++)
#pragma unroll
            for (int nt = 0; nt < 4; nt++) {
                mma16816(acc[mt][nt], ah[mt], bh[nt]);
                mma16816(acc[mt][nt], ah[mt], bl[nt]);
                mma16816(acc[mt][nt], al[mt], bh[nt]);
            }
    }
}

__global__ __launch_bounds__(256, 1)
void attn_fused_mma(float* __restrict__ attn)
{
    extern __shared__ __align__(128) char sm[];
    const uint32_t smb = smem_u32(sm);
    const int tid = threadIdx.x;
    const int wid = tid >> 5, lane = tid & 31;
    const int b = blockIdx.z, h = blockIdx.y;
    const int it = (int)gridDim.x - 1 - (int)blockIdx.x;
    const int r0 = it * 128;
    const int warp_m = (wid & 1) * 64;
    const int warp_n = (wid >> 1) * 32;
    const int wnp = (wid >> 1) * 16;
    const int lr = lane >> 2, lc2 = (lane & 3) * 2;
    const float CE = 0.125f * 1.4426950408889634f;

    const size_t qoff = ((size_t)b * Sc + r0) * Dc + h * DPc;
    const size_t koff = (size_t)b * Sc * Dc + h * DPc;
    const size_t bh_ = (size_t)(b * Hc + h);
    float* attnp = attn + bh_ * Sc * Sc;

    copy_tile(g_qh + qoff, sm, AQH, tid);
    copy_tile(g_ql + qoff, sm, AQL, tid);

    float ctx[4][2][4];
#pragma unroll
    for (int i = 0; i < 4; i++)
#pragma unroll
        for (int j = 0; j < 2; j++)
#pragma unroll
            for (int c = 0; c < 4; c++) ctx[i][j][c] = 0.0f;

    float lsum[4][2];
#pragma unroll
    for (int i = 0; i < 4; i++) { lsum[i][0] = 0.0f; lsum[i][1] = 0.0f; }

    const int arow = lane & 15;
    const int acol = (lane >> 4) * 8;
    const int bg = lane >> 3, bw = lane & 7;

    for (int jt = 0; jt <= it; jt++) {
        const int j0 = jt * 128;
        __syncthreads();
        copy_tile(g_kh + koff + (size_t)j0 * Dc, sm, AKH, tid);
        copy_tile(g_kl + koff + (size_t)j0 * Dc, sm, AKL, tid);
        {
            const int j = tid >> 1;
            const int dbase = (tid & 1) * 32;
            const uint32_t* sh = (const uint32_t*)(g_vh + koff + (size_t)(j0 + j) * Dc + dbase);
            const uint32_t* sl = (const uint32_t*)(g_vl + koff + (size_t)(j0 + j) * Dc + dbase);
#pragma unroll
            for (int e = 0; e < 16; e++) {
                uint32_t wh = sh[e], wl = sl[e];
                int d = dbase + e * 2;
                *(uint16_t*)(sm + AVH + (d + 0) * VROWB + j * 2) = (uint16_t)wh;
                *(uint16_t*)(sm + AVH + (d + 1) * VROWB + j * 2) = (uint16_t)(wh >> 16);
                *(uint16_t*)(sm + AVL + (d + 0) * VROWB + j * 2) = (uint16_t)wl;
                *(uint16_t*)(sm + AVL + (d + 1) * VROWB + j * 2) = (uint16_t)(wl >> 16);
            }
        }
        __syncthreads();

        float acc[4][4][4];
#pragma unroll
        for (int i = 0; i < 4; i++)
#pragma unroll
            for (int j = 0; j < 4; j++)
#pragma unroll
                for (int c = 0; c < 4; c++) acc[i][j][c] = 0.0f;

        s_tile_mma(acc, smb, warp_m, warp_n, lane);

        const bool diag = (jt == it);
#pragma unroll
        for (int mt = 0; mt < 4; mt++)
#pragma unroll
            for (int hf = 0; hf < 2; hf++) {
                const int rowg = warp_m + mt * 16 + lr + hf * 8;
                const int growg = r0 + rowg;
                float rl = 0.0f;
#pragma unroll
                for (int nt = 0; nt < 4; nt++) {
                    int col = warp_n + nt * 8 + lc2;
                    float p0 = fexp2(acc[mt][nt][hf * 2 + 0] * CE);
                    float p1 = fexp2(acc[mt][nt][hf * 2 + 1] * CE);
                    if (diag && (j0 + col + 0) > growg) p0 = 0.0f;
                    if (diag && (j0 + col + 1) > growg) p1 = 0.0f;
                    *(float2*)&attnp[(size_t)growg * Sc + j0 + col] = make_float2(p0, p1);
                    *(uint32_t*)(sm + APH + rowg * VROWB + col * 2) = pack_hi(p0, p1);
                    *(uint32_t*)(sm + APL + rowg * VROWB + col * 2) = pack_lo(p0, p1);
                    rl += p0 + p1;
                }
                lsum[mt][hf] += rl;
            }
        __syncthreads();

#pragma unroll
        for (int ks = 0; ks < 8; ks++) {
            const int k16 = ks * 16;
            uint32_t ph[4][4], pl[4][4];
#pragma unroll
            for (int mt = 0; mt < 4; mt++) {
                uint32_t off = (uint32_t)((warp_m + mt * 16 + arow) * VROWB + (k16 + acol) * 2);
                ldsm4(ph[mt], smb + APH + off);
                ldsm4(pl[mt], smb + APL + off);
            }
            uint32_t vh[2][2], vl[2][2];
            {
                uint32_t off = (uint32_t)((wnp + (bg & 1) * 8 + bw) * VROWB
                                          + (k16 + (bg >> 1) * 8) * 2);
                uint32_t t[4];
                ldsm4(t, smb + AVH + off);
                vh[0][0] = t[0]; vh[0][1] = t[2];
                vh[1][0] = t[1]; vh[1][1] = t[3];
                ldsm4(t, smb + AVL + off);
                vl[0][0] = t[0]; vl[0][1] = t[2];
                vl[1][0] = t[1]; vl[1][1] = t[3];
            }
#pragma unroll
            for (int mt = 0; mt < 4; mt++)
#pragma unroll
                for (int ntp = 0; ntp < 2; ntp++) {
                    mma16816(ctx[mt][ntp], ph[mt], vh[ntp]);
                    mma16816(ctx[mt][ntp], ph[mt], vl[ntp]);
                    mma16816(ctx[mt][ntp], pl[mt], vh[ntp]);
                }
        }
    }

#pragma unroll
    for (int off = 1; off <= 2; off <<= 1)
#pragma unroll
        for (int mt = 0; mt < 4; mt++)
#pragma unroll
            for (int hf = 0; hf < 2; hf++)
                lsum[mt][hf] += __shfl_xor_sync(0xffffffffu, lsum[mt][hf], off);

    __syncthreads();
    float* smR = (float*)(sm + AVH);
    float* smF = smR + 512;
    if ((lane & 3) == 0) {
        const int g = wid >> 1;
#pragma unroll
        for (int mt = 0; mt < 4; mt++)
#pragma unroll
            for (int hf = 0; hf < 2; hf++)
                smR[g * 128 + warp_m + mt * 16 + lr + hf * 8] = lsum[mt][hf];
    }
    __syncthreads();
    if (tid < 128) {
        float l = smR[tid] + smR[128 + tid] + smR[256 + tid] + smR[384 + tid];
        smF[tid] = 1.0f / l;
        g_lbuf[bh_ * Sc + r0 + tid] = l;
    }
    __syncthreads();

#pragma unroll
    for (int mt = 0; mt < 4; mt++)
#pragma unroll
        for (int ntp = 0; ntp < 2; ntp++) {
            int dcol = h * DPc + wnp + ntp * 8 + lc2;
#pragma unroll
            for (int hf = 0; hf < 2; hf++) {
                int rowl = warp_m + mt * 16 + lr + hf * 8;
                float inv = smF[rowl];
                int row = r0 + rowl;
                float x0 = ctx[mt][ntp][hf * 2 + 0] * inv;
                float x1 = ctx[mt][ntp][hf * 2 + 1] * inv;
                size_t idx = ((size_t)b * Sc + row) * Dc + dcol;
                *(uint32_t*)&g_ch2[idx] = pack_hi(x0, x1);
                *(uint32_t*)&g_cl2[idx] = pack_lo(x0, x1);
            }
        }
}

// ---------------------------------------------------------------------------
// fill_upper: zero the causal upper triangle (no dependencies; overlaps attn)
// ---------------------------------------------------------------------------
__global__ __launch_bounds__(512, 2)
void fill_upper(float* __restrict__ attn)
{
    const int b = blockIdx.z, h = blockIdx.y, it = blockIdx.x;
    const int ncol4 = 512 - (it + 1) * 32;
    if (ncol4 <= 0) return;
    const int c0 = (it + 1) * 32;
    float* ap = attn + ((size_t)(b * Hc + h)) * Sc * Sc + (size_t)it * 128 * Sc;
    const float4 z = make_float4(0.f, 0.f, 0.f, 0.f);
    const int tid = threadIdx.x;
    const int total = 128 * ncol4;
    for (int i = tid; i < total; i += 512) {
        int r = i / ncol4, c = i - r * ncol4;
        ((float4*)&ap[(size_t)r * Sc])[c0 + c] = z;
    }
}

// ---------------------------------------------------------------------------
// norm_lower: scale lower-triangle attn rows by 1/l (overlaps O-GEMM)
// ---------------------------------------------------------------------------
__global__ __launch_bounds__(512, 2)
void norm_lower(float* __restrict__ attn)
{
    const int b = blockIdx.z, h = blockIdx.y, it = blockIdx.x;
    const int r0 = it * 128;
    const int tid = threadIdx.x;
    const size_t bh_ = (size_t)(b * Hc + h);
    float* ap = attn + bh_ * Sc * Sc;

    __shared__ float inv[128];
    if (tid < 128) inv[tid] = 1.0f / g_lbuf[bh_ * Sc + r0 + tid];
    __syncthreads();

    const int ncol4 = (it + 1) * 32;
    for (int r = tid >> 7; r < 128; r += 4) {
        const float s = inv[r];
        float4* rowp = (float4*)&ap[(size_t)(r0 + r) * Sc];
#pragma unroll 4
        for (int c4 = (tid & 127); c4 < ncol4; c4 += 128) {
            float4 v = rowp[c4];
            v.x *= s; v.y *= s; v.z *= s; v.w *= s;
            rowp[c4] = v;
        }
    }
}

// ---------------------------------------------------------------------------
extern "C" void kernel_launch(void* const* d_in, const int* in_sizes, int n_in,
                              void* d_out, int out_size)
{
    (void)in_sizes; (void)n_in; (void)out_size;
    const float* Q   = (const float*)d_in[0];
    const float* Kin = (const float*)d_in[1];
    const float* Vin = (const float*)d_in[2];
    const float* Wq = (const float*)d_in[4];
    const float* bq = (const float*)d_in[5];
    const float* Wk = (const float*)d_in[6];
    const float* bk = (const float*)d_in[7];
    const float* Wv = (const float*)d_in[8];
    const float* bv = (const float*)d_in[9];
    const float* Wo = (const float*)d_in[10];
    const float* bo = (const float*)d_in[11];

    float* out  = (float*)d_out;
    float* attn = out + SZ_QKV;
    float* qo   = attn + SZ_ATTN;
    float* ko   = qo + SZ_QKV;
    float* vo   = ko + SZ_QKV;

    void *iah, *ial, *wh, *wl, *qh, *ql, *kh, *kl, *vh, *vl, *ch2, *cl2;
    cudaGetSymbolAddress(&iah, g_iah);  cudaGetSymbolAddress(&ial, g_ial);
    cudaGetSymbolAddress(&wh, g_wh);    cudaGetSymbolAddress(&wl, g_wl);
    cudaGetSymbolAddress(&qh, g_qh);    cudaGetSymbolAddress(&ql, g_ql);
    cudaGetSymbolAddress(&kh, g_kh);    cudaGetSymbolAddress(&kl, g_kl);
    cudaGetSymbolAddress(&vh, g_vh);    cudaGetSymbolAddress(&vl, g_vl);
    cudaGetSymbolAddress(&ch2, g_ch2);  cudaGetSymbolAddress(&cl2, g_cl2);
    __nv_bfloat16 *IAH = (__nv_bfloat16*)iah, *IAL = (__nv_bfloat16*)ial;
    __nv_bfloat16 *WH  = (__nv_bfloat16*)wh,  *WL  = (__nv_bfloat16*)wl;

    cudaFuncSetAttribute(gemm_bf16,
                         cudaFuncAttributeMaxDynamicSharedMemorySize, GSM3);
    cudaFuncSetAttribute(attn_fused_mma,
                         cudaFuncAttributeMaxDynamicSharedMemorySize, SM2_TOT);

    const int M = Bc * Sc;

    // side stream + events for graph-captured fork/join (no device allocs)
    cudaStream_t s1;
    cudaStreamCreateWithFlags(&s1, cudaStreamNonBlocking);
    cudaEvent_t e0, e1, e2;
    cudaEventCreateWithFlags(&e0, cudaEventDisableTiming);
    cudaEventCreateWithFlags(&e1, cudaEventDisableTiming);
    cudaEventCreateWithFlags(&e2, cudaEventDisableTiming);

    // 1) convert inputs + weights
    ConvBatch cb;
    const float* srcs[7] = { Q, Kin, Vin, Wq, Wk, Wv, Wo };
    for (int z = 0; z < 7; z++) {
        cb.j[z].src = srcs[z];
        if (z < 3) {
            cb.j[z].h = IAH + (size_t)z * MD;
            cb.j[z].l = IAL + (size_t)z * MD;
            cb.j[z].n4 = (int)(MD / 4);
        } else {
            cb.j[z].h = WH + (size_t)(z - 3) * DD;
            cb.j[z].l = WL + (size_t)(z - 3) * DD;
            cb.j[z].n4 = (int)(DD / 4);
        }
    }
    dim3 cgrid((unsigned)((MD / 4 + 255) / 256), 1, 7);
    convert_all<<<cgrid, 256>>>(cb);

    // 2) QKV projections
    GemmBatch qb;
    const float* biases[3] = { bq, bk, bv };
    float* outs[3] = { qo, ko, vo };
    __nv_bfloat16* chp[3] = { (__nv_bfloat16*)qh, (__nv_bfloat16*)kh, (__nv_bfloat16*)vh };
    __nv_bfloat16* clp[3] = { (__nv_bfloat16*)ql, (__nv_bfloat16*)kl, (__nv_bfloat16*)vl };
    for (int z = 0; z < 3; z++) {
        qb.j[z].Ah = IAH + (size_t)z * MD; qb.j[z].Al = IAL + (size_t)z * MD;
        qb.j[z].Bh = WH + (size_t)z * DD;  qb.j[z].Bl = WL + (size_t)z * DD;
        qb.j[z].bias = biases[z]; qb.j[z].C = outs[z];
        qb.j[z].Ch = chp[z]; qb.j[z].Cl = clp[z];
    }
    dim3 qgrid(Dc / 128, M / 128, 3);
    gemm_bf16<<<qgrid, 256, GSM3>>>(qb, M, Dc, Dc);

    // fork: fill_upper (independent) runs concurrent with attn_fused
    cudaEventRecord(e0, 0);
    cudaStreamWaitEvent(s1, e0, 0);
    dim3 agrid(Sc / 128, Hc, Bc);
    fill_upper<<<agrid, 512, 0, s1>>>(attn);

    // 3) fused attention on main stream
    attn_fused_mma<<<agrid, 256, SM2_TOT>>>(attn);
    cudaEventRecord(e1, 0);

    // norm_lower on s1 (after attn + after its own fill_upper)
    cudaStreamWaitEvent(s1, e1, 0);
    norm_lower<<<agrid, 512, 0, s1>>>(attn);
    cudaEventRecord(e2, s1);

    // 4) output projection on main stream, concurrent with norm_lower
    GemmBatch ob;
    ob.j[0].Ah = (__nv_bfloat16*)ch2; ob.j[0].Al = (__nv_bfloat16*)cl2;
    ob.j[0].Bh = WH + 3 * DD;         ob.j[0].Bl = WL + 3 * DD;
    ob.j[0].bias = bo; ob.j[0].C = out;
    ob.j[0].Ch = nullptr; ob.j[0].Cl = nullptr;
    ob.j[1] = ob.j[0]; ob.j[2] = ob.j[0];
    dim3 ogrid(Dc / 128, M / 128, 1);
    gemm_bf16<<<ogrid, 256, GSM3>>>(ob, M, Dc, Dc);

    // join
    cudaStreamWaitEvent(0, e2, 0);
}

// round 8
// speedup vs baseline: 1.2355x; 1.1521x over previous
#include <cuda_runtime.h>
#include <cuda_bf16.h>
#include <math.h>
#include <stdint.h>

#define Bc 2
#define Sc 2048
#define Dc 1024
#define Hc 16
#define DPc 64

static const size_t SZ_QKV  = (size_t)Bc * Sc * Dc;        // 4194304
static const size_t SZ_ATTN = (size_t)Bc * Hc * Sc * Sc;   // 134217728
#define MD  ((size_t)4194304)
#define DD  ((size_t)1048576)

__device__ __nv_bfloat16 g_iah[3 * MD], g_ial[3 * MD];
__device__ __nv_bfloat16 g_wh[4 * DD],  g_wl[4 * DD];
__device__ __nv_bfloat16 g_qh[MD], g_ql[MD];
__device__ __nv_bfloat16 g_kh[MD], g_kl[MD];
__device__ __nv_bfloat16 g_vh[MD], g_vl[MD];
__device__ __nv_bfloat16 g_ch2[MD], g_cl2[MD];
__device__ float g_lbuf[(size_t)Bc * Hc * Sc];

// ---------------------------------------------------------------------------
__device__ __forceinline__ uint32_t smem_u32(const void* p) {
    uint32_t a;
    asm("{ .reg .u64 t; cvta.to.shared.u64 t, %1; cvt.u32.u64 %0, t; }"
        : "=r"(a) : "l"(p));
    return a;
}
__device__ __forceinline__ void mma16816(float* d, const uint32_t* a, const uint32_t* b) {
    asm volatile(
        "mma.sync.aligned.m16n8k16.row.col.f32.bf16.bf16.f32 "
        "{%0,%1,%2,%3}, {%4,%5,%6,%7}, {%8,%9}, {%0,%1,%2,%3};"
        : "+f"(d[0]), "+f"(d[1]), "+f"(d[2]), "+f"(d[3])
        : "r"(a[0]), "r"(a[1]), "r"(a[2]), "r"(a[3]), "r"(b[0]), "r"(b[1]));
}
__device__ __forceinline__ void ldsm4(uint32_t* r, uint32_t addr) {
    asm volatile("ldmatrix.sync.aligned.m8n8.x4.shared.b16 {%0,%1,%2,%3}, [%4];"
                 : "=r"(r[0]), "=r"(r[1]), "=r"(r[2]), "=r"(r[3]) : "r"(addr));
}
__device__ __forceinline__ void ldsm4t(uint32_t* r, uint32_t addr) {
    asm volatile("ldmatrix.sync.aligned.m8n8.x4.trans.shared.b16 {%0,%1,%2,%3}, [%4];"
                 : "=r"(r[0]), "=r"(r[1]), "=r"(r[2]), "=r"(r[3]) : "r"(addr));
}
__device__ __forceinline__ float fexp2(float x) {
    float r;
    asm("ex2.approx.f32 %0, %1;" : "=f"(r) : "f"(x));
    return r;
}
__device__ __forceinline__ uint32_t pack_hi(float x, float y) {
    __nv_bfloat162 h = __float22bfloat162_rn(make_float2(x, y));
    return *(uint32_t*)&h;
}
__device__ __forceinline__ uint32_t pack_lo(float x, float y) {
    __nv_bfloat16 hx = __float2bfloat16(x), hy = __float2bfloat16(y);
    __nv_bfloat162 l = __float22bfloat162_rn(
        make_float2(x - __bfloat162float(hx), y - __bfloat162float(hy)));
    return *(uint32_t*)&l;
}
__device__ __forceinline__ void cpa16(uint32_t s, const void* g) {
    asm volatile("cp.async.cg.shared.global [%0], [%1], 16;" :: "r"(s), "l"(g));
}
#define CP_COMMIT()  asm volatile("cp.async.commit_group;" ::: "memory")
#define CP_WAITG(n)  asm volatile("cp.async.wait_group %0;" :: "n"(n) : "memory")

// ---------------------------------------------------------------------------
// converts
// ---------------------------------------------------------------------------
struct ConvJob { const float* src; __nv_bfloat16 *h, *l; int n4; };
struct ConvBatch { ConvJob j[7]; };

__global__ __launch_bounds__(256, 4)
void convert_all(ConvBatch cb)
{
    ConvJob jb = cb.j[blockIdx.z];
    int i = blockIdx.x * 256 + threadIdx.x;
    if (i >= jb.n4) return;
    float4 v = ((const float4*)jb.src)[i];
    uint2 H, L;
    H.x = pack_hi(v.x, v.y); H.y = pack_hi(v.z, v.w);
    L.x = pack_lo(v.x, v.y); L.y = pack_lo(v.z, v.w);
    ((uint2*)jb.h)[i] = H;
    ((uint2*)jb.l)[i] = L;
}

// ---------------------------------------------------------------------------
// GEMM (unchanged from R7)
// ---------------------------------------------------------------------------
#define GROWB 80
#define GPLANE (128 * GROWB)
#define GSTAGE (4 * GPLANE)
#define GSM3 (3 * GSTAGE)

struct GemmJob {
    const __nv_bfloat16 *Ah, *Al, *Bh, *Bl;
    const float* bias;
    float* C;
    __nv_bfloat16 *Ch, *Cl;
};
struct GemmBatch { GemmJob j[3]; };

__global__ __launch_bounds__(256, 1)
void gemm_bf16(GemmBatch gb, int M, int N, int K)
{
    extern __shared__ __align__(128) char sm[];
    const uint32_t smb = smem_u32(sm);
    const GemmJob jb = gb.j[blockIdx.z];
    const int tid = threadIdx.x;
    const int wid = tid >> 5, lane = tid & 31;
    const int m0 = blockIdx.y * 128, n0 = blockIdx.x * 128;
    const int warp_m = (wid & 1) * 64;
    const int warp_n = (wid >> 1) * 32;
    const int nch = K / 32;

    const __nv_bfloat16* bases[4] = { jb.Ah, jb.Al, jb.Bh, jb.Bl };

    auto issue = [&](int ch) {
        const uint32_t sb = smb + (uint32_t)((ch % 3) * GSTAGE);
        const size_t gk = (size_t)ch * 32;
#pragma unroll
        for (int p = 0; p < 4; p++) {
            const int rbase = (p < 2) ? m0 : n0;
#pragma unroll
            for (int hh = 0; hh < 2; hh++) {
                int idx = hh * 256 + tid;
                int r = idx >> 2, c = idx & 3;
                cpa16(sb + (uint32_t)(p * GPLANE + r * 80 + c * 16),
                      bases[p] + (size_t)(rbase + r) * K + gk + c * 8);
            }
        }
    };

    float acc[4][4][4];
#pragma unroll
    for (int i = 0; i < 4; i++)
#pragma unroll
        for (int j = 0; j < 4; j++)
#pragma unroll
            for (int c = 0; c < 4; c++) acc[i][j][c] = 0.0f;

    issue(0); CP_COMMIT();
    issue(1); CP_COMMIT();

    const int arow = lane & 15;
    const int acol = (lane >> 4) * 8;
    const int bg = lane >> 3, bw = lane & 7;

    for (int ch = 0; ch < nch; ch++) {
        CP_WAITG(1);
        __syncthreads();
        if (ch + 2 < nch) issue(ch + 2);
        CP_COMMIT();

        const uint32_t sb = smb + (uint32_t)((ch % 3) * GSTAGE);
#pragma unroll
        for (int ks = 0; ks < 2; ks++) {
            const int k16 = ks * 16;
            uint32_t ah[4][4], al[4][4];
#pragma unroll
            for (int mt = 0; mt < 4; mt++) {
                uint32_t off = (uint32_t)((warp_m + mt * 16 + arow) * 80 + (k16 + acol) * 2);
                ldsm4(ah[mt], sb + 0 * GPLANE + off);
                ldsm4(al[mt], sb + 1 * GPLANE + off);
            }
            uint32_t bh[4][2], bl[4][2];
#pragma unroll
            for (int nb = 0; nb < 2; nb++) {
                uint32_t off = (uint32_t)((warp_n + nb * 16 + (bg & 1) * 8 + bw) * 80
                                          + (k16 + (bg >> 1) * 8) * 2);
                uint32_t t[4];
                ldsm4(t, sb + 2 * GPLANE + off);
                bh[nb * 2 + 0][0] = t[0]; bh[nb * 2 + 0][1] = t[2];
                bh[nb * 2 + 1][0] = t[1]; bh[nb * 2 + 1][1] = t[3];
                ldsm4(t, sb + 3 * GPLANE + off);
                bl[nb * 2 + 0][0] = t[0]; bl[nb * 2 + 0][1] = t[2];
                bl[nb * 2 + 1][0] = t[1]; bl[nb * 2 + 1][1] = t[3];
            }
#pragma unroll
            for (int mt = 0; mt < 4; mt++)
#pragma unroll
                for (int nt = 0; nt < 4; nt++) {
                    mma16816(acc[mt][nt], ah[mt], bh[nt]);
                    mma16816(acc[mt][nt], ah[mt], bl[nt]);
                    mma16816(acc[mt][nt], al[mt], bh[nt]);
                }
        }
        __syncthreads();
    }

    const int lr = lane >> 2, lc = (lane & 3) * 2;
    const bool wplanes = (jb.Ch != nullptr);
#pragma unroll
    for (int nt = 0; nt < 4; nt++) {
        int col = n0 + warp_n + nt * 8 + lc;
        float2 bv = *(const float2*)&jb.bias[col];
#pragma unroll
        for (int mt = 0; mt < 4; mt++) {
            int r0 = m0 + warp_m + mt * 16 + lr;
            float2 o0 = make_float2(acc[mt][nt][0] + bv.x, acc[mt][nt][1] + bv.y);
            float2 o1 = make_float2(acc[mt][nt][2] + bv.x, acc[mt][nt][3] + bv.y);
            *(float2*)(jb.C + (size_t)r0 * N + col) = o0;
            *(float2*)(jb.C + (size_t)(r0 + 8) * N + col) = o1;
            if (wplanes) {
                size_t i0 = (size_t)r0 * N + col;
                size_t i1 = (size_t)(r0 + 8) * N + col;
                *(uint32_t*)&jb.Ch[i0] = pack_hi(o0.x, o0.y);
                *(uint32_t*)&jb.Cl[i0] = pack_lo(o0.x, o0.y);
                *(uint32_t*)&jb.Ch[i1] = pack_hi(o1.x, o1.y);
                *(uint32_t*)&jb.Cl[i1] = pack_lo(o1.x, o1.y);
            }
        }
    }
}

// ---------------------------------------------------------------------------
// Pipelined fused attention.
// smem: Q hi/lo | K stage0 hi/lo | K stage1 hi/lo | V hi/lo | P hi/lo
// ---------------------------------------------------------------------------
#define QROWB 144
#define PROWB 272
#define AQH   0
#define AQL   18432
#define AKH0  36864
#define AKH1  73728
#define AVH   110592
#define AVL   129024
#define APH   147456
#define APL   182272
#define SM2_TOT 217088

__device__ __forceinline__ void s_tile_mma(float acc[4][4][4], uint32_t smb,
                                           uint32_t kbase, int warp_m, int warp_n,
                                           int lane)
{
    const int arow = lane & 15;
    const int acol = (lane >> 4) * 8;
    const int bg = lane >> 3, bw = lane & 7;
#pragma unroll
    for (int ks = 0; ks < 4; ks++) {
        const int k16 = ks * 16;
        uint32_t ah[4][4], al[4][4];
#pragma unroll
        for (int mt = 0; mt < 4; mt++) {
            uint32_t off = (uint32_t)((warp_m + mt * 16 + arow) * QROWB + (k16 + acol) * 2);
            ldsm4(ah[mt], smb + AQH + off);
            ldsm4(al[mt], smb + AQL + off);
        }
        uint32_t bh[4][2], bl[4][2];
#pragma unroll
        for (int nb = 0; nb < 2; nb++) {
            uint32_t off = (uint32_t)((warp_n + nb * 16 + (bg & 1) * 8 + bw) * QROWB
                                      + (k16 + (bg >> 1) * 8) * 2);
            uint32_t t[4];
            ldsm4(t, smb + kbase + off);
            bh[nb * 2 + 0][0] = t[0]; bh[nb * 2 + 0][1] = t[2];
            bh[nb * 2 + 1][0] = t[1]; bh[nb * 2 + 1][1] = t[3];
            ldsm4(t, smb + kbase + 18432 + off);
            bl[nb * 2 + 0][0] = t[0]; bl[nb * 2 + 0][1] = t[2];
            bl[nb * 2 + 1][0] = t[1]; bl[nb * 2 + 1][1] = t[3];
        }
#pragma unroll
        for (int mt = 0; mt < 4; mt++)
#pragma unroll
            for (int nt = 0; nt < 4; nt++) {
                mma16816(acc[mt][nt], ah[mt], bh[nt]);
                mma16816(acc[mt][nt], ah[mt], bl[nt]);
                mma16816(acc[mt][nt], al[mt], bh[nt]);
            }
    }
}

__global__ __launch_bounds__(256, 1)
void attn_fused_mma(float* __restrict__ attn)
{
    extern __shared__ __align__(128) char sm[];
    const uint32_t smb = smem_u32(sm);
    const int tid = threadIdx.x;
    const int wid = tid >> 5, lane = tid & 31;
    const int b = blockIdx.z, h = blockIdx.y;
    const int it = (int)gridDim.x - 1 - (int)blockIdx.x;
    const int r0 = it * 128;
    const int warp_m = (wid & 1) * 64;
    const int warp_n = (wid >> 1) * 32;
    const int wnp = (wid >> 1) * 16;
    const int lr = lane >> 2, lc2 = (lane & 3) * 2;
    const float CE = 0.125f * 1.4426950408889634f;

    const size_t qoff = ((size_t)b * Sc + r0) * Dc + h * DPc;
    const size_t koff = (size_t)b * Sc * Dc + h * DPc;
    const size_t bh_ = (size_t)(b * Hc + h);
    float* attnp = attn + bh_ * Sc * Sc;

    // cp.async a 128x64-bf16 plane (row stride Dc) into smem (stride QROWB)
    auto issue_plane = [&](uint32_t dst, const __nv_bfloat16* src) {
#pragma unroll
        for (int e = 0; e < 4; e++) {
            int idx = tid + e * 256;
            int r = idx >> 3, c = idx & 7;
            cpa16(dst + (uint32_t)(r * QROWB + c * 16), src + (size_t)r * Dc + c * 8);
        }
    };
    auto issue_K = [&](int jt) {
        uint32_t dst = smb + ((jt & 1) ? AKH1 : AKH0);
        const size_t off = koff + (size_t)jt * 128 * Dc;
        issue_plane(dst, g_kh + off);
        issue_plane(dst + 18432, g_kl + off);
    };
    auto issue_V = [&](int jt) {
        const size_t off = koff + (size_t)jt * 128 * Dc;
        issue_plane(smb + AVH, g_vh + off);
        issue_plane(smb + AVL, g_vl + off);
    };

    // prologue: group A0 = {Q, K0}, B0 = {V0}, A1 = {K1}
    issue_plane(smb + AQH, g_qh + qoff);
    issue_plane(smb + AQL, g_ql + qoff);
    issue_K(0);
    CP_COMMIT();
    issue_V(0);
    CP_COMMIT();
    if (it >= 1) issue_K(1);
    CP_COMMIT();

    float ctx[4][2][4];
#pragma unroll
    for (int i = 0; i < 4; i++)
#pragma unroll
        for (int j = 0; j < 2; j++)
#pragma unroll
            for (int c = 0; c < 4; c++) ctx[i][j][c] = 0.0f;

    float lsum[4][2];
#pragma unroll
    for (int i = 0; i < 4; i++) { lsum[i][0] = 0.0f; lsum[i][1] = 0.0f; }

    const int arow = lane & 15;
    const int acol = (lane >> 4) * 8;

    for (int jt = 0; jt <= it; jt++) {
        const int j0 = jt * 128;

        CP_WAITG(2);            // Q + K(jt) arrived
        __syncthreads();

        float acc[4][4][4];
#pragma unroll
        for (int i = 0; i < 4; i++)
#pragma unroll
            for (int j = 0; j < 4; j++)
#pragma unroll
                for (int c = 0; c < 4; c++) acc[i][j][c] = 0.0f;

        s_tile_mma(acc, smb, (jt & 1) ? AKH1 : AKH0, warp_m, warp_n, lane);

        // epilogue: exp -> attn gmem (unnormalized) + P hi/lo smem
        const bool diag = (jt == it);
#pragma unroll
        for (int mt = 0; mt < 4; mt++)
#pragma unroll
            for (int hf = 0; hf < 2; hf++) {
                const int rowg = warp_m + mt * 16 + lr + hf * 8;
                const int growg = r0 + rowg;
                float rl = 0.0f;
#pragma unroll
                for (int nt = 0; nt < 4; nt++) {
                    int col = warp_n + nt * 8 + lc2;
                    float p0 = fexp2(acc[mt][nt][hf * 2 + 0] * CE);
                    float p1 = fexp2(acc[mt][nt][hf * 2 + 1] * CE);
                    if (diag && (j0 + col + 0) > growg) p0 = 0.0f;
                    if (diag && (j0 + col + 1) > growg) p1 = 0.0f;
                    *(float2*)&attnp[(size_t)growg * Sc + j0 + col] = make_float2(p0, p1);
                    *(uint32_t*)(sm + APH + rowg * PROWB + col * 2) = pack_hi(p0, p1);
                    *(uint32_t*)(sm + APL + rowg * PROWB + col * 2) = pack_lo(p0, p1);
                    rl += p0 + p1;
                }
                lsum[mt][hf] += rl;
            }

        CP_WAITG(1);            // V(jt) arrived (K(jt+1) may still be in flight)
        __syncthreads();        // P + V visible to all warps

        // PV: ctx += P[128x128] @ V[128x64], V read via ldmatrix.trans
#pragma unroll
        for (int ks = 0; ks < 8; ks++) {
            const int k16 = ks * 16;
            uint32_t ph[4][4], pl[4][4];
#pragma unroll
            for (int mt = 0; mt < 4; mt++) {
                uint32_t off = (uint32_t)((warp_m + mt * 16 + arow) * PROWB + (k16 + acol) * 2);
                ldsm4(ph[mt], smb + APH + off);
                ldsm4(pl[mt], smb + APL + off);
            }
            uint32_t vh[2][2], vl[2][2];
            {
                uint32_t voff = (uint32_t)((k16 + (lane & 15)) * QROWB
                                           + (wnp + (lane >> 4) * 8) * 2);
                uint32_t t[4];
                ldsm4t(t, smb + AVH + voff);
                vh[0][0] = t[0]; vh[0][1] = t[1];
                vh[1][0] = t[2]; vh[1][1] = t[3];
                ldsm4t(t, smb + AVL + voff);
                vl[0][0] = t[0]; vl[0][1] = t[1];
                vl[1][0] = t[2]; vl[1][1] = t[3];
            }
#pragma unroll
            for (int mt = 0; mt < 4; mt++)
#pragma unroll
                for (int ntp = 0; ntp < 2; ntp++) {
                    mma16816(ctx[mt][ntp], ph[mt], vh[ntp]);
                    mma16816(ctx[mt][ntp], ph[mt], vl[ntp]);
                    mma16816(ctx[mt][ntp], pl[mt], vh[ntp]);
                }
        }

        __syncthreads();        // V/P consumed by all warps

        // prefetch next V and K
        if (jt + 1 <= it) issue_V(jt + 1);
        CP_COMMIT();
        if (jt + 2 <= it) issue_K(jt + 2);
        CP_COMMIT();
    }

    // reduce row sums l across 4 lanes + 4 warp_n groups
#pragma unroll
    for (int off = 1; off <= 2; off <<= 1)
#pragma unroll
        for (int mt = 0; mt < 4; mt++)
#pragma unroll
            for (int hf = 0; hf < 2; hf++)
                lsum[mt][hf] += __shfl_xor_sync(0xffffffffu, lsum[mt][hf], off);

    __syncthreads();
    float* smR = (float*)(sm + AVH);
    float* smF = smR + 512;
    if ((lane & 3) == 0) {
        const int g = wid >> 1;
#pragma unroll
        for (int mt = 0; mt < 4; mt++)
#pragma unroll
            for (int hf = 0; hf < 2; hf++)
                smR[g * 128 + warp_m + mt * 16 + lr + hf * 8] = lsum[mt][hf];
    }
    __syncthreads();
    if (tid < 128) {
        float l = smR[tid] + smR[128 + tid] + smR[256 + tid] + smR[384 + tid];
        smF[tid] = 1.0f / l;
        g_lbuf[bh_ * Sc + r0 + tid] = l;
    }
    __syncthreads();

    // normalized ctx -> bf16 hi/lo planes
#pragma unroll
    for (int mt = 0; mt < 4; mt++)
#pragma unroll
        for (int ntp = 0; ntp < 2; ntp++) {
            int dcol = h * DPc + wnp + ntp * 8 + lc2;
#pragma unroll
            for (int hf = 0; hf < 2; hf++) {
                int rowl = warp_m + mt * 16 + lr + hf * 8;
                float inv = smF[rowl];
                int row = r0 + rowl;
                float x0 = ctx[mt][ntp][hf * 2 + 0] * inv;
                float x1 = ctx[mt][ntp][hf * 2 + 1] * inv;
                size_t idx = ((size_t)b * Sc + row) * Dc + dcol;
                *(uint32_t*)&g_ch2[idx] = pack_hi(x0, x1);
                *(uint32_t*)&g_cl2[idx] = pack_lo(x0, x1);
            }
        }
}

// ---------------------------------------------------------------------------
__global__ __launch_bounds__(512, 2)
void fill_upper(float* __restrict__ attn)
{
    const int b = blockIdx.z, h = blockIdx.y, it = blockIdx.x;
    const int ncol4 = 512 - (it + 1) * 32;
    if (ncol4 <= 0) return;
    const int c0 = (it + 1) * 32;
    float* ap = attn + ((size_t)(b * Hc + h)) * Sc * Sc + (size_t)it * 128 * Sc;
    const float4 z = make_float4(0.f, 0.f, 0.f, 0.f);
    const int tid = threadIdx.x;
    const int total = 128 * ncol4;
    for (int i = tid; i < total; i += 512) {
        int r = i / ncol4, c = i - r * ncol4;
        ((float4*)&ap[(size_t)r * Sc])[c0 + c] = z;
    }
}

__global__ __launch_bounds__(512, 2)
void norm_lower(float* __restrict__ attn)
{
    const int b = blockIdx.z, h = blockIdx.y, it = blockIdx.x;
    const int r0 = it * 128;
    const int tid = threadIdx.x;
    const size_t bh_ = (size_t)(b * Hc + h);
    float* ap = attn + bh_ * Sc * Sc;

    __shared__ float inv[128];
    if (tid < 128) inv[tid] = 1.0f / g_lbuf[bh_ * Sc + r0 + tid];
    __syncthreads();

    const int ncol4 = (it + 1) * 32;
    for (int r = tid >> 7; r < 128; r += 4) {
        const float s = inv[r];
        float4* rowp = (float4*)&ap[(size_t)(r0 + r) * Sc];
#pragma unroll 4
        for (int c4 = (tid & 127); c4 < ncol4; c4 += 128) {
            float4 v = rowp[c4];
            v.x *= s; v.y *= s; v.z *= s; v.w *= s;
            rowp[c4] = v;
        }
    }
}

// ---------------------------------------------------------------------------
extern "C" void kernel_launch(void* const* d_in, const int* in_sizes, int n_in,
                              void* d_out, int out_size)
{
    (void)in_sizes; (void)n_in; (void)out_size;
    const float* Q   = (const float*)d_in[0];
    const float* Kin = (const float*)d_in[1];
    const float* Vin = (const float*)d_in[2];
    const float* Wq = (const float*)d_in[4];
    const float* bq = (const float*)d_in[5];
    const float* Wk = (const float*)d_in[6];
    const float* bk = (const float*)d_in[7];
    const float* Wv = (const float*)d_in[8];
    const float* bv = (const float*)d_in[9];
    const float* Wo = (const float*)d_in[10];
    const float* bo = (const float*)d_in[11];

    float* out  = (float*)d_out;
    float* attn = out + SZ_QKV;
    float* qo   = attn + SZ_ATTN;
    float* ko   = qo + SZ_QKV;
    float* vo   = ko + SZ_QKV;

    void *iah, *ial, *wh, *wl, *qh, *ql, *kh, *kl, *vh, *vl, *ch2, *cl2;
    cudaGetSymbolAddress(&iah, g_iah);  cudaGetSymbolAddress(&ial, g_ial);
    cudaGetSymbolAddress(&wh, g_wh);    cudaGetSymbolAddress(&wl, g_wl);
    cudaGetSymbolAddress(&qh, g_qh);    cudaGetSymbolAddress(&ql, g_ql);
    cudaGetSymbolAddress(&kh, g_kh);    cudaGetSymbolAddress(&kl, g_kl);
    cudaGetSymbolAddress(&vh, g_vh);    cudaGetSymbolAddress(&vl, g_vl);
    cudaGetSymbolAddress(&ch2, g_ch2);  cudaGetSymbolAddress(&cl2, g_cl2);
    __nv_bfloat16 *IAH = (__nv_bfloat16*)iah, *IAL = (__nv_bfloat16*)ial;
    __nv_bfloat16 *WH  = (__nv_bfloat16*)wh,  *WL  = (__nv_bfloat16*)wl;

    cudaFuncSetAttribute(gemm_bf16,
                         cudaFuncAttributeMaxDynamicSharedMemorySize, GSM3);
    cudaFuncSetAttribute(attn_fused_mma,
                         cudaFuncAttributeMaxDynamicSharedMemorySize, SM2_TOT);

    const int M = Bc * Sc;

    cudaStream_t s1;
    cudaStreamCreateWithFlags(&s1, cudaStreamNonBlocking);
    cudaEvent_t e0, e1, e2;
    cudaEventCreateWithFlags(&e0, cudaEventDisableTiming);
    cudaEventCreateWithFlags(&e1, cudaEventDisableTiming);
    cudaEventCreateWithFlags(&e2, cudaEventDisableTiming);

    // 1) converts
    ConvBatch cb;
    const float* srcs[7] = { Q, Kin, Vin, Wq, Wk, Wv, Wo };
    for (int z = 0; z < 7; z++) {
        cb.j[z].src = srcs[z];
        if (z < 3) {
            cb.j[z].h = IAH + (size_t)z * MD;
            cb.j[z].l = IAL + (size_t)z * MD;
            cb.j[z].n4 = (int)(MD / 4);
        } else {
            cb.j[z].h = WH + (size_t)(z - 3) * DD;
            cb.j[z].l = WL + (size_t)(z - 3) * DD;
            cb.j[z].n4 = (int)(DD / 4);
        }
    }
    dim3 cgrid((unsigned)((MD / 4 + 255) / 256), 1, 7);
    convert_all<<<cgrid, 256>>>(cb);

    // 2) QKV projections
    GemmBatch qb;
    const float* biases[3] = { bq, bk, bv };
    float* outs[3] = { qo, ko, vo };
    __nv_bfloat16* chp[3] = { (__nv_bfloat16*)qh, (__nv_bfloat16*)kh, (__nv_bfloat16*)vh };
    __nv_bfloat16* clp[3] = { (__nv_bfloat16*)ql, (__nv_bfloat16*)kl, (__nv_bfloat16*)vl };
    for (int z = 0; z < 3; z++) {
        qb.j[z].Ah = IAH + (size_t)z * MD; qb.j[z].Al = IAL + (size_t)z * MD;
        qb.j[z].Bh = WH + (size_t)z * DD;  qb.j[z].Bl = WL + (size_t)z * DD;
        qb.j[z].bias = biases[z]; qb.j[z].C = outs[z];
        qb.j[z].Ch = chp[z]; qb.j[z].Cl = clp[z];
    }
    dim3 qgrid(Dc / 128, M / 128, 3);
    gemm_bf16<<<qgrid, 256, GSM3>>>(qb, M, Dc, Dc);

    // fork: fill_upper overlaps attn
    cudaEventRecord(e0, 0);
    cudaStreamWaitEvent(s1, e0, 0);
    dim3 agrid(Sc / 128, Hc, Bc);
    fill_upper<<<agrid, 512, 0, s1>>>(attn);

    // 3) attention
    attn_fused_mma<<<agrid, 256, SM2_TOT>>>(attn);
    cudaEventRecord(e1, 0);

    cudaStreamWaitEvent(s1, e1, 0);
    norm_lower<<<agrid, 512, 0, s1>>>(attn);
    cudaEventRecord(e2, s1);

    // 4) O projection (overlaps norm_lower)
    GemmBatch ob;
    ob.j[0].Ah = (__nv_bfloat16*)ch2; ob.j[0].Al = (__nv_bfloat16*)cl2;
    ob.j[0].Bh = WH + 3 * DD;         ob.j[0].Bl = WL + 3 * DD;
    ob.j[0].bias = bo; ob.j[0].C = out;
    ob.j[0].Ch = nullptr; ob.j[0].Cl = nullptr;
    ob.j[1] = ob.j[0]; ob.j[2] = ob.j[0];
    dim3 ogrid(Dc / 128, M / 128, 1);
    gemm_bf16<<<ogrid, 256, GSM3>>>(ob, M, Dc, Dc);

    cudaStreamWaitEvent(0, e2, 0);
}

// round 10
// speedup vs baseline: 1.2434x; 1.0065x over previous
#include <cuda_runtime.h>
#include <cuda_bf16.h>
#include <math.h>
#include <stdint.h>

#define Bc 2
#define Sc 2048
#define Dc 1024
#define Hc 16
#define DPc 64

static const size_t SZ_QKV  = (size_t)Bc * Sc * Dc;        // 4194304
static const size_t SZ_ATTN = (size_t)Bc * Hc * Sc * Sc;   // 134217728
#define MD  ((size_t)4194304)
#define DD  ((size_t)1048576)

__device__ __nv_bfloat16 g_iah[3 * MD], g_ial[3 * MD];
__device__ __nv_bfloat16 g_wh[4 * DD],  g_wl[4 * DD];
__device__ __nv_bfloat16 g_qh[MD], g_ql[MD];
__device__ __nv_bfloat16 g_kh[MD], g_kl[MD];
__device__ __nv_bfloat16 g_vh[MD], g_vl[MD];
__device__ __nv_bfloat16 g_ch2[MD], g_cl2[MD];
__device__ float g_lbuf[(size_t)Bc * Hc * Sc];

// ---------------------------------------------------------------------------
__device__ __forceinline__ uint32_t smem_u32(const void* p) {
    uint32_t a;
    asm("{ .reg .u64 t; cvta.to.shared.u64 t, %1; cvt.u32.u64 %0, t; }"
        : "=r"(a) : "l"(p));
    return a;
}
__device__ __forceinline__ void mma16816(float* d, const uint32_t* a, const uint32_t* b) {
    asm volatile(
        "mma.sync.aligned.m16n8k16.row.col.f32.bf16.bf16.f32 "
        "{%0,%1,%2,%3}, {%4,%5,%6,%7}, {%8,%9}, {%0,%1,%2,%3};"
        : "+f"(d[0]), "+f"(d[1]), "+f"(d[2]), "+f"(d[3])
        : "r"(a[0]), "r"(a[1]), "r"(a[2]), "r"(a[3]), "r"(b[0]), "r"(b[1]));
}
__device__ __forceinline__ void ldsm4(uint32_t* r, uint32_t addr) {
    asm volatile("ldmatrix.sync.aligned.m8n8.x4.shared.b16 {%0,%1,%2,%3}, [%4];"
                 : "=r"(r[0]), "=r"(r[1]), "=r"(r[2]), "=r"(r[3]) : "r"(addr));
}
__device__ __forceinline__ void ldsm4t(uint32_t* r, uint32_t addr) {
    asm volatile("ldmatrix.sync.aligned.m8n8.x4.trans.shared.b16 {%0,%1,%2,%3}, [%4];"
                 : "=r"(r[0]), "=r"(r[1]), "=r"(r[2]), "=r"(r[3]) : "r"(addr));
}
__device__ __forceinline__ float fexp2(float x) {
    float r;
    asm("ex2.approx.f32 %0, %1;" : "=f"(r) : "f"(x));
    return r;
}
__device__ __forceinline__ uint32_t pack_hi(float x, float y) {
    __nv_bfloat162 h = __float22bfloat162_rn(make_float2(x, y));
    return *(uint32_t*)&h;
}
__device__ __forceinline__ uint32_t pack_lo(float x, float y) {
    __nv_bfloat16 hx = __float2bfloat16(x), hy = __float2bfloat16(y);
    __nv_bfloat162 l = __float22bfloat162_rn(
        make_float2(x - __bfloat162float(hx), y - __bfloat162float(hy)));
    return *(uint32_t*)&l;
}
__device__ __forceinline__ void cpa16(uint32_t s, const void* g) {
    asm volatile("cp.async.cg.shared.global [%0], [%1], 16;" :: "r"(s), "l"(g));
}
#define CP_COMMIT()  asm volatile("cp.async.commit_group;" ::: "memory")
#define CP_WAITG(n)  asm volatile("cp.async.wait_group %0;" :: "n"(n) : "memory")

// ---------------------------------------------------------------------------
// converts
// ---------------------------------------------------------------------------
struct ConvJob { const float* src; __nv_bfloat16 *h, *l; int n4; };
struct ConvBatch { ConvJob j[7]; };

__global__ __launch_bounds__(256, 4)
void convert_all(ConvBatch cb)
{
    ConvJob jb = cb.j[blockIdx.z];
    int i = blockIdx.x * 256 + threadIdx.x;
    if (i >= jb.n4) return;
    float4 v = ((const float4*)jb.src)[i];
    uint2 H, L;
    H.x = pack_hi(v.x, v.y); H.y = pack_hi(v.z, v.w);
    L.x = pack_lo(v.x, v.y); L.y = pack_lo(v.z, v.w);
    ((uint2*)jb.h)[i] = H;
    ((uint2*)jb.l)[i] = L;
}

// ---------------------------------------------------------------------------
// GEMM (unchanged from R8)
// ---------------------------------------------------------------------------
#define GROWB 80
#define GPLANE (128 * GROWB)
#define GSTAGE (4 * GPLANE)
#define GSM3 (3 * GSTAGE)

struct GemmJob {
    const __nv_bfloat16 *Ah, *Al, *Bh, *Bl;
    const float* bias;
    float* C;
    __nv_bfloat16 *Ch, *Cl;
};
struct GemmBatch { GemmJob j[3]; };

__global__ __launch_bounds__(256, 1)
void gemm_bf16(GemmBatch gb, int M, int N, int K)
{
    extern __shared__ __align__(128) char sm[];
    const uint32_t smb = smem_u32(sm);
    const GemmJob jb = gb.j[blockIdx.z];
    const int tid = threadIdx.x;
    const int wid = tid >> 5, lane = tid & 31;
    const int m0 = blockIdx.y * 128, n0 = blockIdx.x * 128;
    const int warp_m = (wid & 1) * 64;
    const int warp_n = (wid >> 1) * 32;
    const int nch = K / 32;

    const __nv_bfloat16* bases[4] = { jb.Ah, jb.Al, jb.Bh, jb.Bl };

    auto issue = [&](int ch) {
        const uint32_t sb = smb + (uint32_t)((ch % 3) * GSTAGE);
        const size_t gk = (size_t)ch * 32;
#pragma unroll
        for (int p = 0; p < 4; p++) {
            const int rbase = (p < 2) ? m0 : n0;
#pragma unroll
            for (int hh = 0; hh < 2; hh++) {
                int idx = hh * 256 + tid;
                int r = idx >> 2, c = idx & 3;
                cpa16(sb + (uint32_t)(p * GPLANE + r * 80 + c * 16),
                      bases[p] + (size_t)(rbase + r) * K + gk + c * 8);
            }
        }
    };

    float acc[4][4][4];
#pragma unroll
    for (int i = 0; i < 4; i++)
#pragma unroll
        for (int j = 0; j < 4; j++)
#pragma unroll
            for (int c = 0; c < 4; c++) acc[i][j][c] = 0.0f;

    issue(0); CP_COMMIT();
    issue(1); CP_COMMIT();

    const int arow = lane & 15;
    const int acol = (lane >> 4) * 8;
    const int bg = lane >> 3, bw = lane & 7;

    for (int ch = 0; ch < nch; ch++) {
        CP_WAITG(1);
        __syncthreads();
        if (ch + 2 < nch) issue(ch + 2);
        CP_COMMIT();

        const uint32_t sb = smb + (uint32_t)((ch % 3) * GSTAGE);
#pragma unroll
        for (int ks = 0; ks < 2; ks++) {
            const int k16 = ks * 16;
            uint32_t ah[4][4], al[4][4];
#pragma unroll
            for (int mt = 0; mt < 4; mt++) {
                uint32_t off = (uint32_t)((warp_m + mt * 16 + arow) * 80 + (k16 + acol) * 2);
                ldsm4(ah[mt], sb + 0 * GPLANE + off);
                ldsm4(al[mt], sb + 1 * GPLANE + off);
            }
            uint32_t bh[4][2], bl[4][2];
#pragma unroll
            for (int nb = 0; nb < 2; nb++) {
                uint32_t off = (uint32_t)((warp_n + nb * 16 + (bg & 1) * 8 + bw) * 80
                                          + (k16 + (bg >> 1) * 8) * 2);
                uint32_t t[4];
                ldsm4(t, sb + 2 * GPLANE + off);
                bh[nb * 2 + 0][0] = t[0]; bh[nb * 2 + 0][1] = t[2];
                bh[nb * 2 + 1][0] = t[1]; bh[nb * 2 + 1][1] = t[3];
                ldsm4(t, sb + 3 * GPLANE + off);
                bl[nb * 2 + 0][0] = t[0]; bl[nb * 2 + 0][1] = t[2];
                bl[nb * 2 + 1][0] = t[1]; bl[nb * 2 + 1][1] = t[3];
            }
#pragma unroll
            for (int mt = 0; mt < 4; mt++)
#pragma unroll
                for (int nt = 0; nt < 4; nt++) {
                    mma16816(acc[mt][nt], ah[mt], bh[nt]);
                    mma16816(acc[mt][nt], ah[mt], bl[nt]);
                    mma16816(acc[mt][nt], al[mt], bh[nt]);
                }
        }
        __syncthreads();
    }

    const int lr = lane >> 2, lc = (lane & 3) * 2;
    const bool wplanes = (jb.Ch != nullptr);
#pragma unroll
    for (int nt = 0; nt < 4; nt++) {
        int col = n0 + warp_n + nt * 8 + lc;
        float2 bv = *(const float2*)&jb.bias[col];
#pragma unroll
        for (int mt = 0; mt < 4; mt++) {
            int r0 = m0 + warp_m + mt * 16 + lr;
            float2 o0 = make_float2(acc[mt][nt][0] + bv.x, acc[mt][nt][1] + bv.y);
            float2 o1 = make_float2(acc[mt][nt][2] + bv.x, acc[mt][nt][3] + bv.y);
            *(float2*)(jb.C + (size_t)r0 * N + col) = o0;
            *(float2*)(jb.C + (size_t)(r0 + 8) * N + col) = o1;
            if (wplanes) {
                size_t i0 = (size_t)r0 * N + col;
                size_t i1 = (size_t)(r0 + 8) * N + col;
                *(uint32_t*)&jb.Ch[i0] = pack_hi(o0.x, o0.y);
                *(uint32_t*)&jb.Cl[i0] = pack_lo(o0.x, o0.y);
                *(uint32_t*)&jb.Ch[i1] = pack_hi(o1.x, o1.y);
                *(uint32_t*)&jb.Cl[i1] = pack_lo(o1.x, o1.y);
            }
        }
    }
}

// ---------------------------------------------------------------------------
// Pipelined fused attention (R8 layout: P hi AND lo planes).
// smem: Q hi/lo | K stage0 hi/lo | K stage1 hi/lo | V hi/lo | P hi/lo
// ---------------------------------------------------------------------------
#define QROWB 144
#define PROWB 272
#define AQH   0
#define AQL   18432
#define AKH0  36864
#define AKH1  73728
#define AVH   110592
#define AVL   129024
#define APH   147456
#define APL   182272
#define SM2_TOT 217088

__device__ __forceinline__ void s_tile_mma(float acc[4][4][4], uint32_t smb,
                                           uint32_t kbase, int warp_m, int warp_n,
                                           int lane)
{
    const int arow = lane & 15;
    const int acol = (lane >> 4) * 8;
    const int bg = lane >> 3, bw = lane & 7;
#pragma unroll
    for (int ks = 0; ks < 4; ks++) {
        const int k16 = ks * 16;
        uint32_t ah[4][4], al[4][4];
#pragma unroll
        for (int mt = 0; mt < 4; mt++) {
            uint32_t off = (uint32_t)((warp_m + mt * 16 + arow) * QROWB + (k16 + acol) * 2);
            ldsm4(ah[mt], smb + AQH + off);
            ldsm4(al[mt], smb + AQL + off);
        }
        uint32_t bh[4][2], bl[4][2];
#pragma unroll
        for (int nb = 0; nb < 2; nb++) {
            uint32_t off = (uint32_t)((warp_n + nb * 16 + (bg & 1) * 8 + bw) * QROWB
                                      + (k16 + (bg >> 1) * 8) * 2);
            uint32_t t[4];
            ldsm4(t, smb + kbase + off);
            bh[nb * 2 + 0][0] = t[0]; bh[nb * 2 + 0][1] = t[2];
            bh[nb * 2 + 1][0] = t[1]; bh[nb * 2 + 1][1] = t[3];
            ldsm4(t, smb + kbase + 18432 + off);
            bl[nb * 2 + 0][0] = t[0]; bl[nb * 2 + 0][1] = t[2];
            bl[nb * 2 + 1][0] = t[1]; bl[nb * 2 + 1][1] = t[3];
        }
#pragma unroll
        for (int mt = 0; mt < 4; mt++)
#pragma unroll
            for (int nt = 0; nt < 4; nt++) {
                mma16816(acc[mt][nt], ah[mt], bh[nt]);
                mma16816(acc[mt][nt], ah[mt], bl[nt]);
                mma16816(acc[mt][nt], al[mt], bh[nt]);
            }
    }
}

__global__ __launch_bounds__(256, 1)
void attn_fused_mma(float* __restrict__ attn)
{
    extern __shared__ __align__(128) char sm[];
    const uint32_t smb = smem_u32(sm);
    const int tid = threadIdx.x;
    const int wid = tid >> 5, lane = tid & 31;
    const int b = blockIdx.z, h = blockIdx.y;
    const int it = (int)gridDim.x - 1 - (int)blockIdx.x;
    const int r0 = it * 128;
    const int warp_m = (wid & 1) * 64;
    const int warp_n = (wid >> 1) * 32;
    const int wnp = (wid >> 1) * 16;
    const int lr = lane >> 2, lc2 = (lane & 3) * 2;
    const float CE = 0.125f * 1.4426950408889634f;

    const size_t qoff = ((size_t)b * Sc + r0) * Dc + h * DPc;
    const size_t koff = (size_t)b * Sc * Dc + h * DPc;
    const size_t bh_ = (size_t)(b * Hc + h);
    float* attnp = attn + bh_ * Sc * Sc;

    auto issue_plane = [&](uint32_t dst, const __nv_bfloat16* src) {
#pragma unroll
        for (int e = 0; e < 4; e++) {
            int idx = tid + e * 256;
            int r = idx >> 3, c = idx & 7;
            cpa16(dst + (uint32_t)(r * QROWB + c * 16), src + (size_t)r * Dc + c * 8);
        }
    };
    auto issue_K = [&](int jt) {
        uint32_t dst = smb + ((jt & 1) ? AKH1 : AKH0);
        const size_t off = koff + (size_t)jt * 128 * Dc;
        issue_plane(dst, g_kh + off);
        issue_plane(dst + 18432, g_kl + off);
    };
    auto issue_V = [&](int jt) {
        const size_t off = koff + (size_t)jt * 128 * Dc;
        issue_plane(smb + AVH, g_vh + off);
        issue_plane(smb + AVL, g_vl + off);
    };

    issue_plane(smb + AQH, g_qh + qoff);
    issue_plane(smb + AQL, g_ql + qoff);
    issue_K(0);
    CP_COMMIT();
    issue_V(0);
    CP_COMMIT();
    if (it >= 1) issue_K(1);
    CP_COMMIT();

    float ctx[4][2][4];
#pragma unroll
    for (int i = 0; i < 4; i++)
#pragma unroll
        for (int j = 0; j < 2; j++)
#pragma unroll
            for (int c = 0; c < 4; c++) ctx[i][j][c] = 0.0f;

    float lsum[4][2];
#pragma unroll
    for (int i = 0; i < 4; i++) { lsum[i][0] = 0.0f; lsum[i][1] = 0.0f; }

    const int arow = lane & 15;
    const int acol = (lane >> 4) * 8;

    for (int jt = 0; jt <= it; jt++) {
        const int j0 = jt * 128;

        CP_WAITG(2);
        __syncthreads();

        float acc[4][4][4];
#pragma unroll
        for (int i = 0; i < 4; i++)
#pragma unroll
            for (int j = 0; j < 4; j++)
#pragma unroll
                for (int c = 0; c < 4; c++) acc[i][j][c] = 0.0f;

        s_tile_mma(acc, smb, (jt & 1) ? AKH1 : AKH0, warp_m, warp_n, lane);

        const bool diag = (jt == it);
#pragma unroll
        for (int mt = 0; mt < 4; mt++)
#pragma unroll
            for (int hf = 0; hf < 2; hf++) {
                const int rowg = warp_m + mt * 16 + lr + hf * 8;
                const int growg = r0 + rowg;
                float rl = 0.0f;
#pragma unroll
                for (int nt = 0; nt < 4; nt++) {
                    int col = warp_n + nt * 8 + lc2;
                    float p0 = fexp2(acc[mt][nt][hf * 2 + 0] * CE);
                    float p1 = fexp2(acc[mt][nt][hf * 2 + 1] * CE);
                    if (diag && (j0 + col + 0) > growg) p0 = 0.0f;
                    if (diag && (j0 + col + 1) > growg) p1 = 0.0f;
                    *(float2*)&attnp[(size_t)growg * Sc + j0 + col] = make_float2(p0, p1);
                    *(uint32_t*)(sm + APH + rowg * PROWB + col * 2) = pack_hi(p0, p1);
                    *(uint32_t*)(sm + APL + rowg * PROWB + col * 2) = pack_lo(p0, p1);
                    rl += p0 + p1;
                }
                lsum[mt][hf] += rl;
            }

        CP_WAITG(1);
        __syncthreads();

        // PV: ctx += P(hi+lo) @ V(hi+lo) [3 terms], V via ldmatrix.trans
#pragma unroll
        for (int ks = 0; ks < 8; ks++) {
            const int k16 = ks * 16;
            uint32_t ph[4][4], pl[4][4];
#pragma unroll
            for (int mt = 0; mt < 4; mt++) {
                uint32_t off = (uint32_t)((warp_m + mt * 16 + arow) * PROWB + (k16 + acol) * 2);
                ldsm4(ph[mt], smb + APH + off);
                ldsm4(pl[mt], smb + APL + off);
            }
            uint32_t vh[2][2], vl[2][2];
            {
                uint32_t voff = (uint32_t)((k16 + (lane & 15)) * QROWB
                                           + (wnp + (lane >> 4) * 8) * 2);
                uint32_t t[4];
                ldsm4t(t, smb + AVH + voff);
                vh[0][0] = t[0]; vh[0][1] = t[1];
                vh[1][0] = t[2]; vh[1][1] = t[3];
                ldsm4t(t, smb + AVL + voff);
                vl[0][0] = t[0]; vl[0][1] = t[1];
                vl[1][0] = t[2]; vl[1][1] = t[3];
            }
#pragma unroll
            for (int mt = 0; mt < 4; mt++)
#pragma unroll
                for (int ntp = 0; ntp < 2; ntp++) {
                    mma16816(ctx[mt][ntp], ph[mt], vh[ntp]);
                    mma16816(ctx[mt][ntp], ph[mt], vl[ntp]);
                    mma16816(ctx[mt][ntp], pl[mt], vh[ntp]);
                }
        }

        __syncthreads();

        if (jt + 1 <= it) issue_V(jt + 1);
        CP_COMMIT();
        if (jt + 2 <= it) issue_K(jt + 2);
        CP_COMMIT();
    }

#pragma unroll
    for (int off = 1; off <= 2; off <<= 1)
#pragma unroll
        for (int mt = 0; mt < 4; mt++)
#pragma unroll
            for (int hf = 0; hf < 2; hf++)
                lsum[mt][hf] += __shfl_xor_sync(0xffffffffu, lsum[mt][hf], off);

    __syncthreads();
    float* smR = (float*)(sm + AVH);
    float* smF = smR + 512;
    if ((lane & 3) == 0) {
        const int g = wid >> 1;
#pragma unroll
        for (int mt = 0; mt < 4; mt++)
#pragma unroll
            for (int hf = 0; hf < 2; hf++)
                smR[g * 128 + warp_m + mt * 16 + lr + hf * 8] = lsum[mt][hf];
    }
    __syncthreads();
    if (tid < 128) {
        float l = smR[tid] + smR[128 + tid] + smR[256 + tid] + smR[384 + tid];
        smF[tid] = 1.0f / l;
        g_lbuf[bh_ * Sc + r0 + tid] = l;
    }
    __syncthreads();

#pragma unroll
    for (int mt = 0; mt < 4; mt++)
#pragma unroll
        for (int ntp = 0; ntp < 2; ntp++) {
            int dcol = h * DPc + wnp + ntp * 8 + lc2;
#pragma unroll
            for (int hf = 0; hf < 2; hf++) {
                int rowl = warp_m + mt * 16 + lr + hf * 8;
                float inv = smF[rowl];
                int row = r0 + rowl;
                float x0 = ctx[mt][ntp][hf * 2 + 0] * inv;
                float x1 = ctx[mt][ntp][hf * 2 + 1] * inv;
                size_t idx = ((size_t)b * Sc + row) * Dc + dcol;
                *(uint32_t*)&g_ch2[idx] = pack_hi(x0, x1);
                *(uint32_t*)&g_cl2[idx] = pack_lo(x0, x1);
            }
        }
}

// ---------------------------------------------------------------------------
__global__ __launch_bounds__(512, 2)
void fill_upper(float* __restrict__ attn)
{
    const int b = blockIdx.z, h = blockIdx.y, it = blockIdx.x;
    const int ncol4 = 512 - (it + 1) * 32;
    if (ncol4 <= 0) return;
    const int c0 = (it + 1) * 32;
    float* ap = attn + ((size_t)(b * Hc + h)) * Sc * Sc + (size_t)it * 128 * Sc;
    const float4 z = make_float4(0.f, 0.f, 0.f, 0.f);
    const int tid = threadIdx.x;
    const int total = 128 * ncol4;
    for (int i = tid; i < total; i += 512) {
        int r = i / ncol4, c = i - r * ncol4;
        ((float4*)&ap[(size_t)r * Sc])[c0 + c] = z;
    }
}

__global__ __launch_bounds__(512, 2)
void norm_lower(float* __restrict__ attn)
{
    const int b = blockIdx.z, h = blockIdx.y, it = blockIdx.x;
    const int r0 = it * 128;
    const int tid = threadIdx.x;
    const size_t bh_ = (size_t)(b * Hc + h);
    float* ap = attn + bh_ * Sc * Sc;

    __shared__ float inv[128];
    if (tid < 128) inv[tid] = 1.0f / g_lbuf[bh_ * Sc + r0 + tid];
    __syncthreads();

    const int ncol4 = (it + 1) * 32;
    for (int r = tid >> 7; r < 128; r += 4) {
        const float s = inv[r];
        float4* rowp = (float4*)&ap[(size_t)(r0 + r) * Sc];
#pragma unroll 4
        for (int c4 = (tid & 127); c4 < ncol4; c4 += 128) {
            float4 v = rowp[c4];
            v.x *= s; v.y *= s; v.z *= s; v.w *= s;
            rowp[c4] = v;
        }
    }
}

// ---------------------------------------------------------------------------
extern "C" void kernel_launch(void* const* d_in, const int* in_sizes, int n_in,
                              void* d_out, int out_size)
{
    (void)in_sizes; (void)n_in; (void)out_size;
    const float* Q   = (const float*)d_in[0];
    const float* Kin = (const float*)d_in[1];
    const float* Vin = (const float*)d_in[2];
    const float* Wq = (const float*)d_in[4];
    const float* bq = (const float*)d_in[5];
    const float* Wk = (const float*)d_in[6];
    const float* bk = (const float*)d_in[7];
    const float* Wv = (const float*)d_in[8];
    const float* bv = (const float*)d_in[9];
    const float* Wo = (const float*)d_in[10];
    const float* bo = (const float*)d_in[11];

    float* out  = (float*)d_out;
    float* attn = out + SZ_QKV;
    float* qo   = attn + SZ_ATTN;
    float* ko   = qo + SZ_QKV;
    float* vo   = ko + SZ_QKV;

    void *iah, *ial, *wh, *wl, *qh, *ql, *kh, *kl, *vh, *vl, *ch2, *cl2;
    cudaGetSymbolAddress(&iah, g_iah);  cudaGetSymbolAddress(&ial, g_ial);
    cudaGetSymbolAddress(&wh, g_wh);    cudaGetSymbolAddress(&wl, g_wl);
    cudaGetSymbolAddress(&qh, g_qh);    cudaGetSymbolAddress(&ql, g_ql);
    cudaGetSymbolAddress(&kh, g_kh);    cudaGetSymbolAddress(&kl, g_kl);
    cudaGetSymbolAddress(&vh, g_vh);    cudaGetSymbolAddress(&vl, g_vl);
    cudaGetSymbolAddress(&ch2, g_ch2);  cudaGetSymbolAddress(&cl2, g_cl2);
    __nv_bfloat16 *IAH = (__nv_bfloat16*)iah, *IAL = (__nv_bfloat16*)ial;
    __nv_bfloat16 *WH  = (__nv_bfloat16*)wh,  *WL  = (__nv_bfloat16*)wl;

    cudaFuncSetAttribute(gemm_bf16,
                         cudaFuncAttributeMaxDynamicSharedMemorySize, GSM3);
    cudaFuncSetAttribute(attn_fused_mma,
                         cudaFuncAttributeMaxDynamicSharedMemorySize, SM2_TOT);

    const int M = Bc * Sc;

    cudaStream_t s1;
    cudaStreamCreateWithFlags(&s1, cudaStreamNonBlocking);
    cudaEvent_t e0, e1, e2;
    cudaEventCreateWithFlags(&e0, cudaEventDisableTiming);
    cudaEventCreateWithFlags(&e1, cudaEventDisableTiming);
    cudaEventCreateWithFlags(&e2, cudaEventDisableTiming);

    dim3 agrid(Sc / 128, Hc, Bc);

    // fork EARLY: fill_upper has no deps — overlaps converts + QKV gemm
    cudaEventRecord(e0, 0);
    cudaStreamWaitEvent(s1, e0, 0);
    fill_upper<<<agrid, 512, 0, s1>>>(attn);

    // 1) converts
    ConvBatch cb;
    const float* srcs[7] = { Q, Kin, Vin, Wq, Wk, Wv, Wo };
    for (int z = 0; z < 7; z++) {
        cb.j[z].src = srcs[z];
        if (z < 3) {
            cb.j[z].h = IAH + (size_t)z * MD;
            cb.j[z].l = IAL + (size_t)z * MD;
            cb.j[z].n4 = (int)(MD / 4);
        } else {
            cb.j[z].h = WH + (size_t)(z - 3) * DD;
            cb.j[z].l = WL + (size_t)(z - 3) * DD;
            cb.j[z].n4 = (int)(DD / 4);
        }
    }
    dim3 cgrid((unsigned)((MD / 4 + 255) / 256), 1, 7);
    convert_all<<<cgrid, 256>>>(cb);

    // 2) QKV projections
    GemmBatch qb;
    const float* biases[3] = { bq, bk, bv };
    float* outs[3] = { qo, ko, vo };
    __nv_bfloat16* chp[3] = { (__nv_bfloat16*)qh, (__nv_bfloat16*)kh, (__nv_bfloat16*)vh };
    __nv_bfloat16* clp[3] = { (__nv_bfloat16*)ql, (__nv_bfloat16*)kl, (__nv_bfloat16*)vl };
    for (int z = 0; z < 3; z++) {
        qb.j[z].Ah = IAH + (size_t)z * MD; qb.j[z].Al = IAL + (size_t)z * MD;
        qb.j[z].Bh = WH + (size_t)z * DD;  qb.j[z].Bl = WL + (size_t)z * DD;
        qb.j[z].bias = biases[z]; qb.j[z].C = outs[z];
        qb.j[z].Ch = chp[z]; qb.j[z].Cl = clp[z];
    }
    dim3 qgrid(Dc / 128, M / 128, 3);
    gemm_bf16<<<qgrid, 256, GSM3>>>(qb, M, Dc, Dc);

    // 3) attention
    attn_fused_mma<<<agrid, 256, SM2_TOT>>>(attn);
    cudaEventRecord(e1, 0);

    cudaStreamWaitEvent(s1, e1, 0);
    norm_lower<<<agrid, 512, 0, s1>>>(attn);
    cudaEventRecord(e2, s1);

    // 4) O projection (overlaps norm_lower)
    GemmBatch ob;
    ob.j[0].Ah = (__nv_bfloat16*)ch2; ob.j[0].Al = (__nv_bfloat16*)cl2;
    ob.j[0].Bh = WH + 3 * DD;         ob.j[0].Bl = WL + 3 * DD;
    ob.j[0].bias = bo; ob.j[0].C = out;
    ob.j[0].Ch = nullptr; ob.j[0].Cl = nullptr;
    ob.j[1] = ob.j[0]; ob.j[2] = ob.j[0];
    dim3 ogrid(Dc / 128, M / 128, 1);
    gemm_bf16<<<ogrid, 256, GSM3>>>(ob, M, Dc, Dc);

    cudaStreamWaitEvent(0, e2, 0);
}

// round 11
// speedup vs baseline: 1.2511x; 1.0061x over previous
#include <cuda_runtime.h>
#include <cuda_bf16.h>
#include <math.h>
#include <stdint.h>

#define Bc 2
#define Sc 2048
#define Dc 1024
#define Hc 16
#define DPc 64

static const size_t SZ_QKV  = (size_t)Bc * Sc * Dc;        // 4194304
static const size_t SZ_ATTN = (size_t)Bc * Hc * Sc * Sc;   // 134217728
#define MD  ((size_t)4194304)
#define DD  ((size_t)1048576)

__device__ __nv_bfloat16 g_iah[3 * MD], g_ial[3 * MD];
__device__ __nv_bfloat16 g_wh[4 * DD],  g_wl[4 * DD];
__device__ __nv_bfloat16 g_qh[MD], g_ql[MD];
__device__ __nv_bfloat16 g_kh[MD], g_kl[MD];
__device__ __nv_bfloat16 g_vh[MD], g_vl[MD];
__device__ __nv_bfloat16 g_ch2[MD], g_cl2[MD];
__device__ float g_lbuf[(size_t)Bc * Hc * Sc];

// ---------------------------------------------------------------------------
__device__ __forceinline__ uint32_t smem_u32(const void* p) {
    uint32_t a;
    asm("{ .reg .u64 t; cvta.to.shared.u64 t, %1; cvt.u32.u64 %0, t; }"
        : "=r"(a) : "l"(p));
    return a;
}
__device__ __forceinline__ void mma16816(float* d, const uint32_t* a, const uint32_t* b) {
    asm volatile(
        "mma.sync.aligned.m16n8k16.row.col.f32.bf16.bf16.f32 "
        "{%0,%1,%2,%3}, {%4,%5,%6,%7}, {%8,%9}, {%0,%1,%2,%3};"
        : "+f"(d[0]), "+f"(d[1]), "+f"(d[2]), "+f"(d[3])
        : "r"(a[0]), "r"(a[1]), "r"(a[2]), "r"(a[3]), "r"(b[0]), "r"(b[1]));
}
__device__ __forceinline__ void ldsm4(uint32_t* r, uint32_t addr) {
    asm volatile("ldmatrix.sync.aligned.m8n8.x4.shared.b16 {%0,%1,%2,%3}, [%4];"
                 : "=r"(r[0]), "=r"(r[1]), "=r"(r[2]), "=r"(r[3]) : "r"(addr));
}
__device__ __forceinline__ void ldsm4t(uint32_t* r, uint32_t addr) {
    asm volatile("ldmatrix.sync.aligned.m8n8.x4.trans.shared.b16 {%0,%1,%2,%3}, [%4];"
                 : "=r"(r[0]), "=r"(r[1]), "=r"(r[2]), "=r"(r[3]) : "r"(addr));
}
__device__ __forceinline__ float fexp2(float x) {
    float r;
    asm("ex2.approx.f32 %0, %1;" : "=f"(r) : "f"(x));
    return r;
}
__device__ __forceinline__ uint32_t pack_hi(float x, float y) {
    __nv_bfloat162 h = __float22bfloat162_rn(make_float2(x, y));
    return *(uint32_t*)&h;
}
__device__ __forceinline__ uint32_t pack_lo(float x, float y) {
    __nv_bfloat16 hx = __float2bfloat16(x), hy = __float2bfloat16(y);
    __nv_bfloat162 l = __float22bfloat162_rn(
        make_float2(x - __bfloat162float(hx), y - __bfloat162float(hy)));
    return *(uint32_t*)&l;
}
__device__ __forceinline__ void cpa16(uint32_t s, const void* g) {
    asm volatile("cp.async.cg.shared.global [%0], [%1], 16;" :: "r"(s), "l"(g));
}
#define CP_COMMIT()  asm volatile("cp.async.commit_group;" ::: "memory")
#define CP_WAITG(n)  asm volatile("cp.async.wait_group %0;" :: "n"(n) : "memory")

// ---------------------------------------------------------------------------
// converts
// ---------------------------------------------------------------------------
struct ConvJob { const float* src; __nv_bfloat16 *h, *l; int n4; };
struct ConvBatch { ConvJob j[7]; };

__global__ __launch_bounds__(256, 4)
void convert_all(ConvBatch cb)
{
    ConvJob jb = cb.j[blockIdx.z];
    int i = blockIdx.x * 256 + threadIdx.x;
    if (i >= jb.n4) return;
    float4 v = ((const float4*)jb.src)[i];
    uint2 H, L;
    H.x = pack_hi(v.x, v.y); H.y = pack_hi(v.z, v.w);
    L.x = pack_lo(v.x, v.y); L.y = pack_lo(v.z, v.w);
    ((uint2*)jb.h)[i] = H;
    ((uint2*)jb.l)[i] = L;
}

// ---------------------------------------------------------------------------
// GEMM (unchanged from R10)
// ---------------------------------------------------------------------------
#define GROWB 80
#define GPLANE (128 * GROWB)
#define GSTAGE (4 * GPLANE)
#define GSM3 (3 * GSTAGE)

struct GemmJob {
    const __nv_bfloat16 *Ah, *Al, *Bh, *Bl;
    const float* bias;
    float* C;
    __nv_bfloat16 *Ch, *Cl;
};
struct GemmBatch { GemmJob j[3]; };

__global__ __launch_bounds__(256, 1)
void gemm_bf16(GemmBatch gb, int M, int N, int K)
{
    extern __shared__ __align__(128) char sm[];
    const uint32_t smb = smem_u32(sm);
    const GemmJob jb = gb.j[blockIdx.z];
    const int tid = threadIdx.x;
    const int wid = tid >> 5, lane = tid & 31;
    const int m0 = blockIdx.y * 128, n0 = blockIdx.x * 128;
    const int warp_m = (wid & 1) * 64;
    const int warp_n = (wid >> 1) * 32;
    const int nch = K / 32;

    const __nv_bfloat16* bases[4] = { jb.Ah, jb.Al, jb.Bh, jb.Bl };

    auto issue = [&](int ch) {
        const uint32_t sb = smb + (uint32_t)((ch % 3) * GSTAGE);
        const size_t gk = (size_t)ch * 32;
#pragma unroll
        for (int p = 0; p < 4; p++) {
            const int rbase = (p < 2) ? m0 : n0;
#pragma unroll
            for (int hh = 0; hh < 2; hh++) {
                int idx = hh * 256 + tid;
                int r = idx >> 2, c = idx & 3;
                cpa16(sb + (uint32_t)(p * GPLANE + r * 80 + c * 16),
                      bases[p] + (size_t)(rbase + r) * K + gk + c * 8);
            }
        }
    };

    float acc[4][4][4];
#pragma unroll
    for (int i = 0; i < 4; i++)
#pragma unroll
        for (int j = 0; j < 4; j++)
#pragma unroll
            for (int c = 0; c < 4; c++) acc[i][j][c] = 0.0f;

    issue(0); CP_COMMIT();
    issue(1); CP_COMMIT();

    const int arow = lane & 15;
    const int acol = (lane >> 4) * 8;
    const int bg = lane >> 3, bw = lane & 7;

    for (int ch = 0; ch < nch; ch++) {
        CP_WAITG(1);
        __syncthreads();
        if (ch + 2 < nch) issue(ch + 2);
        CP_COMMIT();

        const uint32_t sb = smb + (uint32_t)((ch % 3) * GSTAGE);
#pragma unroll
        for (int ks = 0; ks < 2; ks++) {
            const int k16 = ks * 16;
            uint32_t ah[4][4], al[4][4];
#pragma unroll
            for (int mt = 0; mt < 4; mt++) {
                uint32_t off = (uint32_t)((warp_m + mt * 16 + arow) * 80 + (k16 + acol) * 2);
                ldsm4(ah[mt], sb + 0 * GPLANE + off);
                ldsm4(al[mt], sb + 1 * GPLANE + off);
            }
            uint32_t bh[4][2], bl[4][2];
#pragma unroll
            for (int nb = 0; nb < 2; nb++) {
                uint32_t off = (uint32_t)((warp_n + nb * 16 + (bg & 1) * 8 + bw) * 80
                                          + (k16 + (bg >> 1) * 8) * 2);
                uint32_t t[4];
                ldsm4(t, sb + 2 * GPLANE + off);
                bh[nb * 2 + 0][0] = t[0]; bh[nb * 2 + 0][1] = t[2];
                bh[nb * 2 + 1][0] = t[1]; bh[nb * 2 + 1][1] = t[3];
                ldsm4(t, sb + 3 * GPLANE + off);
                bl[nb * 2 + 0][0] = t[0]; bl[nb * 2 + 0][1] = t[2];
                bl[nb * 2 + 1][0] = t[1]; bl[nb * 2 + 1][1] = t[3];
            }
#pragma unroll
            for (int mt = 0; mt < 4; mt++)
#pragma unroll
                for (int nt = 0; nt < 4; nt++) {
                    mma16816(acc[mt][nt], ah[mt], bh[nt]);
                    mma16816(acc[mt][nt], ah[mt], bl[nt]);
                    mma16816(acc[mt][nt], al[mt], bh[nt]);
                }
        }
        __syncthreads();
    }

    const int lr = lane >> 2, lc = (lane & 3) * 2;
    const bool wplanes = (jb.Ch != nullptr);
#pragma unroll
    for (int nt = 0; nt < 4; nt++) {
        int col = n0 + warp_n + nt * 8 + lc;
        float2 bv = *(const float2*)&jb.bias[col];
#pragma unroll
        for (int mt = 0; mt < 4; mt++) {
            int r0 = m0 + warp_m + mt * 16 + lr;
            float2 o0 = make_float2(acc[mt][nt][0] + bv.x, acc[mt][nt][1] + bv.y);
            float2 o1 = make_float2(acc[mt][nt][2] + bv.x, acc[mt][nt][3] + bv.y);
            *(float2*)(jb.C + (size_t)r0 * N + col) = o0;
            *(float2*)(jb.C + (size_t)(r0 + 8) * N + col) = o1;
            if (wplanes) {
                size_t i0 = (size_t)r0 * N + col;
                size_t i1 = (size_t)(r0 + 8) * N + col;
                *(uint32_t*)&jb.Ch[i0] = pack_hi(o0.x, o0.y);
                *(uint32_t*)&jb.Cl[i0] = pack_lo(o0.x, o0.y);
                *(uint32_t*)&jb.Ch[i1] = pack_hi(o1.x, o1.y);
                *(uint32_t*)&jb.Cl[i1] = pack_lo(o1.x, o1.y);
            }
        }
    }
}

// ---------------------------------------------------------------------------
// Pipelined fused attention — 512 threads / 16 warps, warp tile 32x32.
// smem: Q hi/lo | K stage0 hi/lo | K stage1 hi/lo | V hi/lo | P hi/lo
// ---------------------------------------------------------------------------
#define QROWB 144
#define PROWB 272
#define AQH   0
#define AQL   18432
#define AKH0  36864
#define AKH1  73728
#define AVH   110592
#define AVL   129024
#define APH   147456
#define APL   182272
#define SM2_TOT 217088

__global__ __launch_bounds__(512, 1)
void attn_fused_mma(float* __restrict__ attn)
{
    extern __shared__ __align__(128) char sm[];
    const uint32_t smb = smem_u32(sm);
    const int tid = threadIdx.x;
    const int wid = tid >> 5, lane = tid & 31;
    const int b = blockIdx.z, h = blockIdx.y;
    const int it = (int)gridDim.x - 1 - (int)blockIdx.x;
    const int r0 = it * 128;
    const int warp_m = (wid & 3) * 32;       // 4 M groups of 32 rows
    const int warp_n = (wid >> 2) * 32;      // 4 N groups of 32 cols
    const int wnp = (wid >> 2) * 16;         // PV depth group
    const int lr = lane >> 2, lc2 = (lane & 3) * 2;
    const float CE = 0.125f * 1.4426950408889634f;

    const size_t qoff = ((size_t)b * Sc + r0) * Dc + h * DPc;
    const size_t koff = (size_t)b * Sc * Dc + h * DPc;
    const size_t bh_ = (size_t)(b * Hc + h);
    float* attnp = attn + bh_ * Sc * Sc;

    // cp.async a 128x64-bf16 plane into smem (stride QROWB): 512 thr x 2 chunks
    auto issue_plane = [&](uint32_t dst, const __nv_bfloat16* src) {
#pragma unroll
        for (int e = 0; e < 2; e++) {
            int idx = tid + e * 512;          // 0..1023
            int r = idx >> 3, c = idx & 7;
            cpa16(dst + (uint32_t)(r * QROWB + c * 16), src + (size_t)r * Dc + c * 8);
        }
    };
    auto issue_K = [&](int jt) {
        uint32_t dst = smb + ((jt & 1) ? AKH1 : AKH0);
        const size_t off = koff + (size_t)jt * 128 * Dc;
        issue_plane(dst, g_kh + off);
        issue_plane(dst + 18432, g_kl + off);
    };
    auto issue_V = [&](int jt) {
        const size_t off = koff + (size_t)jt * 128 * Dc;
        issue_plane(smb + AVH, g_vh + off);
        issue_plane(smb + AVL, g_vl + off);
    };

    issue_plane(smb + AQH, g_qh + qoff);
    issue_plane(smb + AQL, g_ql + qoff);
    issue_K(0);
    CP_COMMIT();
    issue_V(0);
    CP_COMMIT();
    if (it >= 1) issue_K(1);
    CP_COMMIT();

    float ctx[2][2][4];
#pragma unroll
    for (int i = 0; i < 2; i++)
#pragma unroll
        for (int j = 0; j < 2; j++)
#pragma unroll
            for (int c = 0; c < 4; c++) ctx[i][j][c] = 0.0f;

    float lsum[2][2];
#pragma unroll
    for (int i = 0; i < 2; i++) { lsum[i][0] = 0.0f; lsum[i][1] = 0.0f; }

    const int arow = lane & 15;
    const int acol = (lane >> 4) * 8;
    const int bg = lane >> 3, bw = lane & 7;

    for (int jt = 0; jt <= it; jt++) {
        const int j0 = jt * 128;

        CP_WAITG(2);
        __syncthreads();

        const uint32_t kbase = (jt & 1) ? AKH1 : AKH0;
        float acc[2][4][4];
#pragma unroll
        for (int i = 0; i < 2; i++)
#pragma unroll
            for (int j = 0; j < 4; j++)
#pragma unroll
                for (int c = 0; c < 4; c++) acc[i][j][c] = 0.0f;

        // S = Q Kt (3 terms), warp tile 32x32
#pragma unroll
        for (int ks = 0; ks < 4; ks++) {
            const int k16 = ks * 16;
            uint32_t ah[2][4], al[2][4];
#pragma unroll
            for (int mt = 0; mt < 2; mt++) {
                uint32_t off = (uint32_t)((warp_m + mt * 16 + arow) * QROWB + (k16 + acol) * 2);
                ldsm4(ah[mt], smb + AQH + off);
                ldsm4(al[mt], smb + AQL + off);
            }
            uint32_t bhf[4][2], blf[4][2];
#pragma unroll
            for (int nb = 0; nb < 2; nb++) {
                uint32_t off = (uint32_t)((warp_n + nb * 16 + (bg & 1) * 8 + bw) * QROWB
                                          + (k16 + (bg >> 1) * 8) * 2);
                uint32_t t[4];
                ldsm4(t, smb + kbase + off);
                bhf[nb * 2 + 0][0] = t[0]; bhf[nb * 2 + 0][1] = t[2];
                bhf[nb * 2 + 1][0] = t[1]; bhf[nb * 2 + 1][1] = t[3];
                ldsm4(t, smb + kbase + 18432 + off);
                blf[nb * 2 + 0][0] = t[0]; blf[nb * 2 + 0][1] = t[2];
                blf[nb * 2 + 1][0] = t[1]; blf[nb * 2 + 1][1] = t[3];
            }
#pragma unroll
            for (int mt = 0; mt < 2; mt++)
#pragma unroll
                for (int nt = 0; nt < 4; nt++) {
                    mma16816(acc[mt][nt], ah[mt], bhf[nt]);
                    mma16816(acc[mt][nt], ah[mt], blf[nt]);
                    mma16816(acc[mt][nt], al[mt], bhf[nt]);
                }
        }

        // epilogue: exp -> attn gmem (unnormalized) + P hi/lo smem
        const bool diag = (jt == it);
#pragma unroll
        for (int mt = 0; mt < 2; mt++)
#pragma unroll
            for (int hf = 0; hf < 2; hf++) {
                const int rowg = warp_m + mt * 16 + lr + hf * 8;
                const int growg = r0 + rowg;
                float rl = 0.0f;
#pragma unroll
                for (int nt = 0; nt < 4; nt++) {
                    int col = warp_n + nt * 8 + lc2;
                    float p0 = fexp2(acc[mt][nt][hf * 2 + 0] * CE);
                    float p1 = fexp2(acc[mt][nt][hf * 2 + 1] * CE);
                    if (diag && (j0 + col + 0) > growg) p0 = 0.0f;
                    if (diag && (j0 + col + 1) > growg) p1 = 0.0f;
                    *(float2*)&attnp[(size_t)growg * Sc + j0 + col] = make_float2(p0, p1);
                    *(uint32_t*)(sm + APH + rowg * PROWB + col * 2) = pack_hi(p0, p1);
                    *(uint32_t*)(sm + APL + rowg * PROWB + col * 2) = pack_lo(p0, p1);
                    rl += p0 + p1;
                }
                lsum[mt][hf] += rl;
            }

        CP_WAITG(1);
        __syncthreads();

        // PV: ctx += P(hi+lo) @ V(hi+lo) [3 terms]; V via ldmatrix.trans
#pragma unroll
        for (int ks = 0; ks < 8; ks++) {
            const int k16 = ks * 16;
            uint32_t ph[2][4], pl[2][4];
#pragma unroll
            for (int mt = 0; mt < 2; mt++) {
                uint32_t off = (uint32_t)((warp_m + mt * 16 + arow) * PROWB + (k16 + acol) * 2);
                ldsm4(ph[mt], smb + APH + off);
                ldsm4(pl[mt], smb + APL + off);
            }
            uint32_t vh[2][2], vl[2][2];
            {
                uint32_t voff = (uint32_t)((k16 + (lane & 15)) * QROWB
                                           + (wnp + (lane >> 4) * 8) * 2);
                uint32_t t[4];
                ldsm4t(t, smb + AVH + voff);
                vh[0][0] = t[0]; vh[0][1] = t[1];
                vh[1][0] = t[2]; vh[1][1] = t[3];
                ldsm4t(t, smb + AVL + voff);
                vl[0][0] = t[0]; vl[0][1] = t[1];
                vl[1][0] = t[2]; vl[1][1] = t[3];
            }
#pragma unroll
            for (int mt = 0; mt < 2; mt++)
#pragma unroll
                for (int ntp = 0; ntp < 2; ntp++) {
                    mma16816(ctx[mt][ntp], ph[mt], vh[ntp]);
                    mma16816(ctx[mt][ntp], ph[mt], vl[ntp]);
                    mma16816(ctx[mt][ntp], pl[mt], vh[ntp]);
                }
        }

        __syncthreads();

        if (jt + 1 <= it) issue_V(jt + 1);
        CP_COMMIT();
        if (jt + 2 <= it) issue_K(jt + 2);
        CP_COMMIT();
    }

    // reduce row sums: 4 lanes per row, then 4 warp_n groups via smem
#pragma unroll
    for (int off = 1; off <= 2; off <<= 1)
#pragma unroll
        for (int mt = 0; mt < 2; mt++)
#pragma unroll
            for (int hf = 0; hf < 2; hf++)
                lsum[mt][hf] += __shfl_xor_sync(0xffffffffu, lsum[mt][hf], off);

    __syncthreads();
    float* smR = (float*)(sm + AVH);
    float* smF = smR + 512;
    if ((lane & 3) == 0) {
        const int g = wid >> 2;
#pragma unroll
        for (int mt = 0; mt < 2; mt++)
#pragma unroll
            for (int hf = 0; hf < 2; hf++)
                smR[g * 128 + warp_m + mt * 16 + lr + hf * 8] = lsum[mt][hf];
    }
    __syncthreads();
    if (tid < 128) {
        float l = smR[tid] + smR[128 + tid] + smR[256 + tid] + smR[384 + tid];
        smF[tid] = 1.0f / l;
        g_lbuf[bh_ * Sc + r0 + tid] = l;
    }
    __syncthreads();

    // normalized ctx -> bf16 hi/lo planes
#pragma unroll
    for (int mt = 0; mt < 2; mt++)
#pragma unroll
        for (int ntp = 0; ntp < 2; ntp++) {
            int dcol = h * DPc + wnp + ntp * 8 + lc2;
#pragma unroll
            for (int hf = 0; hf < 2; hf++) {
                int rowl = warp_m + mt * 16 + lr + hf * 8;
                float inv = smF[rowl];
                int row = r0 + rowl;
                float x0 = ctx[mt][ntp][hf * 2 + 0] * inv;
                float x1 = ctx[mt][ntp][hf * 2 + 1] * inv;
                size_t idx = ((size_t)b * Sc + row) * Dc + dcol;
                *(uint32_t*)&g_ch2[idx] = pack_hi(x0, x1);
                *(uint32_t*)&g_cl2[idx] = pack_lo(x0, x1);
            }
        }
}

// ---------------------------------------------------------------------------
__global__ __launch_bounds__(512, 2)
void fill_upper(float* __restrict__ attn)
{
    const int b = blockIdx.z, h = blockIdx.y, it = blockIdx.x;
    const int ncol4 = 512 - (it + 1) * 32;
    if (ncol4 <= 0) return;
    const int c0 = (it + 1) * 32;
    float* ap = attn + ((size_t)(b * Hc + h)) * Sc * Sc + (size_t)it * 128 * Sc;
    const float4 z = make_float4(0.f, 0.f, 0.f, 0.f);
    const int tid = threadIdx.x;
    const int total = 128 * ncol4;
    for (int i = tid; i < total; i += 512) {
        int r = i / ncol4, c = i - r * ncol4;
        ((float4*)&ap[(size_t)r * Sc])[c0 + c] = z;
    }
}

__global__ __launch_bounds__(512, 2)
void norm_lower(float* __restrict__ attn)
{
    const int b = blockIdx.z, h = blockIdx.y, it = blockIdx.x;
    const int r0 = it * 128;
    const int tid = threadIdx.x;
    const size_t bh_ = (size_t)(b * Hc + h);
    float* ap = attn + bh_ * Sc * Sc;

    __shared__ float inv[128];
    if (tid < 128) inv[tid] = 1.0f / g_lbuf[bh_ * Sc + r0 + tid];
    __syncthreads();

    const int ncol4 = (it + 1) * 32;
    for (int r = tid >> 7; r < 128; r += 4) {
        const float s = inv[r];
        float4* rowp = (float4*)&ap[(size_t)(r0 + r) * Sc];
#pragma unroll 4
        for (int c4 = (tid & 127); c4 < ncol4; c4 += 128) {
            float4 v = rowp[c4];
            v.x *= s; v.y *= s; v.z *= s; v.w *= s;
            rowp[c4] = v;
        }
    }
}

// ---------------------------------------------------------------------------
extern "C" void kernel_launch(void* const* d_in, const int* in_sizes, int n_in,
                              void* d_out, int out_size)
{
    (void)in_sizes; (void)n_in; (void)out_size;
    const float* Q   = (const float*)d_in[0];
    const float* Kin = (const float*)d_in[1];
    const float* Vin = (const float*)d_in[2];
    const float* Wq = (const float*)d_in[4];
    const float* bq = (const float*)d_in[5];
    const float* Wk = (const float*)d_in[6];
    const float* bk = (const float*)d_in[7];
    const float* Wv = (const float*)d_in[8];
    const float* bv = (const float*)d_in[9];
    const float* Wo = (const float*)d_in[10];
    const float* bo = (const float*)d_in[11];

    float* out  = (float*)d_out;
    float* attn = out + SZ_QKV;
    float* qo   = attn + SZ_ATTN;
    float* ko   = qo + SZ_QKV;
    float* vo   = ko + SZ_QKV;

    void *iah, *ial, *wh, *wl, *qh, *ql, *kh, *kl, *vh, *vl, *ch2, *cl2;
    cudaGetSymbolAddress(&iah, g_iah);  cudaGetSymbolAddress(&ial, g_ial);
    cudaGetSymbolAddress(&wh, g_wh);    cudaGetSymbolAddress(&wl, g_wl);
    cudaGetSymbolAddress(&qh, g_qh);    cudaGetSymbolAddress(&ql, g_ql);
    cudaGetSymbolAddress(&kh, g_kh);    cudaGetSymbolAddress(&kl, g_kl);
    cudaGetSymbolAddress(&vh, g_vh);    cudaGetSymbolAddress(&vl, g_vl);
    cudaGetSymbolAddress(&ch2, g_ch2);  cudaGetSymbolAddress(&cl2, g_cl2);
    __nv_bfloat16 *IAH = (__nv_bfloat16*)iah, *IAL = (__nv_bfloat16*)ial;
    __nv_bfloat16 *WH  = (__nv_bfloat16*)wh,  *WL  = (__nv_bfloat16*)wl;

    cudaFuncSetAttribute(gemm_bf16,
                         cudaFuncAttributeMaxDynamicSharedMemorySize, GSM3);
    cudaFuncSetAttribute(attn_fused_mma,
                         cudaFuncAttributeMaxDynamicSharedMemorySize, SM2_TOT);

    const int M = Bc * Sc;

    cudaStream_t s1;
    cudaStreamCreateWithFlags(&s1, cudaStreamNonBlocking);
    cudaEvent_t e0, e1, e2;
    cudaEventCreateWithFlags(&e0, cudaEventDisableTiming);
    cudaEventCreateWithFlags(&e1, cudaEventDisableTiming);
    cudaEventCreateWithFlags(&e2, cudaEventDisableTiming);

    dim3 agrid(Sc / 128, Hc, Bc);

    // fork EARLY: fill_upper has no deps — overlaps converts + QKV gemm
    cudaEventRecord(e0, 0);
    cudaStreamWaitEvent(s1, e0, 0);
    fill_upper<<<agrid, 512, 0, s1>>>(attn);

    // 1) converts
    ConvBatch cb;
    const float* srcs[7] = { Q, Kin, Vin, Wq, Wk, Wv, Wo };
    for (int z = 0; z < 7; z++) {
        cb.j[z].src = srcs[z];
        if (z < 3) {
            cb.j[z].h = IAH + (size_t)z * MD;
            cb.j[z].l = IAL + (size_t)z * MD;
            cb.j[z].n4 = (int)(MD / 4);
        } else {
            cb.j[z].h = WH + (size_t)(z - 3) * DD;
            cb.j[z].l = WL + (size_t)(z - 3) * DD;
            cb.j[z].n4 = (int)(DD / 4);
        }
    }
    dim3 cgrid((unsigned)((MD / 4 + 255) / 256), 1, 7);
    convert_all<<<cgrid, 256>>>(cb);

    // 2) QKV projections
    GemmBatch qb;
    const float* biases[3] = { bq, bk, bv };
    float* outs[3] = { qo, ko, vo };
    __nv_bfloat16* chp[3] = { (__nv_bfloat16*)qh, (__nv_bfloat16*)kh, (__nv_bfloat16*)vh };
    __nv_bfloat16* clp[3] = { (__nv_bfloat16*)ql, (__nv_bfloat16*)kl, (__nv_bfloat16*)vl };
    for (int z = 0; z < 3; z++) {
        qb.j[z].Ah = IAH + (size_t)z * MD; qb.j[z].Al = IAL + (size_t)z * MD;
        qb.j[z].Bh = WH + (size_t)z * DD;  qb.j[z].Bl = WL + (size_t)z * DD;
        qb.j[z].bias = biases[z]; qb.j[z].C = outs[z];
        qb.j[z].Ch = chp[z]; qb.j[z].Cl = clp[z];
    }
    dim3 qgrid(Dc / 128, M / 128, 3);
    gemm_bf16<<<qgrid, 256, GSM3>>>(qb, M, Dc, Dc);

    // 3) attention (512 threads)
    attn_fused_mma<<<agrid, 512, SM2_TOT>>>(attn);
    cudaEventRecord(e1, 0);

    cudaStreamWaitEvent(s1, e1, 0);
    norm_lower<<<agrid, 512, 0, s1>>>(attn);
    cudaEventRecord(e2, s1);

    // 4) O projection (overlaps norm_lower)
    GemmBatch ob;
    ob.j[0].Ah = (__nv_bfloat16*)ch2; ob.j[0].Al = (__nv_bfloat16*)cl2;
    ob.j[0].Bh = WH + 3 * DD;         ob.j[0].Bl = WL + 3 * DD;
    ob.j[0].bias = bo; ob.j[0].C = out;
    ob.j[0].Ch = nullptr; ob.j[0].Cl = nullptr;
    ob.j[1] = ob.j[0]; ob.j[2] = ob.j[0];
    dim3 ogrid(Dc / 128, M / 128, 1);
    gemm_bf16<<<ogrid, 256, GSM3>>>(ob, M, Dc, Dc);

    cudaStreamWaitEvent(0, e2, 0);
}

// round 12
// speedup vs baseline: 1.2526x; 1.0013x over previous
#include <cuda_runtime.h>
#include <cuda_bf16.h>
#include <math.h>
#include <stdint.h>

#define Bc 2
#define Sc 2048
#define Dc 1024
#define Hc 16
#define DPc 64

static const size_t SZ_QKV  = (size_t)Bc * Sc * Dc;        // 4194304
static const size_t SZ_ATTN = (size_t)Bc * Hc * Sc * Sc;   // 134217728
#define MD  ((size_t)4194304)
#define DD  ((size_t)1048576)

__device__ __nv_bfloat16 g_iah[3 * MD], g_ial[3 * MD];
__device__ __nv_bfloat16 g_wh[4 * DD],  g_wl[4 * DD];
__device__ __nv_bfloat16 g_qh[MD], g_ql[MD];
__device__ __nv_bfloat16 g_kh[MD], g_kl[MD];
__device__ __nv_bfloat16 g_vh[MD], g_vl[MD];
__device__ __nv_bfloat16 g_ch2[MD], g_cl2[MD];
__device__ float g_lbuf[(size_t)Bc * Hc * Sc];

// ---------------------------------------------------------------------------
__device__ __forceinline__ uint32_t smem_u32(const void* p) {
    uint32_t a;
    asm("{ .reg .u64 t; cvta.to.shared.u64 t, %1; cvt.u32.u64 %0, t; }"
        : "=r"(a) : "l"(p));
    return a;
}
__device__ __forceinline__ void mma16816(float* d, const uint32_t* a, const uint32_t* b) {
    asm volatile(
        "mma.sync.aligned.m16n8k16.row.col.f32.bf16.bf16.f32 "
        "{%0,%1,%2,%3}, {%4,%5,%6,%7}, {%8,%9}, {%0,%1,%2,%3};"
        : "+f"(d[0]), "+f"(d[1]), "+f"(d[2]), "+f"(d[3])
        : "r"(a[0]), "r"(a[1]), "r"(a[2]), "r"(a[3]), "r"(b[0]), "r"(b[1]));
}
__device__ __forceinline__ void ldsm4(uint32_t* r, uint32_t addr) {
    asm volatile("ldmatrix.sync.aligned.m8n8.x4.shared.b16 {%0,%1,%2,%3}, [%4];"
                 : "=r"(r[0]), "=r"(r[1]), "=r"(r[2]), "=r"(r[3]) : "r"(addr));
}
__device__ __forceinline__ void ldsm4t(uint32_t* r, uint32_t addr) {
    asm volatile("ldmatrix.sync.aligned.m8n8.x4.trans.shared.b16 {%0,%1,%2,%3}, [%4];"
                 : "=r"(r[0]), "=r"(r[1]), "=r"(r[2]), "=r"(r[3]) : "r"(addr));
}
__device__ __forceinline__ float fexp2(float x) {
    float r;
    asm("ex2.approx.f32 %0, %1;" : "=f"(r) : "f"(x));
    return r;
}
__device__ __forceinline__ uint32_t pack_hi(float x, float y) {
    __nv_bfloat162 h = __float22bfloat162_rn(make_float2(x, y));
    return *(uint32_t*)&h;
}
__device__ __forceinline__ uint32_t pack_lo(float x, float y) {
    __nv_bfloat16 hx = __float2bfloat16(x), hy = __float2bfloat16(y);
    __nv_bfloat162 l = __float22bfloat162_rn(
        make_float2(x - __bfloat162float(hx), y - __bfloat162float(hy)));
    return *(uint32_t*)&l;
}
__device__ __forceinline__ void cpa16(uint32_t s, const void* g) {
    asm volatile("cp.async.cg.shared.global [%0], [%1], 16;" :: "r"(s), "l"(g));
}
#define CP_COMMIT()  asm volatile("cp.async.commit_group;" ::: "memory")
#define CP_WAITG(n)  asm volatile("cp.async.wait_group %0;" :: "n"(n) : "memory")

// ---------------------------------------------------------------------------
// converts
// ---------------------------------------------------------------------------
struct ConvJob { const float* src; __nv_bfloat16 *h, *l; int n4; };
struct ConvBatch { ConvJob j[7]; };

__global__ __launch_bounds__(256, 4)
void convert_all(ConvBatch cb)
{
    ConvJob jb = cb.j[blockIdx.z];
    int i = blockIdx.x * 256 + threadIdx.x;
    if (i >= jb.n4) return;
    float4 v = ((const float4*)jb.src)[i];
    uint2 H, L;
    H.x = pack_hi(v.x, v.y); H.y = pack_hi(v.z, v.w);
    L.x = pack_lo(v.x, v.y); L.y = pack_lo(v.z, v.w);
    ((uint2*)jb.h)[i] = H;
    ((uint2*)jb.l)[i] = L;
}

// ---------------------------------------------------------------------------
// GEMM (unchanged)
// ---------------------------------------------------------------------------
#define GROWB 80
#define GPLANE (128 * GROWB)
#define GSTAGE (4 * GPLANE)
#define GSM3 (3 * GSTAGE)

struct GemmJob {
    const __nv_bfloat16 *Ah, *Al, *Bh, *Bl;
    const float* bias;
    float* C;
    __nv_bfloat16 *Ch, *Cl;
};
struct GemmBatch { GemmJob j[3]; };

__global__ __launch_bounds__(256, 1)
void gemm_bf16(GemmBatch gb, int M, int N, int K)
{
    extern __shared__ __align__(128) char sm[];
    const uint32_t smb = smem_u32(sm);
    const GemmJob jb = gb.j[blockIdx.z];
    const int tid = threadIdx.x;
    const int wid = tid >> 5, lane = tid & 31;
    const int m0 = blockIdx.y * 128, n0 = blockIdx.x * 128;
    const int warp_m = (wid & 1) * 64;
    const int warp_n = (wid >> 1) * 32;
    const int nch = K / 32;

    const __nv_bfloat16* bases[4] = { jb.Ah, jb.Al, jb.Bh, jb.Bl };

    auto issue = [&](int ch) {
        const uint32_t sb = smb + (uint32_t)((ch % 3) * GSTAGE);
        const size_t gk = (size_t)ch * 32;
#pragma unroll
        for (int p = 0; p < 4; p++) {
            const int rbase = (p < 2) ? m0 : n0;
#pragma unroll
            for (int hh = 0; hh < 2; hh++) {
                int idx = hh * 256 + tid;
                int r = idx >> 2, c = idx & 3;
                cpa16(sb + (uint32_t)(p * GPLANE + r * 80 + c * 16),
                      bases[p] + (size_t)(rbase + r) * K + gk + c * 8);
            }
        }
    };

    float acc[4][4][4];
#pragma unroll
    for (int i = 0; i < 4; i++)
#pragma unroll
        for (int j = 0; j < 4; j++)
#pragma unroll
            for (int c = 0; c < 4; c++) acc[i][j][c] = 0.0f;

    issue(0); CP_COMMIT();
    issue(1); CP_COMMIT();

    const int arow = lane & 15;
    const int acol = (lane >> 4) * 8;
    const int bg = lane >> 3, bw = lane & 7;

    for (int ch = 0; ch < nch; ch++) {
        CP_WAITG(1);
        __syncthreads();
        if (ch + 2 < nch) issue(ch + 2);
        CP_COMMIT();

        const uint32_t sb = smb + (uint32_t)((ch % 3) * GSTAGE);
#pragma unroll
        for (int ks = 0; ks < 2; ks++) {
            const int k16 = ks * 16;
            uint32_t ah[4][4], al[4][4];
#pragma unroll
            for (int mt = 0; mt < 4; mt++) {
                uint32_t off = (uint32_t)((warp_m + mt * 16 + arow) * 80 + (k16 + acol) * 2);
                ldsm4(ah[mt], sb + 0 * GPLANE + off);
                ldsm4(al[mt], sb + 1 * GPLANE + off);
            }
            uint32_t bh[4][2], bl[4][2];
#pragma unroll
            for (int nb = 0; nb < 2; nb++) {
                uint32_t off = (uint32_t)((warp_n + nb * 16 + (bg & 1) * 8 + bw) * 80
                                          + (k16 + (bg >> 1) * 8) * 2);
                uint32_t t[4];
                ldsm4(t, sb + 2 * GPLANE + off);
                bh[nb * 2 + 0][0] = t[0]; bh[nb * 2 + 0][1] = t[2];
                bh[nb * 2 + 1][0] = t[1]; bh[nb * 2 + 1][1] = t[3];
                ldsm4(t, sb + 3 * GPLANE + off);
                bl[nb * 2 + 0][0] = t[0]; bl[nb * 2 + 0][1] = t[2];
                bl[nb * 2 + 1][0] = t[1]; bl[nb * 2 + 1][1] = t[3];
            }
#pragma unroll
            for (int mt = 0; mt < 4; mt++)
#pragma unroll
                for (int nt = 0; nt < 4; nt++) {
                    mma16816(acc[mt][nt], ah[mt], bh[nt]);
                    mma16816(acc[mt][nt], ah[mt], bl[nt]);
                    mma16816(acc[mt][nt], al[mt], bh[nt]);
                }
        }
        __syncthreads();
    }

    const int lr = lane >> 2, lc = (lane & 3) * 2;
    const bool wplanes = (jb.Ch != nullptr);
#pragma unroll
    for (int nt = 0; nt < 4; nt++) {
        int col = n0 + warp_n + nt * 8 + lc;
        float2 bv = *(const float2*)&jb.bias[col];
#pragma unroll
        for (int mt = 0; mt < 4; mt++) {
            int r0 = m0 + warp_m + mt * 16 + lr;
            float2 o0 = make_float2(acc[mt][nt][0] + bv.x, acc[mt][nt][1] + bv.y);
            float2 o1 = make_float2(acc[mt][nt][2] + bv.x, acc[mt][nt][3] + bv.y);
            *(float2*)(jb.C + (size_t)r0 * N + col) = o0;
            *(float2*)(jb.C + (size_t)(r0 + 8) * N + col) = o1;
            if (wplanes) {
                size_t i0 = (size_t)r0 * N + col;
                size_t i1 = (size_t)(r0 + 8) * N + col;
                *(uint32_t*)&jb.Ch[i0] = pack_hi(o0.x, o0.y);
                *(uint32_t*)&jb.Cl[i0] = pack_lo(o0.x, o0.y);
                *(uint32_t*)&jb.Ch[i1] = pack_hi(o1.x, o1.y);
                *(uint32_t*)&jb.Cl[i1] = pack_lo(o1.x, o1.y);
            }
        }
    }
}

// ---------------------------------------------------------------------------
// Fused attention, in-register P (FA2 fragment reuse).
// 256 threads / 8 warps; warp tile = 16 rows x 128 S-cols; ctx 16 x 64 in regs.
// smem: Q hi/lo | K stage0 hi/lo | K stage1 hi/lo | V stage0 hi/lo | V stage1 hi/lo
// ---------------------------------------------------------------------------
#define QROWB 144
#define AQH   0
#define AQL   18432
#define AKH0  36864
#define AKH1  73728
#define AVH0  110592
#define AVH1  147456
#define SM2_TOT 184320

__global__ __launch_bounds__(256, 1)
void attn_fused_mma(float* __restrict__ attn)
{
    extern __shared__ __align__(128) char sm[];
    const uint32_t smb = smem_u32(sm);
    const int tid = threadIdx.x;
    const int wid = tid >> 5, lane = tid & 31;
    const int b = blockIdx.z, h = blockIdx.y;
    const int it = (int)gridDim.x - 1 - (int)blockIdx.x;   // big tiles first
    const int r0 = it * 128;
    const int warp_m = wid * 16;             // 8 warps x 16 rows
    const int lr = lane >> 2, lc2 = (lane & 3) * 2;
    const float CE = 0.125f * 1.4426950408889634f;

    const size_t qoff = ((size_t)b * Sc + r0) * Dc + h * DPc;
    const size_t koff = (size_t)b * Sc * Dc + h * DPc;
    const size_t bh_ = (size_t)(b * Hc + h);
    float* attnp = attn + bh_ * Sc * Sc;

    auto issue_plane = [&](uint32_t dst, const __nv_bfloat16* src) {
#pragma unroll
        for (int e = 0; e < 4; e++) {
            int idx = tid + e * 256;
            int r = idx >> 3, c = idx & 7;
            cpa16(dst + (uint32_t)(r * QROWB + c * 16), src + (size_t)r * Dc + c * 8);
        }
    };
    auto issue_K = [&](int jt) {
        uint32_t dst = smb + ((jt & 1) ? AKH1 : AKH0);
        const size_t off = koff + (size_t)jt * 128 * Dc;
        issue_plane(dst, g_kh + off);
        issue_plane(dst + 18432, g_kl + off);
    };
    auto issue_V = [&](int jt) {
        uint32_t dst = smb + ((jt & 1) ? AVH1 : AVH0);
        const size_t off = koff + (size_t)jt * 128 * Dc;
        issue_plane(dst, g_vh + off);
        issue_plane(dst + 18432, g_vl + off);
    };

    // prologue: G0={Q,K0}, G1={V0}, G2={K1}
    issue_plane(smb + AQH, g_qh + qoff);
    issue_plane(smb + AQL, g_ql + qoff);
    issue_K(0);
    CP_COMMIT();
    issue_V(0);
    CP_COMMIT();
    if (it >= 1) issue_K(1);
    CP_COMMIT();

    float ctx[8][4];
#pragma unroll
    for (int d = 0; d < 8; d++)
#pragma unroll
        for (int c = 0; c < 4; c++) ctx[d][c] = 0.0f;

    float lsum0 = 0.0f, lsum1 = 0.0f;

    const int arow = lane & 15;
    const int acol = (lane >> 4) * 8;
    const int bg = lane >> 3, bw = lane & 7;
    const int growg0 = r0 + warp_m + lr;
    const int growg1 = growg0 + 8;

    for (int jt = 0; jt <= it; jt++) {
        const int j0 = jt * 128;

        CP_WAITG(2);            // K(jt) (and Q) arrived
        __syncthreads();

        const uint32_t kbase = (jt & 1) ? AKH1 : AKH0;

        float acc[16][4];
#pragma unroll
        for (int i = 0; i < 16; i++)
#pragma unroll
            for (int c = 0; c < 4; c++) acc[i][c] = 0.0f;

        // ---- S = Q K^T (3 terms), warp tile 16x128
#pragma unroll
        for (int ks = 0; ks < 4; ks++) {
            const int k16 = ks * 16;
            uint32_t ah[4], al[4];
            {
                uint32_t off = (uint32_t)((warp_m + arow) * QROWB + (k16 + acol) * 2);
                ldsm4(ah, smb + AQH + off);
                ldsm4(al, smb + AQL + off);
            }
#pragma unroll
            for (int nb = 0; nb < 8; nb++) {
                uint32_t off = (uint32_t)((nb * 16 + (bg & 1) * 8 + bw) * QROWB
                                          + (k16 + (bg >> 1) * 8) * 2);
                uint32_t t[4], bh0[2], bh1[2], bl0[2], bl1[2];
                ldsm4(t, smb + kbase + off);
                bh0[0] = t[0]; bh0[1] = t[2];
                bh1[0] = t[1]; bh1[1] = t[3];
                ldsm4(t, smb + kbase + 18432 + off);
                bl0[0] = t[0]; bl0[1] = t[2];
                bl1[0] = t[1]; bl1[1] = t[3];
                mma16816(acc[nb * 2 + 0], ah, bh0);
                mma16816(acc[nb * 2 + 0], ah, bl0);
                mma16816(acc[nb * 2 + 0], al, bh0);
                mma16816(acc[nb * 2 + 1], ah, bh1);
                mma16816(acc[nb * 2 + 1], ah, bl1);
                mma16816(acc[nb * 2 + 1], al, bh1);
            }
        }

        // ---- epilogue: exp in-register, store unnormalized attn, row sums
        const bool diag = (jt == it);
#pragma unroll
        for (int nt = 0; nt < 16; nt++) {
            const int col = j0 + nt * 8 + lc2;
            float p0 = fexp2(acc[nt][0] * CE);
            float p1 = fexp2(acc[nt][1] * CE);
            float p2 = fexp2(acc[nt][2] * CE);
            float p3 = fexp2(acc[nt][3] * CE);
            if (diag) {
                if (col + 0 > growg0) p0 = 0.0f;
                if (col + 1 > growg0) p1 = 0.0f;
                if (col + 0 > growg1) p2 = 0.0f;
                if (col + 1 > growg1) p3 = 0.0f;
            }
            *(float2*)&attnp[(size_t)growg0 * Sc + col] = make_float2(p0, p1);
            *(float2*)&attnp[(size_t)growg1 * Sc + col] = make_float2(p2, p3);
            acc[nt][0] = p0; acc[nt][1] = p1; acc[nt][2] = p2; acc[nt][3] = p3;
            lsum0 += p0 + p1;
            lsum1 += p2 + p3;
        }

        CP_WAITG(1);            // V(jt) arrived
        __syncthreads();        // V visible to all warps

        const uint32_t vbase = (jt & 1) ? AVH1 : AVH0;

        // ---- PV: ctx += P(regs, hi+lo) @ V(hi+lo) [3 terms]
#pragma unroll
        for (int ks = 0; ks < 8; ks++) {
            uint32_t aph[4], apl[4];
            aph[0] = pack_hi(acc[ks * 2 + 0][0], acc[ks * 2 + 0][1]);
            aph[1] = pack_hi(acc[ks * 2 + 0][2], acc[ks * 2 + 0][3]);
            aph[2] = pack_hi(acc[ks * 2 + 1][0], acc[ks * 2 + 1][1]);
            aph[3] = pack_hi(acc[ks * 2 + 1][2], acc[ks * 2 + 1][3]);
            apl[0] = pack_lo(acc[ks * 2 + 0][0], acc[ks * 2 + 0][1]);
            apl[1] = pack_lo(acc[ks * 2 + 0][2], acc[ks * 2 + 0][3]);
            apl[2] = pack_lo(acc[ks * 2 + 1][0], acc[ks * 2 + 1][1]);
            apl[3] = pack_lo(acc[ks * 2 + 1][2], acc[ks * 2 + 1][3]);
#pragma unroll
            for (int d16 = 0; d16 < 4; d16++) {
                uint32_t voff = (uint32_t)((ks * 16 + (lane & 15)) * QROWB
                                           + (d16 * 16 + (lane >> 4) * 8) * 2);
                uint32_t t[4], vh0[2], vh1[2], vl0[2], vl1[2];
                ldsm4t(t, smb + vbase + voff);
                vh0[0] = t[0]; vh0[1] = t[1];
                vh1[0] = t[2]; vh1[1] = t[3];
                ldsm4t(t, smb + vbase + 18432 + voff);
                vl0[0] = t[0]; vl0[1] = t[1];
                vl1[0] = t[2]; vl1[1] = t[3];
                mma16816(ctx[d16 * 2 + 0], aph, vh0);
                mma16816(ctx[d16 * 2 + 0], aph, vl0);
                mma16816(ctx[d16 * 2 + 0], apl, vh0);
                mma16816(ctx[d16 * 2 + 1], aph, vh1);
                mma16816(ctx[d16 * 2 + 1], aph, vl1);
                mma16816(ctx[d16 * 2 + 1], apl, vh1);
            }
        }

        // no sync needed: V(jt+1) goes to the other buffer; K(jt+2) overwrites
        // K(jt) which all warps finished reading before the barrier above.
        if (jt + 1 <= it) issue_V(jt + 1);
        CP_COMMIT();
        if (jt + 2 <= it) issue_K(jt + 2);
        CP_COMMIT();
    }

    // ---- row sums: 4 lanes per row (rows owned exclusively by this warp)
#pragma unroll
    for (int off = 1; off <= 2; off <<= 1) {
        lsum0 += __shfl_xor_sync(0xffffffffu, lsum0, off);
        lsum1 += __shfl_xor_sync(0xffffffffu, lsum1, off);
    }
    if ((lane & 3) == 0) {
        g_lbuf[bh_ * Sc + growg0] = lsum0;
        g_lbuf[bh_ * Sc + growg1] = lsum1;
    }
    const float inv0 = 1.0f / lsum0;
    const float inv1 = 1.0f / lsum1;

    // ---- normalized ctx -> bf16 hi/lo planes
#pragma unroll
    for (int d = 0; d < 8; d++) {
        int dcol = h * DPc + d * 8 + lc2;
        float x0 = ctx[d][0] * inv0, x1 = ctx[d][1] * inv0;
        float x2 = ctx[d][2] * inv1, x3 = ctx[d][3] * inv1;
        size_t i0 = ((size_t)b * Sc + growg0) * Dc + dcol;
        size_t i1 = ((size_t)b * Sc + growg1) * Dc + dcol;
        *(uint32_t*)&g_ch2[i0] = pack_hi(x0, x1);
        *(uint32_t*)&g_cl2[i0] = pack_lo(x0, x1);
        *(uint32_t*)&g_ch2[i1] = pack_hi(x2, x3);
        *(uint32_t*)&g_cl2[i1] = pack_lo(x2, x3);
    }
}

// ---------------------------------------------------------------------------
__global__ __launch_bounds__(512, 2)
void fill_upper(float* __restrict__ attn)
{
    const int b = blockIdx.z, h = blockIdx.y, it = blockIdx.x;
    const int ncol4 = 512 - (it + 1) * 32;
    if (ncol4 <= 0) return;
    const int c0 = (it + 1) * 32;
    float* ap = attn + ((size_t)(b * Hc + h)) * Sc * Sc + (size_t)it * 128 * Sc;
    const float4 z = make_float4(0.f, 0.f, 0.f, 0.f);
    const int tid = threadIdx.x;
    const int total = 128 * ncol4;
    for (int i = tid; i < total; i += 512) {
        int r = i / ncol4, c = i - r * ncol4;
        ((float4*)&ap[(size_t)r * Sc])[c0 + c] = z;
    }
}

__global__ __launch_bounds__(512, 2)
void norm_lower(float* __restrict__ attn)
{
    const int b = blockIdx.z, h = blockIdx.y, it = blockIdx.x;
    const int r0 = it * 128;
    const int tid = threadIdx.x;
    const size_t bh_ = (size_t)(b * Hc + h);
    float* ap = attn + bh_ * Sc * Sc;

    __shared__ float inv[128];
    if (tid < 128) inv[tid] = 1.0f / g_lbuf[bh_ * Sc + r0 + tid];
    __syncthreads();

    const int ncol4 = (it + 1) * 32;
    for (int r = tid >> 7; r < 128; r += 4) {
        const float s = inv[r];
        float4* rowp = (float4*)&ap[(size_t)(r0 + r) * Sc];
#pragma unroll 4
        for (int c4 = (tid & 127); c4 < ncol4; c4 += 128) {
            float4 v = rowp[c4];
            v.x *= s; v.y *= s; v.z *= s; v.w *= s;
            rowp[c4] = v;
        }
    }
}

// ---------------------------------------------------------------------------
extern "C" void kernel_launch(void* const* d_in, const int* in_sizes, int n_in,
                              void* d_out, int out_size)
{
    (void)in_sizes; (void)n_in; (void)out_size;
    const float* Q   = (const float*)d_in[0];
    const float* Kin = (const float*)d_in[1];
    const float* Vin = (const float*)d_in[2];
    const float* Wq = (const float*)d_in[4];
    const float* bq = (const float*)d_in[5];
    const float* Wk = (const float*)d_in[6];
    const float* bk = (const float*)d_in[7];
    const float* Wv = (const float*)d_in[8];
    const float* bv = (const float*)d_in[9];
    const float* Wo = (const float*)d_in[10];
    const float* bo = (const float*)d_in[11];

    float* out  = (float*)d_out;
    float* attn = out + SZ_QKV;
    float* qo   = attn + SZ_ATTN;
    float* ko   = qo + SZ_QKV;
    float* vo   = ko + SZ_QKV;

    void *iah, *ial, *wh, *wl, *qh, *ql, *kh, *kl, *vh, *vl, *ch2, *cl2;
    cudaGetSymbolAddress(&iah, g_iah);  cudaGetSymbolAddress(&ial, g_ial);
    cudaGetSymbolAddress(&wh, g_wh);    cudaGetSymbolAddress(&wl, g_wl);
    cudaGetSymbolAddress(&qh, g_qh);    cudaGetSymbolAddress(&ql, g_ql);
    cudaGetSymbolAddress(&kh, g_kh);    cudaGetSymbolAddress(&kl, g_kl);
    cudaGetSymbolAddress(&vh, g_vh);    cudaGetSymbolAddress(&vl, g_vl);
    cudaGetSymbolAddress(&ch2, g_ch2);  cudaGetSymbolAddress(&cl2, g_cl2);
    __nv_bfloat16 *IAH = (__nv_bfloat16*)iah, *IAL = (__nv_bfloat16*)ial;
    __nv_bfloat16 *WH  = (__nv_bfloat16*)wh,  *WL  = (__nv_bfloat16*)wl;

    cudaFuncSetAttribute(gemm_bf16,
                         cudaFuncAttributeMaxDynamicSharedMemorySize, GSM3);
    cudaFuncSetAttribute(attn_fused_mma,
                         cudaFuncAttributeMaxDynamicSharedMemorySize, SM2_TOT);

    const int M = Bc * Sc;

    cudaStream_t s1;
    cudaStreamCreateWithFlags(&s1, cudaStreamNonBlocking);
    cudaEvent_t e0, e1, e2;
    cudaEventCreateWithFlags(&e0, cudaEventDisableTiming);
    cudaEventCreateWithFlags(&e1, cudaEventDisableTiming);
    cudaEventCreateWithFlags(&e2, cudaEventDisableTiming);

    dim3 agrid(Sc / 128, Hc, Bc);

    // fork EARLY: fill_upper has no deps — overlaps converts + QKV gemm
    cudaEventRecord(e0, 0);
    cudaStreamWaitEvent(s1, e0, 0);
    fill_upper<<<agrid, 512, 0, s1>>>(attn);

    // 1) converts
    ConvBatch cb;
    const float* srcs[7] = { Q, Kin, Vin, Wq, Wk, Wv, Wo };
    for (int z = 0; z < 7; z++) {
        cb.j[z].src = srcs[z];
        if (z < 3) {
            cb.j[z].h = IAH + (size_t)z * MD;
            cb.j[z].l = IAL + (size_t)z * MD;
            cb.j[z].n4 = (int)(MD / 4);
        } else {
            cb.j[z].h = WH + (size_t)(z - 3) * DD;
            cb.j[z].l = WL + (size_t)(z - 3) * DD;
            cb.j[z].n4 = (int)(DD / 4);
        }
    }
    dim3 cgrid((unsigned)((MD / 4 + 255) / 256), 1, 7);
    convert_all<<<cgrid, 256>>>(cb);

    // 2) QKV projections
    GemmBatch qb;
    const float* biases[3] = { bq, bk, bv };
    float* outs[3] = { qo, ko, vo };
    __nv_bfloat16* chp[3] = { (__nv_bfloat16*)qh, (__nv_bfloat16*)kh, (__nv_bfloat16*)vh };
    __nv_bfloat16* clp[3] = { (__nv_bfloat16*)ql, (__nv_bfloat16*)kl, (__nv_bfloat16*)vl };
    for (int z = 0; z < 3; z++) {
        qb.j[z].Ah = IAH + (size_t)z * MD; qb.j[z].Al = IAL + (size_t)z * MD;
        qb.j[z].Bh = WH + (size_t)z * DD;  qb.j[z].Bl = WL + (size_t)z * DD;
        qb.j[z].bias = biases[z]; qb.j[z].C = outs[z];
        qb.j[z].Ch = chp[z]; qb.j[z].Cl = clp[z];
    }
    dim3 qgrid(Dc / 128, M / 128, 3);
    gemm_bf16<<<qgrid, 256, GSM3>>>(qb, M, Dc, Dc);

    // 3) attention (256 threads, in-register P)
    attn_fused_mma<<<agrid, 256, SM2_TOT>>>(attn);
    cudaEventRecord(e1, 0);

    cudaStreamWaitEvent(s1, e1, 0);
    norm_lower<<<agrid, 512, 0, s1>>>(attn);
    cudaEventRecord(e2, s1);

    // 4) O projection (overlaps norm_lower)
    GemmBatch ob;
    ob.j[0].Ah = (__nv_bfloat16*)ch2; ob.j[0].Al = (__nv_bfloat16*)cl2;
    ob.j[0].Bh = WH + 3 * DD;         ob.j[0].Bl = WL + 3 * DD;
    ob.j[0].bias = bo; ob.j[0].C = out;
    ob.j[0].Ch = nullptr; ob.j[0].Cl = nullptr;
    ob.j[1] = ob.j[0]; ob.j[2] = ob.j[0];
    dim3 ogrid(Dc / 128, M / 128, 1);
    gemm_bf16<<<ogrid, 256, GSM3>>>(ob, M, Dc, Dc);

    cudaStreamWaitEvent(0, e2, 0);
}

// round 13
// speedup vs baseline: 1.2679x; 1.0122x over previous
#include <cuda_runtime.h>
#include <cuda_bf16.h>
#include <math.h>
#include <stdint.h>

#define Bc 2
#define Sc 2048
#define Dc 1024
#define Hc 16
#define DPc 64

static const size_t SZ_QKV  = (size_t)Bc * Sc * Dc;        // 4194304
static const size_t SZ_ATTN = (size_t)Bc * Hc * Sc * Sc;   // 134217728
#define MD  ((size_t)4194304)
#define DD  ((size_t)1048576)

__device__ __nv_bfloat16 g_iah[3 * MD], g_ial[3 * MD];
__device__ __nv_bfloat16 g_wh[4 * DD],  g_wl[4 * DD];
__device__ __nv_bfloat16 g_qh[MD], g_ql[MD];
__device__ __nv_bfloat16 g_kh[MD], g_kl[MD];
__device__ __nv_bfloat16 g_vh[MD], g_vl[MD];
__device__ __nv_bfloat16 g_ch2[MD], g_cl2[MD];
__device__ float g_lbuf[(size_t)Bc * Hc * Sc];

// ---------------------------------------------------------------------------
__device__ __forceinline__ uint32_t smem_u32(const void* p) {
    uint32_t a;
    asm("{ .reg .u64 t; cvta.to.shared.u64 t, %1; cvt.u32.u64 %0, t; }"
        : "=r"(a) : "l"(p));
    return a;
}
__device__ __forceinline__ void mma16816(float* d, const uint32_t* a, const uint32_t* b) {
    asm volatile(
        "mma.sync.aligned.m16n8k16.row.col.f32.bf16.bf16.f32 "
        "{%0,%1,%2,%3}, {%4,%5,%6,%7}, {%8,%9}, {%0,%1,%2,%3};"
        : "+f"(d[0]), "+f"(d[1]), "+f"(d[2]), "+f"(d[3])
        : "r"(a[0]), "r"(a[1]), "r"(a[2]), "r"(a[3]), "r"(b[0]), "r"(b[1]));
}
__device__ __forceinline__ void ldsm4(uint32_t* r, uint32_t addr) {
    asm volatile("ldmatrix.sync.aligned.m8n8.x4.shared.b16 {%0,%1,%2,%3}, [%4];"
                 : "=r"(r[0]), "=r"(r[1]), "=r"(r[2]), "=r"(r[3]) : "r"(addr));
}
__device__ __forceinline__ void ldsm4t(uint32_t* r, uint32_t addr) {
    asm volatile("ldmatrix.sync.aligned.m8n8.x4.trans.shared.b16 {%0,%1,%2,%3}, [%4];"
                 : "=r"(r[0]), "=r"(r[1]), "=r"(r[2]), "=r"(r[3]) : "r"(addr));
}
__device__ __forceinline__ float fexp2(float x) {
    float r;
    asm("ex2.approx.f32 %0, %1;" : "=f"(r) : "f"(x));
    return r;
}
__device__ __forceinline__ uint32_t pack_hi(float x, float y) {
    __nv_bfloat162 h = __float22bfloat162_rn(make_float2(x, y));
    return *(uint32_t*)&h;
}
__device__ __forceinline__ uint32_t pack_lo(float x, float y) {
    __nv_bfloat16 hx = __float2bfloat16(x), hy = __float2bfloat16(y);
    __nv_bfloat162 l = __float22bfloat162_rn(
        make_float2(x - __bfloat162float(hx), y - __bfloat162float(hy)));
    return *(uint32_t*)&l;
}
__device__ __forceinline__ void cpa16(uint32_t s, const void* g) {
    asm volatile("cp.async.cg.shared.global [%0], [%1], 16;" :: "r"(s), "l"(g));
}
#define CP_COMMIT()  asm volatile("cp.async.commit_group;" ::: "memory")
#define CP_WAITG(n)  asm volatile("cp.async.wait_group %0;" :: "n"(n) : "memory")

// ---------------------------------------------------------------------------
// converts
// ---------------------------------------------------------------------------
struct ConvJob { const float* src; __nv_bfloat16 *h, *l; int n4; };
struct ConvBatch { ConvJob j[7]; };

__global__ __launch_bounds__(256, 4)
void convert_all(ConvBatch cb)
{
    ConvJob jb = cb.j[blockIdx.z];
    int i = blockIdx.x * 256 + threadIdx.x;
    if (i >= jb.n4) return;
    float4 v = ((const float4*)jb.src)[i];
    uint2 H, L;
    H.x = pack_hi(v.x, v.y); H.y = pack_hi(v.z, v.w);
    L.x = pack_lo(v.x, v.y); L.y = pack_lo(v.z, v.w);
    ((uint2*)jb.h)[i] = H;
    ((uint2*)jb.l)[i] = L;
}

// ---------------------------------------------------------------------------
// GEMM v2: 512 threads / 16 warps, warp tile 32x32, K-chunk 64, 3-stage ring.
// smem plane: 128 rows x 144 B (64 bf16 + 16B pad); 4 planes/stage; 3 stages.
// ---------------------------------------------------------------------------
#define G2ROWB 144
#define G2PLANE (128 * G2ROWB)    // 18432
#define G2STAGE (4 * G2PLANE)     // 73728
#define G2SM   (3 * G2STAGE)      // 221184

struct GemmJob {
    const __nv_bfloat16 *Ah, *Al, *Bh, *Bl;
    const float* bias;
    float* C;
    __nv_bfloat16 *Ch, *Cl;
};
struct GemmBatch { GemmJob j[3]; };

__global__ __launch_bounds__(512, 1)
void gemm_bf16(GemmBatch gb, int M, int N, int K)
{
    extern __shared__ __align__(128) char sm[];
    const uint32_t smb = smem_u32(sm);
    const GemmJob jb = gb.j[blockIdx.z];
    const int tid = threadIdx.x;
    const int wid = tid >> 5, lane = tid & 31;
    const int m0 = blockIdx.y * 128, n0 = blockIdx.x * 128;
    const int warp_m = (wid & 3) * 32;
    const int warp_n = (wid >> 2) * 32;
    const int nch = K / 64;           // 16

    const __nv_bfloat16* bases[4] = { jb.Ah, jb.Al, jb.Bh, jb.Bl };

    auto issue = [&](int ch) {
        const uint32_t sb = smb + (uint32_t)((ch % 3) * G2STAGE);
        const size_t gk = (size_t)ch * 64;
#pragma unroll
        for (int p = 0; p < 4; p++) {
            const int rbase = (p < 2) ? m0 : n0;
#pragma unroll
            for (int e = 0; e < 2; e++) {
                int idx = tid + e * 512;       // 0..1023
                int r = idx >> 3, c = idx & 7; // 128 rows x 8 x 16B
                cpa16(sb + (uint32_t)(p * G2PLANE + r * G2ROWB + c * 16),
                      bases[p] + (size_t)(rbase + r) * K + gk + c * 8);
            }
        }
    };

    float acc[2][4][4];
#pragma unroll
    for (int i = 0; i < 2; i++)
#pragma unroll
        for (int j = 0; j < 4; j++)
#pragma unroll
            for (int c = 0; c < 4; c++) acc[i][j][c] = 0.0f;

    issue(0); CP_COMMIT();
    issue(1); CP_COMMIT();

    const int arow = lane & 15;
    const int acol = (lane >> 4) * 8;
    const int bg = lane >> 3, bw = lane & 7;

    for (int ch = 0; ch < nch; ch++) {
        CP_WAITG(1);
        __syncthreads();
        if (ch + 2 < nch) issue(ch + 2);
        CP_COMMIT();

        const uint32_t sb = smb + (uint32_t)((ch % 3) * G2STAGE);
#pragma unroll
        for (int ks = 0; ks < 4; ks++) {
            const int k16 = ks * 16;
            uint32_t ah[2][4], al[2][4];
#pragma unroll
            for (int mt = 0; mt < 2; mt++) {
                uint32_t off = (uint32_t)((warp_m + mt * 16 + arow) * G2ROWB
                                          + (k16 + acol) * 2);
                ldsm4(ah[mt], sb + 0 * G2PLANE + off);
                ldsm4(al[mt], sb + 1 * G2PLANE + off);
            }
            uint32_t bh[4][2], bl[4][2];
#pragma unroll
            for (int nb = 0; nb < 2; nb++) {
                uint32_t off = (uint32_t)((warp_n + nb * 16 + (bg & 1) * 8 + bw) * G2ROWB
                                          + (k16 + (bg >> 1) * 8) * 2);
                uint32_t t[4];
                ldsm4(t, sb + 2 * G2PLANE + off);
                bh[nb * 2 + 0][0] = t[0]; bh[nb * 2 + 0][1] = t[2];
                bh[nb * 2 + 1][0] = t[1]; bh[nb * 2 + 1][1] = t[3];
                ldsm4(t, sb + 3 * G2PLANE + off);
                bl[nb * 2 + 0][0] = t[0]; bl[nb * 2 + 0][1] = t[2];
                bl[nb * 2 + 1][0] = t[1]; bl[nb * 2 + 1][1] = t[3];
            }
#pragma unroll
            for (int mt = 0; mt < 2; mt++)
#pragma unroll
                for (int nt = 0; nt < 4; nt++) {
                    mma16816(acc[mt][nt], ah[mt], bh[nt]);
                    mma16816(acc[mt][nt], ah[mt], bl[nt]);
                    mma16816(acc[mt][nt], al[mt], bh[nt]);
                }
        }
        __syncthreads();
    }

    const int lr = lane >> 2, lc = (lane & 3) * 2;
    const bool wplanes = (jb.Ch != nullptr);
#pragma unroll
    for (int nt = 0; nt < 4; nt++) {
        int col = n0 + warp_n + nt * 8 + lc;
        float2 bv = *(const float2*)&jb.bias[col];
#pragma unroll
        for (int mt = 0; mt < 2; mt++) {
            int r0 = m0 + warp_m + mt * 16 + lr;
            float2 o0 = make_float2(acc[mt][nt][0] + bv.x, acc[mt][nt][1] + bv.y);
            float2 o1 = make_float2(acc[mt][nt][2] + bv.x, acc[mt][nt][3] + bv.y);
            *(float2*)(jb.C + (size_t)r0 * N + col) = o0;
            *(float2*)(jb.C + (size_t)(r0 + 8) * N + col) = o1;
            if (wplanes) {
                size_t i0 = (size_t)r0 * N + col;
                size_t i1 = (size_t)(r0 + 8) * N + col;
                *(uint32_t*)&jb.Ch[i0] = pack_hi(o0.x, o0.y);
                *(uint32_t*)&jb.Cl[i0] = pack_lo(o0.x, o0.y);
                *(uint32_t*)&jb.Ch[i1] = pack_hi(o1.x, o1.y);
                *(uint32_t*)&jb.Cl[i1] = pack_lo(o1.x, o1.y);
            }
        }
    }
}

// ---------------------------------------------------------------------------
// Fused attention (unchanged from R12): in-register P, 8 warps x 16 rows.
// ---------------------------------------------------------------------------
#define QROWB 144
#define AQH   0
#define AQL   18432
#define AKH0  36864
#define AKH1  73728
#define AVH0  110592
#define AVH1  147456
#define SM2_TOT 184320

__global__ __launch_bounds__(256, 1)
void attn_fused_mma(float* __restrict__ attn)
{
    extern __shared__ __align__(128) char sm[];
    const uint32_t smb = smem_u32(sm);
    const int tid = threadIdx.x;
    const int wid = tid >> 5, lane = tid & 31;
    const int b = blockIdx.z, h = blockIdx.y;
    const int it = (int)gridDim.x - 1 - (int)blockIdx.x;
    const int r0 = it * 128;
    const int warp_m = wid * 16;
    const int lr = lane >> 2, lc2 = (lane & 3) * 2;
    const float CE = 0.125f * 1.4426950408889634f;

    const size_t qoff = ((size_t)b * Sc + r0) * Dc + h * DPc;
    const size_t koff = (size_t)b * Sc * Dc + h * DPc;
    const size_t bh_ = (size_t)(b * Hc + h);
    float* attnp = attn + bh_ * Sc * Sc;

    auto issue_plane = [&](uint32_t dst, const __nv_bfloat16* src) {
#pragma unroll
        for (int e = 0; e < 4; e++) {
            int idx = tid + e * 256;
            int r = idx >> 3, c = idx & 7;
            cpa16(dst + (uint32_t)(r * QROWB + c * 16), src + (size_t)r * Dc + c * 8);
        }
    };
    auto issue_K = [&](int jt) {
        uint32_t dst = smb + ((jt & 1) ? AKH1 : AKH0);
        const size_t off = koff + (size_t)jt * 128 * Dc;
        issue_plane(dst, g_kh + off);
        issue_plane(dst + 18432, g_kl + off);
    };
    auto issue_V = [&](int jt) {
        uint32_t dst = smb + ((jt & 1) ? AVH1 : AVH0);
        const size_t off = koff + (size_t)jt * 128 * Dc;
        issue_plane(dst, g_vh + off);
        issue_plane(dst + 18432, g_vl + off);
    };

    issue_plane(smb + AQH, g_qh + qoff);
    issue_plane(smb + AQL, g_ql + qoff);
    issue_K(0);
    CP_COMMIT();
    issue_V(0);
    CP_COMMIT();
    if (it >= 1) issue_K(1);
    CP_COMMIT();

    float ctx[8][4];
#pragma unroll
    for (int d = 0; d < 8; d++)
#pragma unroll
        for (int c = 0; c < 4; c++) ctx[d][c] = 0.0f;

    float lsum0 = 0.0f, lsum1 = 0.0f;

    const int arow = lane & 15;
    const int acol = (lane >> 4) * 8;
    const int bg = lane >> 3, bw = lane & 7;
    const int growg0 = r0 + warp_m + lr;
    const int growg1 = growg0 + 8;

    for (int jt = 0; jt <= it; jt++) {
        const int j0 = jt * 128;

        CP_WAITG(2);
        __syncthreads();

        const uint32_t kbase = (jt & 1) ? AKH1 : AKH0;

        float acc[16][4];
#pragma unroll
        for (int i = 0; i < 16; i++)
#pragma unroll
            for (int c = 0; c < 4; c++) acc[i][c] = 0.0f;

#pragma unroll
        for (int ks = 0; ks < 4; ks++) {
            const int k16 = ks * 16;
            uint32_t ah[4], al[4];
            {
                uint32_t off = (uint32_t)((warp_m + arow) * QROWB + (k16 + acol) * 2);
                ldsm4(ah, smb + AQH + off);
                ldsm4(al, smb + AQL + off);
            }
#pragma unroll
            for (int nb = 0; nb < 8; nb++) {
                uint32_t off = (uint32_t)((nb * 16 + (bg & 1) * 8 + bw) * QROWB
                                          + (k16 + (bg >> 1) * 8) * 2);
                uint32_t t[4], bh0[2], bh1[2], bl0[2], bl1[2];
                ldsm4(t, smb + kbase + off);
                bh0[0] = t[0]; bh0[1] = t[2];
                bh1[0] = t[1]; bh1[1] = t[3];
                ldsm4(t, smb + kbase + 18432 + off);
                bl0[0] = t[0]; bl0[1] = t[2];
                bl1[0] = t[1]; bl1[1] = t[3];
                mma16816(acc[nb * 2 + 0], ah, bh0);
                mma16816(acc[nb * 2 + 0], ah, bl0);
                mma16816(acc[nb * 2 + 0], al, bh0);
                mma16816(acc[nb * 2 + 1], ah, bh1);
                mma16816(acc[nb * 2 + 1], ah, bl1);
                mma16816(acc[nb * 2 + 1], al, bh1);
            }
        }

        const bool diag = (jt == it);
#pragma unroll
        for (int nt = 0; nt < 16; nt++) {
            const int col = j0 + nt * 8 + lc2;
            float p0 = fexp2(acc[nt][0] * CE);
            float p1 = fexp2(acc[nt][1] * CE);
            float p2 = fexp2(acc[nt][2] * CE);
            float p3 = fexp2(acc[nt][3] * CE);
            if (diag) {
                if (col + 0 > growg0) p0 = 0.0f;
                if (col + 1 > growg0) p1 = 0.0f;
                if (col + 0 > growg1) p2 = 0.0f;
                if (col + 1 > growg1) p3 = 0.0f;
            }
            *(float2*)&attnp[(size_t)growg0 * Sc + col] = make_float2(p0, p1);
            *(float2*)&attnp[(size_t)growg1 * Sc + col] = make_float2(p2, p3);
            acc[nt][0] = p0; acc[nt][1] = p1; acc[nt][2] = p2; acc[nt][3] = p3;
            lsum0 += p0 + p1;
            lsum1 += p2 + p3;
        }

        CP_WAITG(1);
        __syncthreads();

        const uint32_t vbase = (jt & 1) ? AVH1 : AVH0;

#pragma unroll
        for (int ks = 0; ks < 8; ks++) {
            uint32_t aph[4], apl[4];
            aph[0] = pack_hi(acc[ks * 2 + 0][0], acc[ks * 2 + 0][1]);
            aph[1] = pack_hi(acc[ks * 2 + 0][2], acc[ks * 2 + 0][3]);
            aph[2] = pack_hi(acc[ks * 2 + 1][0], acc[ks * 2 + 1][1]);
            aph[3] = pack_hi(acc[ks * 2 + 1][2], acc[ks * 2 + 1][3]);
            apl[0] = pack_lo(acc[ks * 2 + 0][0], acc[ks * 2 + 0][1]);
            apl[1] = pack_lo(acc[ks * 2 + 0][2], acc[ks * 2 + 0][3]);
            apl[2] = pack_lo(acc[ks * 2 + 1][0], acc[ks * 2 + 1][1]);
            apl[3] = pack_lo(acc[ks * 2 + 1][2], acc[ks * 2 + 1][3]);
#pragma unroll
            for (int d16 = 0; d16 < 4; d16++) {
                uint32_t voff = (uint32_t)((ks * 16 + (lane & 15)) * QROWB
                                           + (d16 * 16 + (lane >> 4) * 8) * 2);
                uint32_t t[4], vh0[2], vh1[2], vl0[2], vl1[2];
                ldsm4t(t, smb + vbase + voff);
                vh0[0] = t[0]; vh0[1] = t[1];
                vh1[0] = t[2]; vh1[1] = t[3];
                ldsm4t(t, smb + vbase + 18432 + voff);
                vl0[0] = t[0]; vl0[1] = t[1];
                vl1[0] = t[2]; vl1[1] = t[3];
                mma16816(ctx[d16 * 2 + 0], aph, vh0);
                mma16816(ctx[d16 * 2 + 0], aph, vl0);
                mma16816(ctx[d16 * 2 + 0], apl, vh0);
                mma16816(ctx[d16 * 2 + 1], aph, vh1);
                mma16816(ctx[d16 * 2 + 1], aph, vl1);
                mma16816(ctx[d16 * 2 + 1], apl, vh1);
            }
        }

        if (jt + 1 <= it) issue_V(jt + 1);
        CP_COMMIT();
        if (jt + 2 <= it) issue_K(jt + 2);
        CP_COMMIT();
    }

#pragma unroll
    for (int off = 1; off <= 2; off <<= 1) {
        lsum0 += __shfl_xor_sync(0xffffffffu, lsum0, off);
        lsum1 += __shfl_xor_sync(0xffffffffu, lsum1, off);
    }
    if ((lane & 3) == 0) {
        g_lbuf[bh_ * Sc + growg0] = lsum0;
        g_lbuf[bh_ * Sc + growg1] = lsum1;
    }
    const float inv0 = 1.0f / lsum0;
    const float inv1 = 1.0f / lsum1;

#pragma unroll
    for (int d = 0; d < 8; d++) {
        int dcol = h * DPc + d * 8 + lc2;
        float x0 = ctx[d][0] * inv0, x1 = ctx[d][1] * inv0;
        float x2 = ctx[d][2] * inv1, x3 = ctx[d][3] * inv1;
        size_t i0 = ((size_t)b * Sc + growg0) * Dc + dcol;
        size_t i1 = ((size_t)b * Sc + growg1) * Dc + dcol;
        *(uint32_t*)&g_ch2[i0] = pack_hi(x0, x1);
        *(uint32_t*)&g_cl2[i0] = pack_lo(x0, x1);
        *(uint32_t*)&g_ch2[i1] = pack_hi(x2, x3);
        *(uint32_t*)&g_cl2[i1] = pack_lo(x2, x3);
    }
}

// ---------------------------------------------------------------------------
__global__ __launch_bounds__(512, 2)
void fill_upper(float* __restrict__ attn)
{
    const int b = blockIdx.z, h = blockIdx.y, it = blockIdx.x;
    const int ncol4 = 512 - (it + 1) * 32;
    if (ncol4 <= 0) return;
    const int c0 = (it + 1) * 32;
    float* ap = attn + ((size_t)(b * Hc + h)) * Sc * Sc + (size_t)it * 128 * Sc;
    const float4 z = make_float4(0.f, 0.f, 0.f, 0.f);
    const int tid = threadIdx.x;
    const int total = 128 * ncol4;
    for (int i = tid; i < total; i += 512) {
        int r = i / ncol4, c = i - r * ncol4;
        ((float4*)&ap[(size_t)r * Sc])[c0 + c] = z;
    }
}

__global__ __launch_bounds__(512, 2)
void norm_lower(float* __restrict__ attn)
{
    const int b = blockIdx.z, h = blockIdx.y, it = blockIdx.x;
    const int r0 = it * 128;
    const int tid = threadIdx.x;
    const size_t bh_ = (size_t)(b * Hc + h);
    float* ap = attn + bh_ * Sc * Sc;

    __shared__ float inv[128];
    if (tid < 128) inv[tid] = 1.0f / g_lbuf[bh_ * Sc + r0 + tid];
    __syncthreads();

    const int ncol4 = (it + 1) * 32;
    for (int r = tid >> 7; r < 128; r += 4) {
        const float s = inv[r];
        float4* rowp = (float4*)&ap[(size_t)(r0 + r) * Sc];
#pragma unroll 4
        for (int c4 = (tid & 127); c4 < ncol4; c4 += 128) {
            float4 v = rowp[c4];
            v.x *= s; v.y *= s; v.z *= s; v.w *= s;
            rowp[c4] = v;
        }
    }
}

// ---------------------------------------------------------------------------
extern "C" void kernel_launch(void* const* d_in, const int* in_sizes, int n_in,
                              void* d_out, int out_size)
{
    (void)in_sizes; (void)n_in; (void)out_size;
    const float* Q   = (const float*)d_in[0];
    const float* Kin = (const float*)d_in[1];
    const float* Vin = (const float*)d_in[2];
    const float* Wq = (const float*)d_in[4];
    const float* bq = (const float*)d_in[5];
    const float* Wk = (const float*)d_in[6];
    const float* bk = (const float*)d_in[7];
    const float* Wv = (const float*)d_in[8];
    const float* bv = (const float*)d_in[9];
    const float* Wo = (const float*)d_in[10];
    const float* bo = (const float*)d_in[11];

    float* out  = (float*)d_out;
    float* attn = out + SZ_QKV;
    float* qo   = attn + SZ_ATTN;
    float* ko   = qo + SZ_QKV;
    float* vo   = ko + SZ_QKV;

    void *iah, *ial, *wh, *wl, *qh, *ql, *kh, *kl, *vh, *vl, *ch2, *cl2;
    cudaGetSymbolAddress(&iah, g_iah);  cudaGetSymbolAddress(&ial, g_ial);
    cudaGetSymbolAddress(&wh, g_wh);    cudaGetSymbolAddress(&wl, g_wl);
    cudaGetSymbolAddress(&qh, g_qh);    cudaGetSymbolAddress(&ql, g_ql);
    cudaGetSymbolAddress(&kh, g_kh);    cudaGetSymbolAddress(&kl, g_kl);
    cudaGetSymbolAddress(&vh, g_vh);    cudaGetSymbolAddress(&vl, g_vl);
    cudaGetSymbolAddress(&ch2, g_ch2);  cudaGetSymbolAddress(&cl2, g_cl2);
    __nv_bfloat16 *IAH = (__nv_bfloat16*)iah, *IAL = (__nv_bfloat16*)ial;
    __nv_bfloat16 *WH  = (__nv_bfloat16*)wh,  *WL  = (__nv_bfloat16*)wl;

    cudaFuncSetAttribute(gemm_bf16,
                         cudaFuncAttributeMaxDynamicSharedMemorySize, G2SM);
    cudaFuncSetAttribute(attn_fused_mma,
                         cudaFuncAttributeMaxDynamicSharedMemorySize, SM2_TOT);

    const int M = Bc * Sc;

    cudaStream_t s1;
    cudaStreamCreateWithFlags(&s1, cudaStreamNonBlocking);
    cudaEvent_t e0, e1, e2;
    cudaEventCreateWithFlags(&e0, cudaEventDisableTiming);
    cudaEventCreateWithFlags(&e1, cudaEventDisableTiming);
    cudaEventCreateWithFlags(&e2, cudaEventDisableTiming);

    dim3 agrid(Sc / 128, Hc, Bc);

    // fork EARLY: fill_upper has no deps — overlaps converts + QKV gemm
    cudaEventRecord(e0, 0);
    cudaStreamWaitEvent(s1, e0, 0);
    fill_upper<<<agrid, 512, 0, s1>>>(attn);

    // 1) converts
    ConvBatch cb;
    const float* srcs[7] = { Q, Kin, Vin, Wq, Wk, Wv, Wo };
    for (int z = 0; z < 7; z++) {
        cb.j[z].src = srcs[z];
        if (z < 3) {
            cb.j[z].h = IAH + (size_t)z * MD;
            cb.j[z].l = IAL + (size_t)z * MD;
            cb.j[z].n4 = (int)(MD / 4);
        } else {
            cb.j[z].h = WH + (size_t)(z - 3) * DD;
            cb.j[z].l = WL + (size_t)(z - 3) * DD;
            cb.j[z].n4 = (int)(DD / 4);
        }
    }
    dim3 cgrid((unsigned)((MD / 4 + 255) / 256), 1, 7);
    convert_all<<<cgrid, 256>>>(cb);

    // 2) QKV projections (512-thread GEMM v2)
    GemmBatch qb;
    const float* biases[3] = { bq, bk, bv };
    float* outs[3] = { qo, ko, vo };
    __nv_bfloat16* chp[3] = { (__nv_bfloat16*)qh, (__nv_bfloat16*)kh, (__nv_bfloat16*)vh };
    __nv_bfloat16* clp[3] = { (__nv_bfloat16*)ql, (__nv_bfloat16*)kl, (__nv_bfloat16*)vl };
    for (int z = 0; z < 3; z++) {
        qb.j[z].Ah = IAH + (size_t)z * MD; qb.j[z].Al = IAL + (size_t)z * MD;
        qb.j[z].Bh = WH + (size_t)z * DD;  qb.j[z].Bl = WL + (size_t)z * DD;
        qb.j[z].bias = biases[z]; qb.j[z].C = outs[z];
        qb.j[z].Ch = chp[z]; qb.j[z].Cl = clp[z];
    }
    dim3 qgrid(Dc / 128, M / 128, 3);
    gemm_bf16<<<qgrid, 512, G2SM>>>(qb, M, Dc, Dc);

    // 3) attention
    attn_fused_mma<<<agrid, 256, SM2_TOT>>>(attn);
    cudaEventRecord(e1, 0);

    cudaStreamWaitEvent(s1, e1, 0);
    norm_lower<<<agrid, 512, 0, s1>>>(attn);
    cudaEventRecord(e2, s1);

    // 4) O projection (overlaps norm_lower)
    GemmBatch ob;
    ob.j[0].Ah = (__nv_bfloat16*)ch2; ob.j[0].Al = (__nv_bfloat16*)cl2;
    ob.j[0].Bh = WH + 3 * DD;         ob.j[0].Bl = WL + 3 * DD;
    ob.j[0].bias = bo; ob.j[0].C = out;
    ob.j[0].Ch = nullptr; ob.j[0].Cl = nullptr;
    ob.j[1] = ob.j[0]; ob.j[2] = ob.j[0];
    dim3 ogrid(Dc / 128, M / 128, 1);
    gemm_bf16<<<ogrid, 512, G2SM>>>(ob, M, Dc, Dc);

    cudaStreamWaitEvent(0, e2, 0);
}

// round 14
// speedup vs baseline: 1.2742x; 1.0049x over previous
#include <cuda_runtime.h>
#include <cuda_bf16.h>
#include <math.h>
#include <stdint.h>

#define Bc 2
#define Sc 2048
#define Dc 1024
#define Hc 16
#define DPc 64

static const size_t SZ_QKV  = (size_t)Bc * Sc * Dc;        // 4194304
static const size_t SZ_ATTN = (size_t)Bc * Hc * Sc * Sc;   // 134217728
#define MD  ((size_t)4194304)
#define DD  ((size_t)1048576)

__device__ __nv_bfloat16 g_iah[3 * MD], g_ial[3 * MD];
__device__ __nv_bfloat16 g_wh[4 * DD],  g_wl[4 * DD];
__device__ __nv_bfloat16 g_qh[MD], g_ql[MD];
__device__ __nv_bfloat16 g_kh[MD], g_kl[MD];
__device__ __nv_bfloat16 g_vh[MD], g_vl[MD];
__device__ __nv_bfloat16 g_ch2[MD], g_cl2[MD];
__device__ float g_lbuf[(size_t)Bc * Hc * Sc];

// ---------------------------------------------------------------------------
__device__ __forceinline__ uint32_t smem_u32(const void* p) {
    uint32_t a;
    asm("{ .reg .u64 t; cvta.to.shared.u64 t, %1; cvt.u32.u64 %0, t; }"
        : "=r"(a) : "l"(p));
    return a;
}
__device__ __forceinline__ void mma16816(float* d, const uint32_t* a, const uint32_t* b) {
    asm volatile(
        "mma.sync.aligned.m16n8k16.row.col.f32.bf16.bf16.f32 "
        "{%0,%1,%2,%3}, {%4,%5,%6,%7}, {%8,%9}, {%0,%1,%2,%3};"
        : "+f"(d[0]), "+f"(d[1]), "+f"(d[2]), "+f"(d[3])
        : "r"(a[0]), "r"(a[1]), "r"(a[2]), "r"(a[3]), "r"(b[0]), "r"(b[1]));
}
__device__ __forceinline__ void ldsm4(uint32_t* r, uint32_t addr) {
    asm volatile("ldmatrix.sync.aligned.m8n8.x4.shared.b16 {%0,%1,%2,%3}, [%4];"
                 : "=r"(r[0]), "=r"(r[1]), "=r"(r[2]), "=r"(r[3]) : "r"(addr));
}
__device__ __forceinline__ void ldsm4t(uint32_t* r, uint32_t addr) {
    asm volatile("ldmatrix.sync.aligned.m8n8.x4.trans.shared.b16 {%0,%1,%2,%3}, [%4];"
                 : "=r"(r[0]), "=r"(r[1]), "=r"(r[2]), "=r"(r[3]) : "r"(addr));
}
__device__ __forceinline__ float fexp2(float x) {
    float r;
    asm("ex2.approx.f32 %0, %1;" : "=f"(r) : "f"(x));
    return r;
}
__device__ __forceinline__ uint32_t pack_hi(float x, float y) {
    __nv_bfloat162 h = __float22bfloat162_rn(make_float2(x, y));
    return *(uint32_t*)&h;
}
__device__ __forceinline__ uint32_t pack_lo(float x, float y) {
    __nv_bfloat16 hx = __float2bfloat16(x), hy = __float2bfloat16(y);
    __nv_bfloat162 l = __float22bfloat162_rn(
        make_float2(x - __bfloat162float(hx), y - __bfloat162float(hy)));
    return *(uint32_t*)&l;
}
__device__ __forceinline__ void cpa16(uint32_t s, const void* g) {
    asm volatile("cp.async.cg.shared.global [%0], [%1], 16;" :: "r"(s), "l"(g));
}
#define CP_COMMIT()  asm volatile("cp.async.commit_group;" ::: "memory")
#define CP_WAITG(n)  asm volatile("cp.async.wait_group %0;" :: "n"(n) : "memory")

// ---------------------------------------------------------------------------
// converts
// ---------------------------------------------------------------------------
struct ConvJob { const float* src; __nv_bfloat16 *h, *l; int n4; };
struct ConvBatch { ConvJob j[7]; };

__global__ __launch_bounds__(256, 4)
void convert_all(ConvBatch cb)
{
    ConvJob jb = cb.j[blockIdx.z];
    int i = blockIdx.x * 256 + threadIdx.x;
    if (i >= jb.n4) return;
    float4 v = ((const float4*)jb.src)[i];
    uint2 H, L;
    H.x = pack_hi(v.x, v.y); H.y = pack_hi(v.z, v.w);
    L.x = pack_lo(v.x, v.y); L.y = pack_lo(v.z, v.w);
    ((uint2*)jb.h)[i] = H;
    ((uint2*)jb.l)[i] = L;
}

// ---------------------------------------------------------------------------
// GEMM v2.1: 512 threads / 16 warps, warp tile 32x32, K-chunk 64, 3-stage
// ring, ONE barrier per mainloop iteration.
// ---------------------------------------------------------------------------
#define G2ROWB 144
#define G2PLANE (128 * G2ROWB)    // 18432
#define G2STAGE (4 * G2PLANE)     // 73728
#define G2SM   (3 * G2STAGE)      // 221184

struct GemmJob {
    const __nv_bfloat16 *Ah, *Al, *Bh, *Bl;
    const float* bias;
    float* C;
    __nv_bfloat16 *Ch, *Cl;
};
struct GemmBatch { GemmJob j[3]; };

__global__ __launch_bounds__(512, 1)
void gemm_bf16(GemmBatch gb, int M, int N, int K)
{
    extern __shared__ __align__(128) char sm[];
    const uint32_t smb = smem_u32(sm);
    const GemmJob jb = gb.j[blockIdx.z];
    const int tid = threadIdx.x;
    const int wid = tid >> 5, lane = tid & 31;
    const int m0 = blockIdx.y * 128, n0 = blockIdx.x * 128;
    const int warp_m = (wid & 3) * 32;
    const int warp_n = (wid >> 2) * 32;
    const int nch = K / 64;

    const __nv_bfloat16* bases[4] = { jb.Ah, jb.Al, jb.Bh, jb.Bl };

    auto issue = [&](int ch) {
        const uint32_t sb = smb + (uint32_t)((ch % 3) * G2STAGE);
        const size_t gk = (size_t)ch * 64;
#pragma unroll
        for (int p = 0; p < 4; p++) {
            const int rbase = (p < 2) ? m0 : n0;
#pragma unroll
            for (int e = 0; e < 2; e++) {
                int idx = tid + e * 512;
                int r = idx >> 3, c = idx & 7;
                cpa16(sb + (uint32_t)(p * G2PLANE + r * G2ROWB + c * 16),
                      bases[p] + (size_t)(rbase + r) * K + gk + c * 8);
            }
        }
    };

    float acc[2][4][4];
#pragma unroll
    for (int i = 0; i < 2; i++)
#pragma unroll
        for (int j = 0; j < 4; j++)
#pragma unroll
            for (int c = 0; c < 4; c++) acc[i][j][c] = 0.0f;

    issue(0); CP_COMMIT();
    issue(1); CP_COMMIT();

    const int arow = lane & 15;
    const int acol = (lane >> 4) * 8;
    const int bg = lane >> 3, bw = lane & 7;

    for (int ch = 0; ch < nch; ch++) {
        CP_WAITG(1);
        __syncthreads();          // single barrier per iteration:
        if (ch + 2 < nch) issue(ch + 2);   // writes stage (ch+2)%3 — not in use
        CP_COMMIT();

        const uint32_t sb = smb + (uint32_t)((ch % 3) * G2STAGE);
#pragma unroll
        for (int ks = 0; ks < 4; ks++) {
            const int k16 = ks * 16;
            uint32_t ah[2][4], al[2][4];
#pragma unroll
            for (int mt = 0; mt < 2; mt++) {
                uint32_t off = (uint32_t)((warp_m + mt * 16 + arow) * G2ROWB
                                          + (k16 + acol) * 2);
                ldsm4(ah[mt], sb + 0 * G2PLANE + off);
                ldsm4(al[mt], sb + 1 * G2PLANE + off);
            }
            uint32_t bh[4][2], bl[4][2];
#pragma unroll
            for (int nb = 0; nb < 2; nb++) {
                uint32_t off = (uint32_t)((warp_n + nb * 16 + (bg & 1) * 8 + bw) * G2ROWB
                                          + (k16 + (bg >> 1) * 8) * 2);
                uint32_t t[4];
                ldsm4(t, sb + 2 * G2PLANE + off);
                bh[nb * 2 + 0][0] = t[0]; bh[nb * 2 + 0][1] = t[2];
                bh[nb * 2 + 1][0] = t[1]; bh[nb * 2 + 1][1] = t[3];
                ldsm4(t, sb + 3 * G2PLANE + off);
                bl[nb * 2 + 0][0] = t[0]; bl[nb * 2 + 0][1] = t[2];
                bl[nb * 2 + 1][0] = t[1]; bl[nb * 2 + 1][1] = t[3];
            }
#pragma unroll
            for (int mt = 0; mt < 2; mt++)
#pragma unroll
                for (int nt = 0; nt < 4; nt++) {
                    mma16816(acc[mt][nt], ah[mt], bh[nt]);
                    mma16816(acc[mt][nt], ah[mt], bl[nt]);
                    mma16816(acc[mt][nt], al[mt], bh[nt]);
                }
        }
    }

    const int lr = lane >> 2, lc = (lane & 3) * 2;
    const bool wplanes = (jb.Ch != nullptr);
#pragma unroll
    for (int nt = 0; nt < 4; nt++) {
        int col = n0 + warp_n + nt * 8 + lc;
        float2 bv = *(const float2*)&jb.bias[col];
#pragma unroll
        for (int mt = 0; mt < 2; mt++) {
            int r0 = m0 + warp_m + mt * 16 + lr;
            float2 o0 = make_float2(acc[mt][nt][0] + bv.x, acc[mt][nt][1] + bv.y);
            float2 o1 = make_float2(acc[mt][nt][2] + bv.x, acc[mt][nt][3] + bv.y);
            *(float2*)(jb.C + (size_t)r0 * N + col) = o0;
            *(float2*)(jb.C + (size_t)(r0 + 8) * N + col) = o1;
            if (wplanes) {
                size_t i0 = (size_t)r0 * N + col;
                size_t i1 = (size_t)(r0 + 8) * N + col;
                *(uint32_t*)&jb.Ch[i0] = pack_hi(o0.x, o0.y);
                *(uint32_t*)&jb.Cl[i0] = pack_lo(o0.x, o0.y);
                *(uint32_t*)&jb.Ch[i1] = pack_hi(o1.x, o1.y);
                *(uint32_t*)&jb.Cl[i1] = pack_lo(o1.x, o1.y);
            }
        }
    }
}

// ---------------------------------------------------------------------------
// Fused attention, in-register P; prefetch commits hoisted.
// Group order: G1={Q,K0}, G2={V0}, G3={K1}; per jt: top-commit V(jt+1),
// mid-commit K(jt+2). Waits: top WAITG(2) -> K(jt); pre-PV WAITG(2) -> V(jt).
// ---------------------------------------------------------------------------
#define QROWB 144
#define AQH   0
#define AQL   18432
#define AKH0  36864
#define AKH1  73728
#define AVH0  110592
#define AVH1  147456
#define SM2_TOT 184320

__global__ __launch_bounds__(256, 1)
void attn_fused_mma(float* __restrict__ attn)
{
    extern __shared__ __align__(128) char sm[];
    const uint32_t smb = smem_u32(sm);
    const int tid = threadIdx.x;
    const int wid = tid >> 5, lane = tid & 31;
    const int b = blockIdx.z, h = blockIdx.y;
    const int it = (int)gridDim.x - 1 - (int)blockIdx.x;
    const int r0 = it * 128;
    const int warp_m = wid * 16;
    const int lr = lane >> 2, lc2 = (lane & 3) * 2;
    const float CE = 0.125f * 1.4426950408889634f;

    const size_t qoff = ((size_t)b * Sc + r0) * Dc + h * DPc;
    const size_t koff = (size_t)b * Sc * Dc + h * DPc;
    const size_t bh_ = (size_t)(b * Hc + h);
    float* attnp = attn + bh_ * Sc * Sc;

    auto issue_plane = [&](uint32_t dst, const __nv_bfloat16* src) {
#pragma unroll
        for (int e = 0; e < 4; e++) {
            int idx = tid + e * 256;
            int r = idx >> 3, c = idx & 7;
            cpa16(dst + (uint32_t)(r * QROWB + c * 16), src + (size_t)r * Dc + c * 8);
        }
    };
    auto issue_K = [&](int jt) {
        uint32_t dst = smb + ((jt & 1) ? AKH1 : AKH0);
        const size_t off = koff + (size_t)jt * 128 * Dc;
        issue_plane(dst, g_kh + off);
        issue_plane(dst + 18432, g_kl + off);
    };
    auto issue_V = [&](int jt) {
        uint32_t dst = smb + ((jt & 1) ? AVH1 : AVH0);
        const size_t off = koff + (size_t)jt * 128 * Dc;
        issue_plane(dst, g_vh + off);
        issue_plane(dst + 18432, g_vl + off);
    };

    issue_plane(smb + AQH, g_qh + qoff);
    issue_plane(smb + AQL, g_ql + qoff);
    issue_K(0);
    CP_COMMIT();            // G1
    issue_V(0);
    CP_COMMIT();            // G2
    if (it >= 1) issue_K(1);
    CP_COMMIT();            // G3 (possibly empty)

    float ctx[8][4];
#pragma unroll
    for (int d = 0; d < 8; d++)
#pragma unroll
        for (int c = 0; c < 4; c++) ctx[d][c] = 0.0f;

    float lsum0 = 0.0f, lsum1 = 0.0f;

    const int arow = lane & 15;
    const int acol = (lane >> 4) * 8;
    const int bg = lane >> 3, bw = lane & 7;
    const int growg0 = r0 + warp_m + lr;
    const int growg1 = growg0 + 8;

    for (int jt = 0; jt <= it; jt++) {
        const int j0 = jt * 128;

        CP_WAITG(2);        // K(jt) arrived (2 newer groups may be outstanding)
        __syncthreads();    // all warps done with PV(jt-1) -> V buf (jt+1)&1 free

        if (jt + 1 <= it) issue_V(jt + 1);
        CP_COMMIT();        // top commit (possibly empty)

        const uint32_t kbase = (jt & 1) ? AKH1 : AKH0;

        float acc[16][4];
#pragma unroll
        for (int i = 0; i < 16; i++)
#pragma unroll
            for (int c = 0; c < 4; c++) acc[i][c] = 0.0f;

#pragma unroll
        for (int ks = 0; ks < 4; ks++) {
            const int k16 = ks * 16;
            uint32_t ah[4], al[4];
            {
                uint32_t off = (uint32_t)((warp_m + arow) * QROWB + (k16 + acol) * 2);
                ldsm4(ah, smb + AQH + off);
                ldsm4(al, smb + AQL + off);
            }
#pragma unroll
            for (int nb = 0; nb < 8; nb++) {
                uint32_t off = (uint32_t)((nb * 16 + (bg & 1) * 8 + bw) * QROWB
                                          + (k16 + (bg >> 1) * 8) * 2);
                uint32_t t[4], bh0[2], bh1[2], bl0[2], bl1[2];
                ldsm4(t, smb + kbase + off);
                bh0[0] = t[0]; bh0[1] = t[2];
                bh1[0] = t[1]; bh1[1] = t[3];
                ldsm4(t, smb + kbase + 18432 + off);
                bl0[0] = t[0]; bl0[1] = t[2];
                bl1[0] = t[1]; bl1[1] = t[3];
                mma16816(acc[nb * 2 + 0], ah, bh0);
                mma16816(acc[nb * 2 + 0], ah, bl0);
                mma16816(acc[nb * 2 + 0], al, bh0);
                mma16816(acc[nb * 2 + 1], ah, bh1);
                mma16816(acc[nb * 2 + 1], ah, bl1);
                mma16816(acc[nb * 2 + 1], al, bh1);
            }
        }

        const bool diag = (jt == it);
#pragma unroll
        for (int nt = 0; nt < 16; nt++) {
            const int col = j0 + nt * 8 + lc2;
            float p0 = fexp2(acc[nt][0] * CE);
            float p1 = fexp2(acc[nt][1] * CE);
            float p2 = fexp2(acc[nt][2] * CE);
            float p3 = fexp2(acc[nt][3] * CE);
            if (diag) {
                if (col + 0 > growg0) p0 = 0.0f;
                if (col + 1 > growg0) p1 = 0.0f;
                if (col + 0 > growg1) p2 = 0.0f;
                if (col + 1 > growg1) p3 = 0.0f;
            }
            *(float2*)&attnp[(size_t)growg0 * Sc + col] = make_float2(p0, p1);
            *(float2*)&attnp[(size_t)growg1 * Sc + col] = make_float2(p2, p3);
            acc[nt][0] = p0; acc[nt][1] = p1; acc[nt][2] = p2; acc[nt][3] = p3;
            lsum0 += p0 + p1;
            lsum1 += p2 + p3;
        }

        CP_WAITG(2);        // V(jt) arrived (K(jt+1), V(jt+1) may be outstanding)
        __syncthreads();    // all warps done reading K(jt) -> K buf jt&1 free

        if (jt + 2 <= it) issue_K(jt + 2);
        CP_COMMIT();        // mid commit (possibly empty)

        const uint32_t vbase = (jt & 1) ? AVH1 : AVH0;

#pragma unroll
        for (int ks = 0; ks < 8; ks++) {
            uint32_t aph[4], apl[4];
            aph[0] = pack_hi(acc[ks * 2 + 0][0], acc[ks * 2 + 0][1]);
            aph[1] = pack_hi(acc[ks * 2 + 0][2], acc[ks * 2 + 0][3]);
            aph[2] = pack_hi(acc[ks * 2 + 1][0], acc[ks * 2 + 1][1]);
            aph[3] = pack_hi(acc[ks * 2 + 1][2], acc[ks * 2 + 1][3]);
            apl[0] = pack_lo(acc[ks * 2 + 0][0], acc[ks * 2 + 0][1]);
            apl[1] = pack_lo(acc[ks * 2 + 0][2], acc[ks * 2 + 0][3]);
            apl[2] = pack_lo(acc[ks * 2 + 1][0], acc[ks * 2 + 1][1]);
            apl[3] = pack_lo(acc[ks * 2 + 1][2], acc[ks * 2 + 1][3]);
#pragma unroll
            for (int d16 = 0; d16 < 4; d16++) {
                uint32_t voff = (uint32_t)((ks * 16 + (lane & 15)) * QROWB
                                           + (d16 * 16 + (lane >> 4) * 8) * 2);
                uint32_t t[4], vh0[2], vh1[2], vl0[2], vl1[2];
                ldsm4t(t, smb + vbase + voff);
                vh0[0] = t[0]; vh0[1] = t[1];
                vh1[0] = t[2]; vh1[1] = t[3];
                ldsm4t(t, smb + vbase + 18432 + voff);
                vl0[0] = t[0]; vl0[1] = t[1];
                vl1[0] = t[2]; vl1[1] = t[3];
                mma16816(ctx[d16 * 2 + 0], aph, vh0);
                mma16816(ctx[d16 * 2 + 0], aph, vl0);
                mma16816(ctx[d16 * 2 + 0], apl, vh0);
                mma16816(ctx[d16 * 2 + 1], aph, vh1);
                mma16816(ctx[d16 * 2 + 1], aph, vl1);
                mma16816(ctx[d16 * 2 + 1], apl, vh1);
            }
        }
    }

#pragma unroll
    for (int off = 1; off <= 2; off <<= 1) {
        lsum0 += __shfl_xor_sync(0xffffffffu, lsum0, off);
        lsum1 += __shfl_xor_sync(0xffffffffu, lsum1, off);
    }
    if ((lane & 3) == 0) {
        g_lbuf[bh_ * Sc + growg0] = lsum0;
        g_lbuf[bh_ * Sc + growg1] = lsum1;
    }
    const float inv0 = 1.0f / lsum0;
    const float inv1 = 1.0f / lsum1;

#pragma unroll
    for (int d = 0; d < 8; d++) {
        int dcol = h * DPc + d * 8 + lc2;
        float x0 = ctx[d][0] * inv0, x1 = ctx[d][1] * inv0;
        float x2 = ctx[d][2] * inv1, x3 = ctx[d][3] * inv1;
        size_t i0 = ((size_t)b * Sc + growg0) * Dc + dcol;
        size_t i1 = ((size_t)b * Sc + growg1) * Dc + dcol;
        *(uint32_t*)&g_ch2[i0] = pack_hi(x0, x1);
        *(uint32_t*)&g_cl2[i0] = pack_lo(x0, x1);
        *(uint32_t*)&g_ch2[i1] = pack_hi(x2, x3);
        *(uint32_t*)&g_cl2[i1] = pack_lo(x2, x3);
    }
}

// ---------------------------------------------------------------------------
__global__ __launch_bounds__(512, 2)
void fill_upper(float* __restrict__ attn)
{
    const int b = blockIdx.z, h = blockIdx.y, it = blockIdx.x;
    const int ncol4 = 512 - (it + 1) * 32;
    if (ncol4 <= 0) return;
    const int c0 = (it + 1) * 32;
    float* ap = attn + ((size_t)(b * Hc + h)) * Sc * Sc + (size_t)it * 128 * Sc;
    const float4 z = make_float4(0.f, 0.f, 0.f, 0.f);
    const int tid = threadIdx.x;
    const int total = 128 * ncol4;
    for (int i = tid; i < total; i += 512) {
        int r = i / ncol4, c = i - r * ncol4;
        ((float4*)&ap[(size_t)r * Sc])[c0 + c] = z;
    }
}

__global__ __launch_bounds__(512, 2)
void norm_lower(float* __restrict__ attn)
{
    const int b = blockIdx.z, h = blockIdx.y, it = blockIdx.x;
    const int r0 = it * 128;
    const int tid = threadIdx.x;
    const size_t bh_ = (size_t)(b * Hc + h);
    float* ap = attn + bh_ * Sc * Sc;

    __shared__ float inv[128];
    if (tid < 128) inv[tid] = 1.0f / g_lbuf[bh_ * Sc + r0 + tid];
    __syncthreads();

    const int ncol4 = (it + 1) * 32;
    for (int r = tid >> 7; r < 128; r += 4) {
        const float s = inv[r];
        float4* rowp = (float4*)&ap[(size_t)(r0 + r) * Sc];
#pragma unroll 4
        for (int c4 = (tid & 127); c4 < ncol4; c4 += 128) {
            float4 v = rowp[c4];
            v.x *= s; v.y *= s; v.z *= s; v.w *= s;
            rowp[c4] = v;
        }
    }
}

// ---------------------------------------------------------------------------
extern "C" void kernel_launch(void* const* d_in, const int* in_sizes, int n_in,
                              void* d_out, int out_size)
{
    (void)in_sizes; (void)n_in; (void)out_size;
    const float* Q   = (const float*)d_in[0];
    const float* Kin = (const float*)d_in[1];
    const float* Vin = (const float*)d_in[2];
    const float* Wq = (const float*)d_in[4];
    const float* bq = (const float*)d_in[5];
    const float* Wk = (const float*)d_in[6];
    const float* bk = (const float*)d_in[7];
    const float* Wv = (const float*)d_in[8];
    const float* bv = (const float*)d_in[9];
    const float* Wo = (const float*)d_in[10];
    const float* bo = (const float*)d_in[11];

    float* out  = (float*)d_out;
    float* attn = out + SZ_QKV;
    float* qo   = attn + SZ_ATTN;
    float* ko   = qo + SZ_QKV;
    float* vo   = ko + SZ_QKV;

    void *iah, *ial, *wh, *wl, *qh, *ql, *kh, *kl, *vh, *vl, *ch2, *cl2;
    cudaGetSymbolAddress(&iah, g_iah);  cudaGetSymbolAddress(&ial, g_ial);
    cudaGetSymbolAddress(&wh, g_wh);    cudaGetSymbolAddress(&wl, g_wl);
    cudaGetSymbolAddress(&qh, g_qh);    cudaGetSymbolAddress(&ql, g_ql);
    cudaGetSymbolAddress(&kh, g_kh);    cudaGetSymbolAddress(&kl, g_kl);
    cudaGetSymbolAddress(&vh, g_vh);    cudaGetSymbolAddress(&vl, g_vl);
    cudaGetSymbolAddress(&ch2, g_ch2);  cudaGetSymbolAddress(&cl2, g_cl2);
    __nv_bfloat16 *IAH = (__nv_bfloat16*)iah, *IAL = (__nv_bfloat16*)ial;
    __nv_bfloat16 *WH  = (__nv_bfloat16*)wh,  *WL  = (__nv_bfloat16*)wl;

    cudaFuncSetAttribute(gemm_bf16,
                         cudaFuncAttributeMaxDynamicSharedMemorySize, G2SM);
    cudaFuncSetAttribute(attn_fused_mma,
                         cudaFuncAttributeMaxDynamicSharedMemorySize, SM2_TOT);

    const int M = Bc * Sc;

    cudaStream_t s1;
    cudaStreamCreateWithFlags(&s1, cudaStreamNonBlocking);
    cudaEvent_t e0, e1, e2;
    cudaEventCreateWithFlags(&e0, cudaEventDisableTiming);
    cudaEventCreateWithFlags(&e1, cudaEventDisableTiming);
    cudaEventCreateWithFlags(&e2, cudaEventDisableTiming);

    dim3 agrid(Sc / 128, Hc, Bc);

    // fork EARLY: fill_upper has no deps — overlaps converts + QKV gemm
    cudaEventRecord(e0, 0);
    cudaStreamWaitEvent(s1, e0, 0);
    fill_upper<<<agrid, 512, 0, s1>>>(attn);

    // 1) converts
    ConvBatch cb;
    const float* srcs[7] = { Q, Kin, Vin, Wq, Wk, Wv, Wo };
    for (int z = 0; z < 7; z++) {
        cb.j[z].src = srcs[z];
        if (z < 3) {
            cb.j[z].h = IAH + (size_t)z * MD;
            cb.j[z].l = IAL + (size_t)z * MD;
            cb.j[z].n4 = (int)(MD / 4);
        } else {
            cb.j[z].h = WH + (size_t)(z - 3) * DD;
            cb.j[z].l = WL + (size_t)(z - 3) * DD;
            cb.j[z].n4 = (int)(DD / 4);
        }
    }
    dim3 cgrid((unsigned)((MD / 4 + 255) / 256), 1, 7);
    convert_all<<<cgrid, 256>>>(cb);

    // 2) QKV projections
    GemmBatch qb;
    const float* biases[3] = { bq, bk, bv };
    float* outs[3] = { qo, ko, vo };
    __nv_bfloat16* chp[3] = { (__nv_bfloat16*)qh, (__nv_bfloat16*)kh, (__nv_bfloat16*)vh };
    __nv_bfloat16* clp[3] = { (__nv_bfloat16*)ql, (__nv_bfloat16*)kl, (__nv_bfloat16*)vl };
    for (int z = 0; z < 3; z++) {
        qb.j[z].Ah = IAH + (size_t)z * MD; qb.j[z].Al = IAL + (size_t)z * MD;
        qb.j[z].Bh = WH + (size_t)z * DD;  qb.j[z].Bl = WL + (size_t)z * DD;
        qb.j[z].bias = biases[z]; qb.j[z].C = outs[z];
        qb.j[z].Ch = chp[z]; qb.j[z].Cl = clp[z];
    }
    dim3 qgrid(Dc / 128, M / 128, 3);
    gemm_bf16<<<qgrid, 512, G2SM>>>(qb, M, Dc, Dc);

    // 3) attention
    attn_fused_mma<<<agrid, 256, SM2_TOT>>>(attn);
    cudaEventRecord(e1, 0);

    cudaStreamWaitEvent(s1, e1, 0);
    norm_lower<<<agrid, 512, 0, s1>>>(attn);
    cudaEventRecord(e2, s1);

    // 4) O projection (overlaps norm_lower)
    GemmBatch ob;
    ob.j[0].Ah = (__nv_bfloat16*)ch2; ob.j[0].Al = (__nv_bfloat16*)cl2;
    ob.j[0].Bh = WH + 3 * DD;         ob.j[0].Bl = WL + 3 * DD;
    ob.j[0].bias = bo; ob.j[0].C = out;
    ob.j[0].Ch = nullptr; ob.j[0].Cl = nullptr;
    ob.j[1] = ob.j[0]; ob.j[2] = ob.j[0];
    dim3 ogrid(Dc / 128, M / 128, 1);
    gemm_bf16<<<ogrid, 512, G2SM>>>(ob, M, Dc, Dc);

    cudaStreamWaitEvent(0, e2, 0);
}